// round 8
// baseline (speedup 1.0000x reference)
#include <cuda_runtime.h>
#include <cuda_bf16.h>
#include <cstdint>
#include <math.h>

// ---------------- problem constants (fixed shapes) ----------------
#define NN 100000      // nodes
#define EE 400000      // edges (without self loops)
#define ET (EE + NN)   // total edges incl self loops
#define F0 128         // input features
#define HID 256        // hidden (4 heads x 64)
#define OUTC 128       // output features
#define SLOPE 0.2f
#define MPAD 100096    // 782 * 128 (row-padded M for the GEMM)

// ---------------- device scratch (no allocations allowed) ----------------
__device__ __align__(16) float g_h[(size_t)NN * HID];     // GEMM output of current layer
__device__ __align__(16) float g_agg[(size_t)NN * HID];   // aggregated output (next layer input)
__device__ __align__(16) float g_als[(size_t)NN * 4];
__device__ __align__(16) float g_ald[(size_t)NN * 4];
__device__ int   g_deg[NN];
__device__ int   g_off[NN + 1];
__device__ int   g_cur[NN];
__device__ int   g_csr[ET];
__device__ int   g_is64;   // 1 if edge_index is int64, 0 if int32

// bf16 split operands for MMA GEMM
__device__ __align__(16) __nv_bfloat16 g_Ah[(size_t)MPAD * 256];
__device__ __align__(16) __nv_bfloat16 g_Al[(size_t)MPAD * 256];
__device__ __align__(16) __nv_bfloat16 g_Bh[256 * 256];   // W^T hi  [N, K]
__device__ __align__(16) __nv_bfloat16 g_Bl[256 * 256];   // W^T lo  [N, K]

// scan temporaries
#define SCAN_BLK 1024
#define NSB ((NN + SCAN_BLK - 1) / SCAN_BLK)   // 98
__device__ int g_bsum[NSB];
__device__ int g_bbase[NSB];

// ---------------- helpers ----------------
__device__ __forceinline__ uint32_t smem_u32(const void* p) {
    uint32_t a;
    asm("{ .reg .u64 t; cvta.to.shared.u64 t, %1; cvt.u32.u64 %0, t; }" : "=r"(a) : "l"(p));
    return a;
}
#define SWZ128(off) ((off) ^ (((off) >> 3) & 0x70))

__device__ __forceinline__ void ldmat_x4(uint32_t& r0, uint32_t& r1, uint32_t& r2,
                                         uint32_t& r3, uint32_t addr) {
    asm volatile("ldmatrix.sync.aligned.m8n8.x4.shared.b16 {%0,%1,%2,%3}, [%4];"
        : "=r"(r0), "=r"(r1), "=r"(r2), "=r"(r3) : "r"(addr));
}
__device__ __forceinline__ void mma_bf16(float* d, const uint32_t* a, const uint32_t* b) {
    asm volatile("mma.sync.aligned.m16n8k16.row.col.f32.bf16.bf16.f32 "
        "{%0,%1,%2,%3}, {%4,%5,%6,%7}, {%8,%9}, {%0,%1,%2,%3};"
        : "+f"(d[0]), "+f"(d[1]), "+f"(d[2]), "+f"(d[3])
        : "r"(a[0]), "r"(a[1]), "r"(a[2]), "r"(a[3]), "r"(b[0]), "r"(b[1]));
}

// ---------------- edge-index dtype probe ----------------
__global__ void k_detect(const int* __restrict__ ei32) {
    if (threadIdx.x == 0 && blockIdx.x == 0) {
        int odd_nonzero = 0;
        for (int i = 1; i < 256; i += 2) odd_nonzero += (ei32[i] != 0);
        g_is64 = (odd_nonzero == 0) ? 1 : 0;
    }
}
__device__ __forceinline__ int edge_at(const void* __restrict__ ei, size_t idx) {
    if (g_is64) return (int)((const long long*)ei)[idx];
    return ((const int*)ei)[idx];
}

// ---------------- CSR build ----------------
__global__ void k_init_deg() {
    int i = blockIdx.x * blockDim.x + threadIdx.x;
    if (i < NN) g_deg[i] = 1;
}
__global__ void k_count_edges(const void* __restrict__ ei) {
    int i = blockIdx.x * blockDim.x + threadIdx.x;
    if (i < EE) atomicAdd(&g_deg[edge_at(ei, (size_t)EE + i)], 1);
}

// 3-kernel parallel scan
__global__ void k_scan_partial() {  // grid NSB, 256 thr
    __shared__ int sh[256];
    int b = blockIdx.x, t = threadIdx.x;
    int base = b * SCAN_BLK;
    int sum = 0;
    for (int i = t; i < SCAN_BLK; i += 256) {
        int g = base + i;
        if (g < NN) sum += g_deg[g];
    }
    sh[t] = sum; __syncthreads();
    for (int o = 128; o; o >>= 1) { if (t < o) sh[t] += sh[t + o]; __syncthreads(); }
    if (t == 0) g_bsum[b] = sh[0];
}
__global__ void k_scan_tops() {  // 1 block, 128 thr (NSB <= 128)
    __shared__ int sh[128];
    int t = threadIdx.x;
    int v = (t < NSB) ? g_bsum[t] : 0;
    sh[t] = v; __syncthreads();
    for (int o = 1; o < 128; o <<= 1) {
        int u = (t >= o) ? sh[t - o] : 0; __syncthreads();
        sh[t] += u; __syncthreads();
    }
    if (t < NSB) g_bbase[t] = sh[t] - v;
    if (t == 127) g_off[NN] = sh[127];
}
__global__ void k_scan_final() {  // grid NSB, 1024 thr
    __shared__ int sh[SCAN_BLK];
    int b = blockIdx.x, t = threadIdx.x;
    int g = b * SCAN_BLK + t;
    int v = (g < NN) ? g_deg[g] : 0;
    sh[t] = v; __syncthreads();
    for (int o = 1; o < SCAN_BLK; o <<= 1) {
        int u = (t >= o) ? sh[t - o] : 0; __syncthreads();
        sh[t] += u; __syncthreads();
    }
    if (g < NN) g_off[g] = g_bbase[b] + sh[t] - v;
}

__global__ void k_scatter_self() {
    int i = blockIdx.x * blockDim.x + threadIdx.x;
    if (i < NN) { int o = g_off[i]; g_csr[o] = i; g_cur[i] = o + 1; }
}
__global__ void k_scatter_edges(const void* __restrict__ ei) {
    int i = blockIdx.x * blockDim.x + threadIdx.x;
    if (i < EE) {
        int d = edge_at(ei, (size_t)EE + i);
        int p = atomicAdd(&g_cur[d], 1);
        g_csr[p] = edge_at(ei, i);
    }
}

// ---------------- bf16 hi/lo conversion ----------------
template <bool EXT>
__global__ void k_convA(const float* __restrict__ ext, int K) {
    const float* __restrict__ src = EXT ? ext : (const float*)g_agg;
    size_t i = ((size_t)blockIdx.x * blockDim.x + threadIdx.x) * 4;
    size_t tot = (size_t)MPAD * K;
    if (i >= tot) return;
    float a[4] = {0.f, 0.f, 0.f, 0.f};
    if (i < (size_t)NN * K) {
        float4 v = *(const float4*)(src + i);
        a[0] = v.x; a[1] = v.y; a[2] = v.z; a[3] = v.w;
    }
    __nv_bfloat16 h[4], l[4];
#pragma unroll
    for (int j = 0; j < 4; j++) {
        h[j] = __float2bfloat16(a[j]);
        l[j] = __float2bfloat16(a[j] - __bfloat162float(h[j]));
    }
    *(uint2*)(g_Ah + i) = *(uint2*)h;
    *(uint2*)(g_Al + i) = *(uint2*)l;
}

__global__ void k_convB(const float* __restrict__ W, int K, int Ncol) {
    int idx = blockIdx.x * blockDim.x + threadIdx.x;   // n*K + k
    if (idx >= K * Ncol) return;
    int n = idx / K, k = idx % K;
    float w = W[k * Ncol + n];
    __nv_bfloat16 h = __float2bfloat16(w);
    __nv_bfloat16 l = __float2bfloat16(w - __bfloat162float(h));
    g_Bh[idx] = h; g_Bl[idx] = l;
}

// ---------------- warp-level bf16 MMA GEMM (3-pass hi/lo split) ----------------
// g_h[row, nBase:nBase+128] = sum of segments: Ah@Bh^T + Al@Bh^T + Ah@Bl^T
// K3 = 3*K (virtual K), KS = K (row stride), NT = output row width (256 or 128).
// grid = (MPAD/128, NT/128). CTA 128x128, 8 warps 2x4, warp tile 64x32.
template <int K3, int KS, int NT>
__global__ __launch_bounds__(256) void k_mgemm() {
    __shared__ __align__(1024) char smA[128 * 128];   // 128 rows x 64 bf16, SW128
    __shared__ __align__(1024) char smB[128 * 128];

    const int tid = threadIdx.x;
    const int wid = tid >> 5;
    const int lane = tid & 31;
    const int wm = wid >> 2;          // 0..1
    const int wn = wid & 3;           // 0..3
    const size_t rowBase = (size_t)blockIdx.x * 128;
    const int nBase = blockIdx.y * 128;
    const uint32_t sA = smem_u32(smA);
    const uint32_t sB = smem_u32(smB);

    float acc[4][4][4];
#pragma unroll
    for (int i = 0; i < 4; i++)
#pragma unroll
        for (int j = 0; j < 4; j++)
#pragma unroll
            for (int f = 0; f < 4; f++) acc[i][j][f] = 0.f;

    constexpr int CHUNKS = K3 / 64;
    constexpr int CPS = KS / 64;

    for (int c = 0; c < CHUNKS; c++) {
        const int seg = c / CPS;
        const int off = (c % CPS) * 64;
        const __nv_bfloat16* __restrict__ Asrc = (seg == 1) ? g_Al : g_Ah;
        const __nv_bfloat16* __restrict__ Bsrc = (seg == 2) ? g_Bl : g_Bh;

        // stage A chunk: 128 rows x 64 bf16
        for (int u = tid; u < 128 * 8; u += 256) {
            int r = u >> 3, uu = u & 7;
            uint4 v = *(const uint4*)(Asrc + (rowBase + r) * KS + off + uu * 8);
            uint32_t boff = (uint32_t)(r * 128 + uu * 16);
            *(uint4*)(smA + SWZ128(boff)) = v;
        }
        // stage B chunk: 128 n-rows x 64 bf16
        for (int u = tid; u < 128 * 8; u += 256) {
            int r = u >> 3, uu = u & 7;
            uint4 v = *(const uint4*)(Bsrc + (size_t)(nBase + r) * KS + off + uu * 8);
            uint32_t boff = (uint32_t)(r * 128 + uu * 16);
            *(uint4*)(smB + SWZ128(boff)) = v;
        }
        __syncthreads();

        const int mat = lane >> 3;     // 0..3
        const int rr = lane & 7;
#pragma unroll
        for (int kk = 0; kk < 4; kk++) {
            const int k0 = kk * 16;
            uint32_t a[4][4];
#pragma unroll
            for (int ms = 0; ms < 4; ms++) {
                int row = wm * 64 + ms * 16 + (mat & 1) * 8 + rr;
                int bcol = (k0 + (mat >> 1) * 8) * 2;
                ldmat_x4(a[ms][0], a[ms][1], a[ms][2], a[ms][3],
                         sA + SWZ128((uint32_t)(row * 128 + bcol)));
            }
            uint32_t b[4][2];
#pragma unroll
            for (int nb = 0; nb < 2; nb++) {
                int nrow = wn * 32 + nb * 16 + (mat >> 1) * 8 + rr;
                int bcol = (k0 + (mat & 1) * 8) * 2;
                uint32_t r0, r1, r2, r3;
                ldmat_x4(r0, r1, r2, r3, sB + SWZ128((uint32_t)(nrow * 128 + bcol)));
                b[nb * 2][0] = r0;     b[nb * 2][1] = r1;
                b[nb * 2 + 1][0] = r2; b[nb * 2 + 1][1] = r3;
            }
#pragma unroll
            for (int ms = 0; ms < 4; ms++)
#pragma unroll
                for (int ns = 0; ns < 4; ns++)
                    mma_bf16(acc[ms][ns], a[ms], b[ns]);
        }
        __syncthreads();
    }

    // epilogue: c-frag: d0,d1 -> (row T/4, col 2*(T%4), +1); d2,d3 -> row+8
    const int cr = lane >> 2;
    const int cc = (lane & 3) * 2;
#pragma unroll
    for (int ms = 0; ms < 4; ms++) {
#pragma unroll
        for (int ns = 0; ns < 4; ns++) {
            size_t row0 = rowBase + wm * 64 + ms * 16 + cr;
            int col = nBase + wn * 32 + ns * 8 + cc;
            if (row0 < NN) {
                float2 v0 = make_float2(acc[ms][ns][0], acc[ms][ns][1]);
                *(float2*)(g_h + row0 * NT + col) = v0;
            }
            size_t row1 = row0 + 8;
            if (row1 < NN) {
                float2 v1 = make_float2(acc[ms][ns][2], acc[ms][ns][3]);
                *(float2*)(g_h + row1 * NT + col) = v1;
            }
        }
    }
}

// ---------------- per-node attention scores ----------------
template <int CT, int H>
__global__ __launch_bounds__(256) void k_scores(const float* __restrict__ a_s,
                                                const float* __restrict__ a_d) {
    int wid = (blockIdx.x * blockDim.x + threadIdx.x) >> 5;
    int lane = threadIdx.x & 31;
    if (wid >= NN) return;
    const float* hp = g_h + (size_t)wid * CT;

    int cA = lane * 4;
    float4 hv = *(const float4*)(hp + cA);
    float4 sv = *(const float4*)(a_s + cA);
    float4 dv = *(const float4*)(a_d + cA);
    float psA = hv.x * sv.x + hv.y * sv.y + hv.z * sv.z + hv.w * sv.w;
    float pdA = hv.x * dv.x + hv.y * dv.y + hv.z * dv.z + hv.w * dv.w;

    if (CT == 256) {
        int cB = 128 + lane * 4;
        float4 hv2 = *(const float4*)(hp + cB);
        float4 sv2 = *(const float4*)(a_s + cB);
        float4 dv2 = *(const float4*)(a_d + cB);
        float psB = hv2.x * sv2.x + hv2.y * sv2.y + hv2.z * sv2.z + hv2.w * sv2.w;
        float pdB = hv2.x * dv2.x + hv2.y * dv2.y + hv2.z * dv2.z + hv2.w * dv2.w;
#pragma unroll
        for (int o = 8; o; o >>= 1) {
            psA += __shfl_xor_sync(0xffffffffu, psA, o);
            pdA += __shfl_xor_sync(0xffffffffu, pdA, o);
            psB += __shfl_xor_sync(0xffffffffu, psB, o);
            pdB += __shfl_xor_sync(0xffffffffu, pdB, o);
        }
        if (lane == 0)  { g_als[wid * 4 + 0] = psA; g_ald[wid * 4 + 0] = pdA;
                          g_als[wid * 4 + 2] = psB; g_ald[wid * 4 + 2] = pdB; }
        if (lane == 16) { g_als[wid * 4 + 1] = psA; g_ald[wid * 4 + 1] = pdA;
                          g_als[wid * 4 + 3] = psB; g_ald[wid * 4 + 3] = pdB; }
    } else {
#pragma unroll
        for (int o = 16; o; o >>= 1) {
            psA += __shfl_xor_sync(0xffffffffu, psA, o);
            pdA += __shfl_xor_sync(0xffffffffu, pdA, o);
        }
        if (lane == 0) { g_als[wid] = psA; g_ald[wid] = pdA; }
    }
}

__device__ __forceinline__ float lrelu(float x) { return x > 0.f ? x : SLOPE * x; }
__device__ __forceinline__ float elu(float x)   { return x > 0.f ? x : expm1f(x); }

// ---------------- warp-per-dst-node softmax + aggregation ----------------
template <int CT, int H, bool DO_ELU, bool EXT_OUT>
__global__ __launch_bounds__(256) void k_agg(const float* __restrict__ bias,
                                             float* __restrict__ extOut) {
    int n = (blockIdx.x * blockDim.x + threadIdx.x) >> 5;
    int lane = threadIdx.x & 31;
    if (n >= NN) return;
    float* __restrict__ out = EXT_OUT ? extOut : (float*)g_agg;
    const int beg = g_off[n], end = g_off[n + 1];
    const float* __restrict__ h = g_h;
    const float* __restrict__ als = g_als;
    const float* __restrict__ ald = g_ald;

    if (H == 4) {
        float4 ad = *(const float4*)(ald + (size_t)n * 4);
        float4 m = make_float4(-INFINITY, -INFINITY, -INFINITY, -INFINITY);
        for (int i = beg + lane; i < end; i += 32) {
            int s = g_csr[i];
            float4 as = *(const float4*)(als + (size_t)s * 4);
            m.x = fmaxf(m.x, lrelu(as.x + ad.x));
            m.y = fmaxf(m.y, lrelu(as.y + ad.y));
            m.z = fmaxf(m.z, lrelu(as.z + ad.z));
            m.w = fmaxf(m.w, lrelu(as.w + ad.w));
        }
#pragma unroll
        for (int o = 16; o; o >>= 1) {
            m.x = fmaxf(m.x, __shfl_xor_sync(0xffffffffu, m.x, o));
            m.y = fmaxf(m.y, __shfl_xor_sync(0xffffffffu, m.y, o));
            m.z = fmaxf(m.z, __shfl_xor_sync(0xffffffffu, m.z, o));
            m.w = fmaxf(m.w, __shfl_xor_sync(0xffffffffu, m.w, o));
        }
        float4 den = make_float4(0.f, 0.f, 0.f, 0.f);
        for (int i = beg + lane; i < end; i += 32) {
            int s = g_csr[i];
            float4 as = *(const float4*)(als + (size_t)s * 4);
            den.x += __expf(lrelu(as.x + ad.x) - m.x);
            den.y += __expf(lrelu(as.y + ad.y) - m.y);
            den.z += __expf(lrelu(as.z + ad.z) - m.z);
            den.w += __expf(lrelu(as.w + ad.w) - m.w);
        }
#pragma unroll
        for (int o = 16; o; o >>= 1) {
            den.x += __shfl_xor_sync(0xffffffffu, den.x, o);
            den.y += __shfl_xor_sync(0xffffffffu, den.y, o);
            den.z += __shfl_xor_sync(0xffffffffu, den.z, o);
            den.w += __shfl_xor_sync(0xffffffffu, den.w, o);
        }
        float4 inv = make_float4(1.f / (den.x + 1e-16f), 1.f / (den.y + 1e-16f),
                                 1.f / (den.z + 1e-16f), 1.f / (den.w + 1e-16f));
        const int hA = lane >> 4;
        const float adA = hA ? ad.y : ad.x;
        const float adB = hA ? ad.w : ad.z;
        const float mA  = hA ? m.y  : m.x;
        const float mB  = hA ? m.w  : m.z;
        const float ivA = hA ? inv.y : inv.x;
        const float ivB = hA ? inv.w : inv.z;
        const int cA = lane * 4;
        const int cB = 128 + lane * 4;
        float acc[8] = {0.f, 0.f, 0.f, 0.f, 0.f, 0.f, 0.f, 0.f};
        for (int i = beg; i < end; i++) {
            int s = g_csr[i];
            float4 as = *(const float4*)(als + (size_t)s * 4);
            float asA = hA ? as.y : as.x;
            float asB = hA ? as.w : as.z;
            float alA = __expf(lrelu(asA + adA) - mA) * ivA;
            float alB = __expf(lrelu(asB + adB) - mB) * ivB;
            const float* hp = h + (size_t)s * 256;
            float4 v0 = *(const float4*)(hp + cA);
            float4 v1 = *(const float4*)(hp + cB);
            acc[0] = fmaf(alA, v0.x, acc[0]); acc[1] = fmaf(alA, v0.y, acc[1]);
            acc[2] = fmaf(alA, v0.z, acc[2]); acc[3] = fmaf(alA, v0.w, acc[3]);
            acc[4] = fmaf(alB, v1.x, acc[4]); acc[5] = fmaf(alB, v1.y, acc[5]);
            acc[6] = fmaf(alB, v1.z, acc[6]); acc[7] = fmaf(alB, v1.w, acc[7]);
        }
        float4 b0 = *(const float4*)(bias + cA);
        float4 b1 = *(const float4*)(bias + cB);
        float4 o0, o1;
        o0.x = acc[0] + b0.x; o0.y = acc[1] + b0.y; o0.z = acc[2] + b0.z; o0.w = acc[3] + b0.w;
        o1.x = acc[4] + b1.x; o1.y = acc[5] + b1.y; o1.z = acc[6] + b1.z; o1.w = acc[7] + b1.w;
        if (DO_ELU) {
            o0.x = elu(o0.x); o0.y = elu(o0.y); o0.z = elu(o0.z); o0.w = elu(o0.w);
            o1.x = elu(o1.x); o1.y = elu(o1.y); o1.z = elu(o1.z); o1.w = elu(o1.w);
        }
        float* op = out + (size_t)n * 256;
        *(float4*)(op + cA) = o0;
        *(float4*)(op + cB) = o1;
    } else {
        float adn = ald[n];
        float m = -INFINITY;
        for (int i = beg + lane; i < end; i += 32) {
            int s = g_csr[i];
            m = fmaxf(m, lrelu(als[s] + adn));
        }
#pragma unroll
        for (int o = 16; o; o >>= 1) m = fmaxf(m, __shfl_xor_sync(0xffffffffu, m, o));
        float den = 0.f;
        for (int i = beg + lane; i < end; i += 32) {
            int s = g_csr[i];
            den += __expf(lrelu(als[s] + adn) - m);
        }
#pragma unroll
        for (int o = 16; o; o >>= 1) den += __shfl_xor_sync(0xffffffffu, den, o);
        float iv = 1.f / (den + 1e-16f);
        const int cA = lane * 4;
        float acc[4] = {0.f, 0.f, 0.f, 0.f};
        for (int i = beg; i < end; i++) {
            int s = g_csr[i];
            float al = __expf(lrelu(als[s] + adn) - m) * iv;
            float4 v = *(const float4*)(h + (size_t)s * 128 + cA);
            acc[0] = fmaf(al, v.x, acc[0]); acc[1] = fmaf(al, v.y, acc[1]);
            acc[2] = fmaf(al, v.z, acc[2]); acc[3] = fmaf(al, v.w, acc[3]);
        }
        float4 bv = *(const float4*)(bias + cA);
        float4 o0;
        o0.x = acc[0] + bv.x; o0.y = acc[1] + bv.y;
        o0.z = acc[2] + bv.z; o0.w = acc[3] + bv.w;
        *(float4*)(out + (size_t)n * 128 + cA) = o0;
    }
}

// ---------------- launch ----------------
extern "C" void kernel_launch(void* const* d_in, const int* in_sizes, int n_in,
                              void* d_out, int out_size) {
    const float* x   = (const float*)d_in[0];
    const void*  ei  = d_in[1];
    const float* W0  = (const float*)d_in[2];
    const float* as0 = (const float*)d_in[3];
    const float* ad0 = (const float*)d_in[4];
    const float* b0  = (const float*)d_in[5];
    const float* W1  = (const float*)d_in[6];
    const float* as1 = (const float*)d_in[7];
    const float* ad1 = (const float*)d_in[8];
    const float* b1  = (const float*)d_in[9];
    const float* W2  = (const float*)d_in[10];
    const float* as2 = (const float*)d_in[11];
    const float* ad2 = (const float*)d_in[12];
    const float* b2  = (const float*)d_in[13];
    float* out = (float*)d_out;

    const int TB = 256;
    const int gN = (NN + TB - 1) / TB;
    const int gE = (EE + TB - 1) / TB;
    const int gW = (NN + 7) / 8;

    // dtype probe + CSR build (shared by all 3 layers)
    k_detect<<<1, 32>>>((const int*)ei);
    k_init_deg<<<gN, TB>>>();
    k_count_edges<<<gE, TB>>>(ei);
    k_scan_partial<<<NSB, 256>>>();
    k_scan_tops<<<1, 128>>>();
    k_scan_final<<<NSB, SCAN_BLK>>>();
    k_scatter_self<<<gN, TB>>>();
    k_scatter_edges<<<gE, TB>>>(ei);

    const int GEMM_GRID = MPAD / 128;  // 782
    dim3 grid2(GEMM_GRID, 2);
    dim3 grid1(GEMM_GRID, 1);

    // ---- layer 0: x[N,128] @ W0[128,256] ----
    {
        size_t tot = (size_t)MPAD * F0;
        k_convA<true><<<(int)((tot / 4 + TB - 1) / TB), TB>>>(x, F0);
        k_convB<<<(F0 * HID + TB - 1) / TB, TB>>>(W0, F0, HID);
        k_mgemm<384, 128, 256><<<grid2, 256>>>();
        k_scores<256, 4><<<gW, TB>>>(as0, ad0);
        k_agg<256, 4, true, false><<<gW, TB>>>(b0, nullptr);
    }
    // ---- layer 1: g_agg[N,256] @ W1[256,256] ----
    {
        size_t tot = (size_t)MPAD * HID;
        k_convA<false><<<(int)((tot / 4 + TB - 1) / TB), TB>>>(nullptr, HID);
        k_convB<<<(HID * HID + TB - 1) / TB, TB>>>(W1, HID, HID);
        k_mgemm<768, 256, 256><<<grid2, 256>>>();
        k_scores<256, 4><<<gW, TB>>>(as1, ad1);
        k_agg<256, 4, true, false><<<gW, TB>>>(b1, nullptr);
    }
    // ---- layer 2: g_agg[N,256] @ W2[256,128], 1 head, no ELU ----
    {
        size_t tot = (size_t)MPAD * HID;
        k_convA<false><<<(int)((tot / 4 + TB - 1) / TB), TB>>>(nullptr, HID);
        k_convB<<<(HID * OUTC + TB - 1) / TB, TB>>>(W2, HID, OUTC);
        k_mgemm<768, 256, 128><<<grid1, 256>>>();
        k_scores<128, 1><<<gW, TB>>>(as2, ad2);
        k_agg<128, 1, false, true><<<gW, TB>>>(b2, out);
    }
}

// round 10
// speedup vs baseline: 1.5452x; 1.5452x over previous
#include <cuda_runtime.h>
#include <cuda_bf16.h>
#include <cstdint>
#include <math.h>

// ---------------- problem constants (fixed shapes) ----------------
#define NN 100000      // nodes
#define EE 400000      // edges (without self loops)
#define ET (EE + NN)   // total edges incl self loops
#define F0 128         // input features
#define HID 256        // hidden (4 heads x 64)
#define OUTC 128       // output features
#define SLOPE 0.2f
#define MPAD 100096    // 782 * 128 (row-padded M for the GEMM)

// ---------------- device scratch (no allocations allowed) ----------------
__device__ __align__(16) float g_h[(size_t)NN * HID];     // GEMM output of current layer
__device__ __align__(16) float g_agg[(size_t)NN * HID];   // aggregated output (next layer input)
__device__ __align__(16) float g_als[(size_t)NN * 4];
__device__ __align__(16) float g_ald[(size_t)NN * 4];
__device__ int   g_deg[NN];
__device__ int   g_off[NN + 1];
__device__ int   g_cur[NN];
__device__ int   g_csr[ET];
__device__ int   g_is64;   // 1 if edge_index is int64, 0 if int32

// bf16 split W^T (small, per layer)
__device__ __align__(16) __nv_bfloat16 g_Bh[256 * 256];   // W^T hi  [N, K]
__device__ __align__(16) __nv_bfloat16 g_Bl[256 * 256];   // W^T lo  [N, K]

// scan temporaries
#define SCAN_BLK 1024
#define NSB ((NN + SCAN_BLK - 1) / SCAN_BLK)   // 98
__device__ int g_bsum[NSB];
__device__ int g_bbase[NSB];

// ---------------- helpers ----------------
__device__ __forceinline__ uint32_t smem_u32(const void* p) {
    uint32_t a;
    asm("{ .reg .u64 t; cvta.to.shared.u64 t, %1; cvt.u32.u64 %0, t; }" : "=r"(a) : "l"(p));
    return a;
}
#define SWZ128(off) ((off) ^ (((off) >> 3) & 0x70))

__device__ __forceinline__ void ldmat_x4(uint32_t& r0, uint32_t& r1, uint32_t& r2,
                                         uint32_t& r3, uint32_t addr) {
    asm volatile("ldmatrix.sync.aligned.m8n8.x4.shared.b16 {%0,%1,%2,%3}, [%4];"
        : "=r"(r0), "=r"(r1), "=r"(r2), "=r"(r3) : "r"(addr));
}
__device__ __forceinline__ void mma_bf16(float* d, const uint32_t* a, const uint32_t* b) {
    asm volatile("mma.sync.aligned.m16n8k16.row.col.f32.bf16.bf16.f32 "
        "{%0,%1,%2,%3}, {%4,%5,%6,%7}, {%8,%9}, {%0,%1,%2,%3};"
        : "+f"(d[0]), "+f"(d[1]), "+f"(d[2]), "+f"(d[3])
        : "r"(a[0]), "r"(a[1]), "r"(a[2]), "r"(a[3]), "r"(b[0]), "r"(b[1]));
}

// ---------------- edge-index dtype probe ----------------
__global__ void k_detect(const int* __restrict__ ei32) {
    if (threadIdx.x == 0 && blockIdx.x == 0) {
        int odd_nonzero = 0;
        for (int i = 1; i < 256; i += 2) odd_nonzero += (ei32[i] != 0);
        g_is64 = (odd_nonzero == 0) ? 1 : 0;
    }
}
__device__ __forceinline__ int edge_at(const void* __restrict__ ei, size_t idx) {
    if (g_is64) return (int)((const long long*)ei)[idx];
    return ((const int*)ei)[idx];
}

// ---------------- CSR build ----------------
__global__ void k_init_deg() {
    int i = blockIdx.x * blockDim.x + threadIdx.x;
    if (i < NN) g_deg[i] = 1;
}
__global__ void k_count_edges(const void* __restrict__ ei) {
    int i = blockIdx.x * blockDim.x + threadIdx.x;
    if (i < EE) atomicAdd(&g_deg[edge_at(ei, (size_t)EE + i)], 1);
}

// 3-kernel parallel scan
__global__ void k_scan_partial() {  // grid NSB, 256 thr
    __shared__ int sh[256];
    int b = blockIdx.x, t = threadIdx.x;
    int base = b * SCAN_BLK;
    int sum = 0;
    for (int i = t; i < SCAN_BLK; i += 256) {
        int g = base + i;
        if (g < NN) sum += g_deg[g];
    }
    sh[t] = sum; __syncthreads();
    for (int o = 128; o; o >>= 1) { if (t < o) sh[t] += sh[t + o]; __syncthreads(); }
    if (t == 0) g_bsum[b] = sh[0];
}
__global__ void k_scan_tops() {  // 1 block, 128 thr (NSB <= 128)
    __shared__ int sh[128];
    int t = threadIdx.x;
    int v = (t < NSB) ? g_bsum[t] : 0;
    sh[t] = v; __syncthreads();
    for (int o = 1; o < 128; o <<= 1) {
        int u = (t >= o) ? sh[t - o] : 0; __syncthreads();
        sh[t] += u; __syncthreads();
    }
    if (t < NSB) g_bbase[t] = sh[t] - v;
    if (t == 127) g_off[NN] = sh[127];
}
__global__ void k_scan_final() {  // grid NSB, 1024 thr
    __shared__ int sh[SCAN_BLK];
    int b = blockIdx.x, t = threadIdx.x;
    int g = b * SCAN_BLK + t;
    int v = (g < NN) ? g_deg[g] : 0;
    sh[t] = v; __syncthreads();
    for (int o = 1; o < SCAN_BLK; o <<= 1) {
        int u = (t >= o) ? sh[t - o] : 0; __syncthreads();
        sh[t] += u; __syncthreads();
    }
    if (g < NN) g_off[g] = g_bbase[b] + sh[t] - v;
}

__global__ void k_scatter_self() {
    int i = blockIdx.x * blockDim.x + threadIdx.x;
    if (i < NN) { int o = g_off[i]; g_csr[o] = i; g_cur[i] = o + 1; }
}
__global__ void k_scatter_edges(const void* __restrict__ ei) {
    int i = blockIdx.x * blockDim.x + threadIdx.x;
    if (i < EE) {
        int d = edge_at(ei, (size_t)EE + i);
        int p = atomicAdd(&g_cur[d], 1);
        g_csr[p] = edge_at(ei, i);
    }
}

// ---------------- W^T hi/lo conversion (tiny, per layer) ----------------
__global__ void k_convB(const float* __restrict__ W, int K, int Ncol) {
    int idx = blockIdx.x * blockDim.x + threadIdx.x;   // n*K + k
    if (idx >= K * Ncol) return;
    int n = idx / K, k = idx % K;
    float w = W[k * Ncol + n];
    __nv_bfloat16 h = __float2bfloat16(w);
    __nv_bfloat16 l = __float2bfloat16(w - __bfloat162float(h));
    g_Bh[idx] = h; g_Bl[idx] = l;
}

// ---------------- fused-conversion bf16 MMA GEMM (3-pass hi/lo split) ----------------
// g_h[row, nBase:nBase+128] = Ah@Bh^T + Al@Bh^T + Ah@Bl^T, with A converted from
// fp32 source (x or g_agg) on the fly per 64-wide k-chunk.
// K = GEMM depth == A row stride. NT = output row width. grid (MPAD/128, NT/128).
// CTA 128x128, 8 warps 2x4, warp tile 64x32. Smem = 48 KB (Ah + Al + B).
template <int K, int NT>
__global__ __launch_bounds__(256) void k_mgemm(const float* __restrict__ Aext) {
    __shared__ __align__(1024) char smAh[128 * 128];
    __shared__ __align__(1024) char smAl[128 * 128];
    __shared__ __align__(1024) char smB [128 * 128];

    const float* __restrict__ A = Aext ? Aext : (const float*)g_agg;
    const int tid = threadIdx.x;
    const int wid = tid >> 5;
    const int lane = tid & 31;
    const int wm = wid >> 2;          // 0..1
    const int wn = wid & 3;           // 0..3
    const size_t rowBase = (size_t)blockIdx.x * 128;
    const int nBase = blockIdx.y * 128;
    const uint32_t sAh = smem_u32(smAh);
    const uint32_t sAl = smem_u32(smAl);
    const uint32_t sB  = smem_u32(smB);

    float acc[4][4][4];
#pragma unroll
    for (int i = 0; i < 4; i++)
#pragma unroll
        for (int j = 0; j < 4; j++)
#pragma unroll
            for (int f = 0; f < 4; f++) acc[i][j][f] = 0.f;

    const int mat = lane >> 3;     // 0..3
    const int rr = lane & 7;

    for (int c = 0; c < K / 64; c++) {
        const int off = c * 64;

        // ---- stage A chunk fp32 -> bf16 hi/lo (128 rows x 64 cols) ----
        for (int u = tid; u < 128 * 16; u += 256) {       // 2048 float4 units
            int r = u >> 4, q = u & 15;                    // q: float4 idx within row
            float4 v = make_float4(0.f, 0.f, 0.f, 0.f);
            size_t gr = rowBase + r;
            if (gr < NN) v = *(const float4*)(A + gr * K + off + q * 4);
            __nv_bfloat16 h[4], l[4];
            float a0[4] = {v.x, v.y, v.z, v.w};
#pragma unroll
            for (int j = 0; j < 4; j++) {
                h[j] = __float2bfloat16(a0[j]);
                l[j] = __float2bfloat16(a0[j] - __bfloat162float(h[j]));
            }
            uint32_t boff = (uint32_t)(r * 128 + q * 8);
            *(uint2*)(smAh + SWZ128(boff)) = *(uint2*)h;
            *(uint2*)(smAl + SWZ128(boff)) = *(uint2*)l;
        }
        // ---- stage B chunk (bf16 hi) ----
        for (int u = tid; u < 128 * 8; u += 256) {
            int r = u >> 3, uu = u & 7;
            uint4 v = *(const uint4*)(g_Bh + (size_t)(nBase + r) * K + off + uu * 8);
            *(uint4*)(smB + SWZ128((uint32_t)(r * 128 + uu * 16))) = v;
        }
        __syncthreads();

        // ---- passes hh + lh (shared B fragments) ----
#pragma unroll
        for (int kk = 0; kk < 4; kk++) {
            const int k0 = kk * 16;
            uint32_t b[4][2];
#pragma unroll
            for (int nb = 0; nb < 2; nb++) {
                int nrow = wn * 32 + nb * 16 + (mat >> 1) * 8 + rr;
                int bcol = (k0 + (mat & 1) * 8) * 2;
                uint32_t r0, r1, r2, r3;
                ldmat_x4(r0, r1, r2, r3, sB + SWZ128((uint32_t)(nrow * 128 + bcol)));
                b[nb * 2][0] = r0;     b[nb * 2][1] = r1;
                b[nb * 2 + 1][0] = r2; b[nb * 2 + 1][1] = r3;
            }
            uint32_t a[4][4];
#pragma unroll
            for (int ms = 0; ms < 4; ms++) {
                int row = wm * 64 + ms * 16 + (mat & 1) * 8 + rr;
                int bcol = (k0 + (mat >> 1) * 8) * 2;
                ldmat_x4(a[ms][0], a[ms][1], a[ms][2], a[ms][3],
                         sAh + SWZ128((uint32_t)(row * 128 + bcol)));
            }
#pragma unroll
            for (int ms = 0; ms < 4; ms++)
#pragma unroll
                for (int ns = 0; ns < 4; ns++)
                    mma_bf16(acc[ms][ns], a[ms], b[ns]);
#pragma unroll
            for (int ms = 0; ms < 4; ms++) {
                int row = wm * 64 + ms * 16 + (mat & 1) * 8 + rr;
                int bcol = (k0 + (mat >> 1) * 8) * 2;
                ldmat_x4(a[ms][0], a[ms][1], a[ms][2], a[ms][3],
                         sAl + SWZ128((uint32_t)(row * 128 + bcol)));
            }
#pragma unroll
            for (int ms = 0; ms < 4; ms++)
#pragma unroll
                for (int ns = 0; ns < 4; ns++)
                    mma_bf16(acc[ms][ns], a[ms], b[ns]);
        }
        __syncthreads();

        // ---- restage B with lo ----
        for (int u = tid; u < 128 * 8; u += 256) {
            int r = u >> 3, uu = u & 7;
            uint4 v = *(const uint4*)(g_Bl + (size_t)(nBase + r) * K + off + uu * 8);
            *(uint4*)(smB + SWZ128((uint32_t)(r * 128 + uu * 16))) = v;
        }
        __syncthreads();

        // ---- pass hl: Ah x Bl ----
#pragma unroll
        for (int kk = 0; kk < 4; kk++) {
            const int k0 = kk * 16;
            uint32_t b[4][2];
#pragma unroll
            for (int nb = 0; nb < 2; nb++) {
                int nrow = wn * 32 + nb * 16 + (mat >> 1) * 8 + rr;
                int bcol = (k0 + (mat & 1) * 8) * 2;
                uint32_t r0, r1, r2, r3;
                ldmat_x4(r0, r1, r2, r3, sB + SWZ128((uint32_t)(nrow * 128 + bcol)));
                b[nb * 2][0] = r0;     b[nb * 2][1] = r1;
                b[nb * 2 + 1][0] = r2; b[nb * 2 + 1][1] = r3;
            }
            uint32_t a[4][4];
#pragma unroll
            for (int ms = 0; ms < 4; ms++) {
                int row = wm * 64 + ms * 16 + (mat & 1) * 8 + rr;
                int bcol = (k0 + (mat >> 1) * 8) * 2;
                ldmat_x4(a[ms][0], a[ms][1], a[ms][2], a[ms][3],
                         sAh + SWZ128((uint32_t)(row * 128 + bcol)));
            }
#pragma unroll
            for (int ms = 0; ms < 4; ms++)
#pragma unroll
                for (int ns = 0; ns < 4; ns++)
                    mma_bf16(acc[ms][ns], a[ms], b[ns]);
        }
        __syncthreads();
    }

    // epilogue: c-frag mapping (verified in R8)
    const int cr = lane >> 2;
    const int cc = (lane & 3) * 2;
#pragma unroll
    for (int ms = 0; ms < 4; ms++) {
#pragma unroll
        for (int ns = 0; ns < 4; ns++) {
            size_t row0 = rowBase + wm * 64 + ms * 16 + cr;
            int col = nBase + wn * 32 + ns * 8 + cc;
            if (row0 < NN) {
                *(float2*)(g_h + row0 * NT + col) =
                    make_float2(acc[ms][ns][0], acc[ms][ns][1]);
            }
            size_t row1 = row0 + 8;
            if (row1 < NN) {
                *(float2*)(g_h + row1 * NT + col) =
                    make_float2(acc[ms][ns][2], acc[ms][ns][3]);
            }
        }
    }
}

// ---------------- per-node attention scores ----------------
template <int CT, int H>
__global__ __launch_bounds__(256) void k_scores(const float* __restrict__ a_s,
                                                const float* __restrict__ a_d) {
    int wid = (blockIdx.x * blockDim.x + threadIdx.x) >> 5;
    int lane = threadIdx.x & 31;
    if (wid >= NN) return;
    const float* hp = g_h + (size_t)wid * CT;

    int cA = lane * 4;
    float4 hv = *(const float4*)(hp + cA);
    float4 sv = *(const float4*)(a_s + cA);
    float4 dv = *(const float4*)(a_d + cA);
    float psA = hv.x * sv.x + hv.y * sv.y + hv.z * sv.z + hv.w * sv.w;
    float pdA = hv.x * dv.x + hv.y * dv.y + hv.z * dv.z + hv.w * dv.w;

    if (CT == 256) {
        int cB = 128 + lane * 4;
        float4 hv2 = *(const float4*)(hp + cB);
        float4 sv2 = *(const float4*)(a_s + cB);
        float4 dv2 = *(const float4*)(a_d + cB);
        float psB = hv2.x * sv2.x + hv2.y * sv2.y + hv2.z * sv2.z + hv2.w * sv2.w;
        float pdB = hv2.x * dv2.x + hv2.y * dv2.y + hv2.z * dv2.z + hv2.w * dv2.w;
#pragma unroll
        for (int o = 8; o; o >>= 1) {
            psA += __shfl_xor_sync(0xffffffffu, psA, o);
            pdA += __shfl_xor_sync(0xffffffffu, pdA, o);
            psB += __shfl_xor_sync(0xffffffffu, psB, o);
            pdB += __shfl_xor_sync(0xffffffffu, pdB, o);
        }
        if (lane == 0)  { g_als[wid * 4 + 0] = psA; g_ald[wid * 4 + 0] = pdA;
                          g_als[wid * 4 + 2] = psB; g_ald[wid * 4 + 2] = pdB; }
        if (lane == 16) { g_als[wid * 4 + 1] = psA; g_ald[wid * 4 + 1] = pdA;
                          g_als[wid * 4 + 3] = psB; g_ald[wid * 4 + 3] = pdB; }
    } else {
#pragma unroll
        for (int o = 16; o; o >>= 1) {
            psA += __shfl_xor_sync(0xffffffffu, psA, o);
            pdA += __shfl_xor_sync(0xffffffffu, pdA, o);
        }
        if (lane == 0) { g_als[wid] = psA; g_ald[wid] = pdA; }
    }
}

__device__ __forceinline__ float lrelu(float x) { return x > 0.f ? x : SLOPE * x; }
__device__ __forceinline__ float elu(float x)   { return x > 0.f ? x : expm1f(x); }

// ---------------- warp-per-dst-node softmax + aggregation ----------------
template <int CT, int H, bool DO_ELU, bool EXT_OUT>
__global__ __launch_bounds__(256) void k_agg(const float* __restrict__ bias,
                                             float* __restrict__ extOut) {
    int n = (blockIdx.x * blockDim.x + threadIdx.x) >> 5;
    int lane = threadIdx.x & 31;
    if (n >= NN) return;
    float* __restrict__ out = EXT_OUT ? extOut : (float*)g_agg;
    const int beg = g_off[n], end = g_off[n + 1];
    const float* __restrict__ h = g_h;
    const float* __restrict__ als = g_als;
    const float* __restrict__ ald = g_ald;

    if (H == 4) {
        float4 ad = *(const float4*)(ald + (size_t)n * 4);
        float4 m = make_float4(-INFINITY, -INFINITY, -INFINITY, -INFINITY);
        for (int i = beg + lane; i < end; i += 32) {
            int s = g_csr[i];
            float4 as = *(const float4*)(als + (size_t)s * 4);
            m.x = fmaxf(m.x, lrelu(as.x + ad.x));
            m.y = fmaxf(m.y, lrelu(as.y + ad.y));
            m.z = fmaxf(m.z, lrelu(as.z + ad.z));
            m.w = fmaxf(m.w, lrelu(as.w + ad.w));
        }
#pragma unroll
        for (int o = 16; o; o >>= 1) {
            m.x = fmaxf(m.x, __shfl_xor_sync(0xffffffffu, m.x, o));
            m.y = fmaxf(m.y, __shfl_xor_sync(0xffffffffu, m.y, o));
            m.z = fmaxf(m.z, __shfl_xor_sync(0xffffffffu, m.z, o));
            m.w = fmaxf(m.w, __shfl_xor_sync(0xffffffffu, m.w, o));
        }
        float4 den = make_float4(0.f, 0.f, 0.f, 0.f);
        for (int i = beg + lane; i < end; i += 32) {
            int s = g_csr[i];
            float4 as = *(const float4*)(als + (size_t)s * 4);
            den.x += __expf(lrelu(as.x + ad.x) - m.x);
            den.y += __expf(lrelu(as.y + ad.y) - m.y);
            den.z += __expf(lrelu(as.z + ad.z) - m.z);
            den.w += __expf(lrelu(as.w + ad.w) - m.w);
        }
#pragma unroll
        for (int o = 16; o; o >>= 1) {
            den.x += __shfl_xor_sync(0xffffffffu, den.x, o);
            den.y += __shfl_xor_sync(0xffffffffu, den.y, o);
            den.z += __shfl_xor_sync(0xffffffffu, den.z, o);
            den.w += __shfl_xor_sync(0xffffffffu, den.w, o);
        }
        float4 inv = make_float4(1.f / (den.x + 1e-16f), 1.f / (den.y + 1e-16f),
                                 1.f / (den.z + 1e-16f), 1.f / (den.w + 1e-16f));
        const int hA = lane >> 4;
        const float adA = hA ? ad.y : ad.x;
        const float adB = hA ? ad.w : ad.z;
        const float mA  = hA ? m.y  : m.x;
        const float mB  = hA ? m.w  : m.z;
        const float ivA = hA ? inv.y : inv.x;
        const float ivB = hA ? inv.w : inv.z;
        const int cA = lane * 4;
        const int cB = 128 + lane * 4;
        float acc[8] = {0.f, 0.f, 0.f, 0.f, 0.f, 0.f, 0.f, 0.f};
        for (int i = beg; i < end; i++) {
            int s = g_csr[i];
            float4 as = *(const float4*)(als + (size_t)s * 4);
            float asA = hA ? as.y : as.x;
            float asB = hA ? as.w : as.z;
            float alA = __expf(lrelu(asA + adA) - mA) * ivA;
            float alB = __expf(lrelu(asB + adB) - mB) * ivB;
            const float* hp = h + (size_t)s * 256;
            float4 v0 = *(const float4*)(hp + cA);
            float4 v1 = *(const float4*)(hp + cB);
            acc[0] = fmaf(alA, v0.x, acc[0]); acc[1] = fmaf(alA, v0.y, acc[1]);
            acc[2] = fmaf(alA, v0.z, acc[2]); acc[3] = fmaf(alA, v0.w, acc[3]);
            acc[4] = fmaf(alB, v1.x, acc[4]); acc[5] = fmaf(alB, v1.y, acc[5]);
            acc[6] = fmaf(alB, v1.z, acc[6]); acc[7] = fmaf(alB, v1.w, acc[7]);
        }
        float4 b0 = *(const float4*)(bias + cA);
        float4 b1 = *(const float4*)(bias + cB);
        float4 o0, o1;
        o0.x = acc[0] + b0.x; o0.y = acc[1] + b0.y; o0.z = acc[2] + b0.z; o0.w = acc[3] + b0.w;
        o1.x = acc[4] + b1.x; o1.y = acc[5] + b1.y; o1.z = acc[6] + b1.z; o1.w = acc[7] + b1.w;
        if (DO_ELU) {
            o0.x = elu(o0.x); o0.y = elu(o0.y); o0.z = elu(o0.z); o0.w = elu(o0.w);
            o1.x = elu(o1.x); o1.y = elu(o1.y); o1.z = elu(o1.z); o1.w = elu(o1.w);
        }
        float* op = out + (size_t)n * 256;
        *(float4*)(op + cA) = o0;
        *(float4*)(op + cB) = o1;
    } else {
        float adn = ald[n];
        float m = -INFINITY;
        for (int i = beg + lane; i < end; i += 32) {
            int s = g_csr[i];
            m = fmaxf(m, lrelu(als[s] + adn));
        }
#pragma unroll
        for (int o = 16; o; o >>= 1) m = fmaxf(m, __shfl_xor_sync(0xffffffffu, m, o));
        float den = 0.f;
        for (int i = beg + lane; i < end; i += 32) {
            int s = g_csr[i];
            den += __expf(lrelu(als[s] + adn) - m);
        }
#pragma unroll
        for (int o = 16; o; o >>= 1) den += __shfl_xor_sync(0xffffffffu, den, o);
        float iv = 1.f / (den + 1e-16f);
        const int cA = lane * 4;
        float acc[4] = {0.f, 0.f, 0.f, 0.f};
        for (int i = beg; i < end; i++) {
            int s = g_csr[i];
            float al = __expf(lrelu(als[s] + adn) - m) * iv;
            float4 v = *(const float4*)(h + (size_t)s * 128 + cA);
            acc[0] = fmaf(al, v.x, acc[0]); acc[1] = fmaf(al, v.y, acc[1]);
            acc[2] = fmaf(al, v.z, acc[2]); acc[3] = fmaf(al, v.w, acc[3]);
        }
        float4 bv = *(const float4*)(bias + cA);
        float4 o0;
        o0.x = acc[0] + bv.x; o0.y = acc[1] + bv.y;
        o0.z = acc[2] + bv.z; o0.w = acc[3] + bv.w;
        *(float4*)(out + (size_t)n * 128 + cA) = o0;
    }
}

// ---------------- launch ----------------
extern "C" void kernel_launch(void* const* d_in, const int* in_sizes, int n_in,
                              void* d_out, int out_size) {
    const float* x   = (const float*)d_in[0];
    const void*  ei  = d_in[1];
    const float* W0  = (const float*)d_in[2];
    const float* as0 = (const float*)d_in[3];
    const float* ad0 = (const float*)d_in[4];
    const float* b0  = (const float*)d_in[5];
    const float* W1  = (const float*)d_in[6];
    const float* as1 = (const float*)d_in[7];
    const float* ad1 = (const float*)d_in[8];
    const float* b1  = (const float*)d_in[9];
    const float* W2  = (const float*)d_in[10];
    const float* as2 = (const float*)d_in[11];
    const float* ad2 = (const float*)d_in[12];
    const float* b2  = (const float*)d_in[13];
    float* out = (float*)d_out;

    const int TB = 256;
    const int gN = (NN + TB - 1) / TB;
    const int gE = (EE + TB - 1) / TB;
    const int gW = (NN + 7) / 8;
    const int GEMM_GRID = MPAD / 128;  // 782
    dim3 grid2(GEMM_GRID, 2);
    dim3 grid1(GEMM_GRID, 1);

    // Order puts mgemm L0 at our launch index 3 (= ncu's observed profile slot).
    k_detect<<<1, 32>>>((const int*)ei);                              // 0
    k_convB<<<(F0 * HID + TB - 1) / TB, TB>>>(W0, F0, HID);           // 1
    k_init_deg<<<gN, TB>>>();                                         // 2
    k_mgemm<128, 256><<<grid2, 256>>>(x);                             // 3  <- profiled
    k_count_edges<<<gE, TB>>>(ei);                                    // 4
    k_scan_partial<<<NSB, 256>>>();                                   // 5
    k_scan_tops<<<1, 128>>>();                                        // 6
    k_scan_final<<<NSB, SCAN_BLK>>>();                                // 7
    k_scatter_self<<<gN, TB>>>();                                     // 8
    k_scatter_edges<<<gE, TB>>>(ei);                                  // 9
    k_scores<256, 4><<<gW, TB>>>(as0, ad0);                           // 10
    k_agg<256, 4, true, false><<<gW, TB>>>(b0, nullptr);              // 11

    // ---- layer 1: g_agg[N,256] @ W1[256,256] ----
    k_convB<<<(HID * HID + TB - 1) / TB, TB>>>(W1, HID, HID);
    k_mgemm<256, 256><<<grid2, 256>>>(nullptr);
    k_scores<256, 4><<<gW, TB>>>(as1, ad1);
    k_agg<256, 4, true, false><<<gW, TB>>>(b1, nullptr);

    // ---- layer 2: g_agg[N,256] @ W2[256,128], 1 head, no ELU ----
    k_convB<<<(HID * OUTC + TB - 1) / TB, TB>>>(W2, HID, OUTC);
    k_mgemm<256, 128><<<grid1, 256>>>(nullptr);
    k_scores<128, 1><<<gW, TB>>>(as2, ad2);
    k_agg<128, 1, false, true><<<gW, TB>>>(b2, out);
}

// round 11
// speedup vs baseline: 1.9166x; 1.2404x over previous
#include <cuda_runtime.h>
#include <cuda_bf16.h>
#include <cstdint>
#include <math.h>

// ---------------- problem constants (fixed shapes) ----------------
#define NN 100000      // nodes
#define EE 400000      // edges (without self loops)
#define ET (EE + NN)   // total edges incl self loops
#define F0 128         // input features
#define HID 256        // hidden (4 heads x 64)
#define OUTC 128       // output features
#define SLOPE 0.2f
#define MPAD 100096    // 782 * 128 (row-padded M for the GEMM)

// ---------------- device scratch (no allocations allowed) ----------------
__device__ __align__(16) float g_h[(size_t)NN * HID];
__device__ __align__(16) float g_agg[(size_t)NN * HID];
__device__ __align__(16) float g_als[(size_t)NN * 4];
__device__ __align__(16) float g_ald[(size_t)NN * 4];
__device__ int   g_deg[NN];
__device__ int   g_off[NN + 1];
__device__ int   g_cur[NN];
__device__ int   g_csr[ET];
__device__ int   g_is64;

// bf16 split W^T (small, per layer)
__device__ __align__(16) __nv_bfloat16 g_Bh[256 * 256];   // W^T hi  [N, K]
__device__ __align__(16) __nv_bfloat16 g_Bl[256 * 256];   // W^T lo  [N, K]

// scan temporaries
#define SCAN_BLK 1024
#define NSB ((NN + SCAN_BLK - 1) / SCAN_BLK)   // 98
__device__ int g_bsum[NSB];
__device__ int g_bbase[NSB];

// ---------------- helpers ----------------
__device__ __forceinline__ uint32_t smem_u32(const void* p) {
    uint32_t a;
    asm("{ .reg .u64 t; cvta.to.shared.u64 t, %1; cvt.u32.u64 %0, t; }" : "=r"(a) : "l"(p));
    return a;
}
#define SWZ128(off) ((off) ^ (((off) >> 3) & 0x70))

__device__ __forceinline__ void ldmat_x4(uint32_t& r0, uint32_t& r1, uint32_t& r2,
                                         uint32_t& r3, uint32_t addr) {
    asm volatile("ldmatrix.sync.aligned.m8n8.x4.shared.b16 {%0,%1,%2,%3}, [%4];"
        : "=r"(r0), "=r"(r1), "=r"(r2), "=r"(r3) : "r"(addr));
}
__device__ __forceinline__ void mma_bf16(float* d, const uint32_t* a, const uint32_t* b) {
    asm volatile("mma.sync.aligned.m16n8k16.row.col.f32.bf16.bf16.f32 "
        "{%0,%1,%2,%3}, {%4,%5,%6,%7}, {%8,%9}, {%0,%1,%2,%3};"
        : "+f"(d[0]), "+f"(d[1]), "+f"(d[2]), "+f"(d[3])
        : "r"(a[0]), "r"(a[1]), "r"(a[2]), "r"(a[3]), "r"(b[0]), "r"(b[1]));
}
__device__ __forceinline__ void cp16(uint32_t dst, const void* src, uint32_t src_bytes) {
    asm volatile("cp.async.cg.shared.global [%0], [%1], 16, %2;"
        :: "r"(dst), "l"(src), "r"(src_bytes));
}
#define CP_COMMIT() asm volatile("cp.async.commit_group;" ::: "memory")
#define CP_WAIT0()  asm volatile("cp.async.wait_group 0;" ::: "memory")
#define CP_WAIT1()  asm volatile("cp.async.wait_group 1;" ::: "memory")

// ---------------- edge-index dtype probe ----------------
__global__ void k_detect(const int* __restrict__ ei32) {
    if (threadIdx.x == 0 && blockIdx.x == 0) {
        int odd_nonzero = 0;
        for (int i = 1; i < 256; i += 2) odd_nonzero += (ei32[i] != 0);
        g_is64 = (odd_nonzero == 0) ? 1 : 0;
    }
}
__device__ __forceinline__ int edge_at(const void* __restrict__ ei, size_t idx) {
    if (g_is64) return (int)((const long long*)ei)[idx];
    return ((const int*)ei)[idx];
}

// ---------------- CSR build ----------------
__global__ void k_init_deg() {
    int i = blockIdx.x * blockDim.x + threadIdx.x;
    if (i < NN) g_deg[i] = 1;
}
__global__ void k_count_edges(const void* __restrict__ ei) {
    int i = blockIdx.x * blockDim.x + threadIdx.x;
    if (i < EE) atomicAdd(&g_deg[edge_at(ei, (size_t)EE + i)], 1);
}

__global__ void k_scan_partial() {  // grid NSB, 256 thr
    __shared__ int sh[256];
    int b = blockIdx.x, t = threadIdx.x;
    int base = b * SCAN_BLK;
    int sum = 0;
    for (int i = t; i < SCAN_BLK; i += 256) {
        int g = base + i;
        if (g < NN) sum += g_deg[g];
    }
    sh[t] = sum; __syncthreads();
    for (int o = 128; o; o >>= 1) { if (t < o) sh[t] += sh[t + o]; __syncthreads(); }
    if (t == 0) g_bsum[b] = sh[0];
}
__global__ void k_scan_tops() {  // 1 block, 128 thr
    __shared__ int sh[128];
    int t = threadIdx.x;
    int v = (t < NSB) ? g_bsum[t] : 0;
    sh[t] = v; __syncthreads();
    for (int o = 1; o < 128; o <<= 1) {
        int u = (t >= o) ? sh[t - o] : 0; __syncthreads();
        sh[t] += u; __syncthreads();
    }
    if (t < NSB) g_bbase[t] = sh[t] - v;
    if (t == 127) g_off[NN] = sh[127];
}
__global__ void k_scan_final() {  // grid NSB, 1024 thr
    __shared__ int sh[SCAN_BLK];
    int b = blockIdx.x, t = threadIdx.x;
    int g = b * SCAN_BLK + t;
    int v = (g < NN) ? g_deg[g] : 0;
    sh[t] = v; __syncthreads();
    for (int o = 1; o < SCAN_BLK; o <<= 1) {
        int u = (t >= o) ? sh[t - o] : 0; __syncthreads();
        sh[t] += u; __syncthreads();
    }
    if (g < NN) g_off[g] = g_bbase[b] + sh[t] - v;
}

__global__ void k_scatter_self() {
    int i = blockIdx.x * blockDim.x + threadIdx.x;
    if (i < NN) { int o = g_off[i]; g_csr[o] = i; g_cur[i] = o + 1; }
}
__global__ void k_scatter_edges(const void* __restrict__ ei) {
    int i = blockIdx.x * blockDim.x + threadIdx.x;
    if (i < EE) {
        int d = edge_at(ei, (size_t)EE + i);
        int p = atomicAdd(&g_cur[d], 1);
        g_csr[p] = edge_at(ei, i);
    }
}

// ---------------- W^T hi/lo conversion (tiny, per layer) ----------------
__global__ void k_convB(const float* __restrict__ W, int K, int Ncol) {
    int idx = blockIdx.x * blockDim.x + threadIdx.x;   // n*K + k
    if (idx >= K * Ncol) return;
    int n = idx / K, k = idx % K;
    float w = W[k * Ncol + n];
    __nv_bfloat16 h = __float2bfloat16(w);
    __nv_bfloat16 l = __float2bfloat16(w - __bfloat162float(h));
    g_Bh[idx] = h; g_Bl[idx] = l;
}

// ---------------- cp.async-pipelined bf16 MMA GEMM (3-pass hi/lo split) ----------------
// Dynamic smem layout (1024-aligned base):
//   smF  [0,      65536)  : 2 x (128 x 64 fp32 raw A chunk), linear, row stride 256B
//   smAh [65536,  81920)  : 128 x 64 bf16 hi, SW128
//   smAl [81920,  98304)  : 128 x 64 bf16 lo, SW128
//   smB  [98304, 163840)  : 2 x { Bh 16KB ; Bl 16KB }, SW128
#define SM_BYTES (163840 + 1024)
template <int K, int NT>
__global__ __launch_bounds__(256, 1) void k_mgemm(const float* __restrict__ Aext) {
    extern __shared__ char dynsm[];
    char* smp = (char*)(((uintptr_t)dynsm + 1023) & ~(uintptr_t)1023);
    const uint32_t sF  = smem_u32(smp);
    const uint32_t sAh = sF + 65536;
    const uint32_t sAl = sF + 81920;
    const uint32_t sB  = sF + 98304;

    const float* __restrict__ A = Aext ? Aext : (const float*)g_agg;
    const int tid = threadIdx.x;
    const int wid = tid >> 5;
    const int lane = tid & 31;
    const int wm = wid >> 2;
    const int wn = wid & 3;
    const size_t rowBase = (size_t)blockIdx.x * 128;
    const int nBase = blockIdx.y * 128;

    float acc[4][4][4];
#pragma unroll
    for (int i = 0; i < 4; i++)
#pragma unroll
        for (int j = 0; j < 4; j++)
#pragma unroll
            for (int f = 0; f < 4; f++) acc[i][j][f] = 0.f;

    const int mat = lane >> 3;
    const int rr = lane & 7;
    constexpr int CH = K / 64;

    // ---- staging (cp.async) for chunk cc ----
    auto stage = [&](int cc) {
        const int buf = cc & 1;
        const int off = cc * 64;
        // raw fp32 A: 2048 16B units, linear layout
#pragma unroll
        for (int u = tid; u < 2048; u += 256) {
            int r = u >> 4, q = u & 15;
            size_t gr = rowBase + r;
            uint32_t ok = (gr < NN) ? 16u : 0u;
            const float* src = A + (gr < NN ? gr : 0) * K + off + q * 4;
            cp16(sF + buf * 32768 + (uint32_t)(r * 256 + q * 16), src, ok);
        }
        // Bh + Bl: 1024 16B units each, swizzled dest
#pragma unroll
        for (int u = tid; u < 1024; u += 256) {
            int r = u >> 3, uu = u & 7;
            uint32_t boff = SWZ128((uint32_t)(r * 128 + uu * 16));
            const size_t gsrc = (size_t)(nBase + r) * K + off + uu * 8;
            cp16(sB + buf * 32768 + boff,         g_Bh + gsrc, 16u);
            cp16(sB + buf * 32768 + 16384 + boff, g_Bl + gsrc, 16u);
        }
    };

    stage(0); CP_COMMIT();

    for (int c = 0; c < CH; c++) {
        const int buf = c & 1;
        if (c + 1 < CH) { stage(c + 1); CP_COMMIT(); CP_WAIT1(); }
        else            { CP_WAIT0(); }
        __syncthreads();   // chunk-c data visible to all threads

        // ---- convert raw fp32 -> bf16 hi/lo in smem ----
        const char* fsrc = smp + buf * 32768;
#pragma unroll
        for (int u = tid; u < 2048; u += 256) {
            int r = u >> 4, q = u & 15;
            float4 v = *(const float4*)(fsrc + r * 256 + q * 16);
            float a0[4] = {v.x, v.y, v.z, v.w};
            __nv_bfloat16 h[4], l[4];
#pragma unroll
            for (int j = 0; j < 4; j++) {
                h[j] = __float2bfloat16(a0[j]);
                l[j] = __float2bfloat16(a0[j] - __bfloat162float(h[j]));
            }
            uint32_t boff = SWZ128((uint32_t)(r * 128 + q * 8));
            *(uint2*)(smp + 65536 + boff) = *(uint2*)h;
            *(uint2*)(smp + 81920 + boff) = *(uint2*)l;
        }
        __syncthreads();

        // ---- compute: hh, hl (Ah regs reused), lh ----
        const uint32_t bHi = sB + buf * 32768;
        const uint32_t bLo = bHi + 16384;
#pragma unroll
        for (int kk = 0; kk < 4; kk++) {
            const int k0 = kk * 16;
            uint32_t bh[4][2], bl[4][2];
#pragma unroll
            for (int nb = 0; nb < 2; nb++) {
                int nrow = wn * 32 + nb * 16 + (mat >> 1) * 8 + rr;
                uint32_t boff = SWZ128((uint32_t)(nrow * 128 + (k0 + (mat & 1) * 8) * 2));
                uint32_t r0, r1, r2, r3;
                ldmat_x4(r0, r1, r2, r3, bHi + boff);
                bh[nb * 2][0] = r0;     bh[nb * 2][1] = r1;
                bh[nb * 2 + 1][0] = r2; bh[nb * 2 + 1][1] = r3;
                ldmat_x4(r0, r1, r2, r3, bLo + boff);
                bl[nb * 2][0] = r0;     bl[nb * 2][1] = r1;
                bl[nb * 2 + 1][0] = r2; bl[nb * 2 + 1][1] = r3;
            }
            uint32_t a[4][4];
#pragma unroll
            for (int ms = 0; ms < 4; ms++) {
                int row = wm * 64 + ms * 16 + (mat & 1) * 8 + rr;
                uint32_t aoff = SWZ128((uint32_t)(row * 128 + (k0 + (mat >> 1) * 8) * 2));
                ldmat_x4(a[ms][0], a[ms][1], a[ms][2], a[ms][3], sAh + aoff);
            }
#pragma unroll
            for (int ms = 0; ms < 4; ms++)
#pragma unroll
                for (int ns = 0; ns < 4; ns++)
                    mma_bf16(acc[ms][ns], a[ms], bh[ns]);
#pragma unroll
            for (int ms = 0; ms < 4; ms++)
#pragma unroll
                for (int ns = 0; ns < 4; ns++)
                    mma_bf16(acc[ms][ns], a[ms], bl[ns]);
#pragma unroll
            for (int ms = 0; ms < 4; ms++) {
                int row = wm * 64 + ms * 16 + (mat & 1) * 8 + rr;
                uint32_t aoff = SWZ128((uint32_t)(row * 128 + (k0 + (mat >> 1) * 8) * 2));
                ldmat_x4(a[ms][0], a[ms][1], a[ms][2], a[ms][3], sAl + aoff);
            }
#pragma unroll
            for (int ms = 0; ms < 4; ms++)
#pragma unroll
                for (int ns = 0; ns < 4; ns++)
                    mma_bf16(acc[ms][ns], a[ms], bh[ns]);
        }
        __syncthreads();   // protect smAh/Al (and finished smB buf) for next iteration
    }

    // ---- epilogue (c-frag mapping verified in R8/R10) ----
    const int cr = lane >> 2;
    const int cc2 = (lane & 3) * 2;
#pragma unroll
    for (int ms = 0; ms < 4; ms++) {
#pragma unroll
        for (int ns = 0; ns < 4; ns++) {
            size_t row0 = rowBase + wm * 64 + ms * 16 + cr;
            int col = nBase + wn * 32 + ns * 8 + cc2;
            if (row0 < NN) {
                *(float2*)(g_h + row0 * NT + col) =
                    make_float2(acc[ms][ns][0], acc[ms][ns][1]);
            }
            size_t row1 = row0 + 8;
            if (row1 < NN) {
                *(float2*)(g_h + row1 * NT + col) =
                    make_float2(acc[ms][ns][2], acc[ms][ns][3]);
            }
        }
    }
}

// ---------------- per-node attention scores ----------------
template <int CT, int H>
__global__ __launch_bounds__(256) void k_scores(const float* __restrict__ a_s,
                                                const float* __restrict__ a_d) {
    int wid = (blockIdx.x * blockDim.x + threadIdx.x) >> 5;
    int lane = threadIdx.x & 31;
    if (wid >= NN) return;
    const float* hp = g_h + (size_t)wid * CT;

    int cA = lane * 4;
    float4 hv = *(const float4*)(hp + cA);
    float4 sv = *(const float4*)(a_s + cA);
    float4 dv = *(const float4*)(a_d + cA);
    float psA = hv.x * sv.x + hv.y * sv.y + hv.z * sv.z + hv.w * sv.w;
    float pdA = hv.x * dv.x + hv.y * dv.y + hv.z * dv.z + hv.w * dv.w;

    if (CT == 256) {
        int cB = 128 + lane * 4;
        float4 hv2 = *(const float4*)(hp + cB);
        float4 sv2 = *(const float4*)(a_s + cB);
        float4 dv2 = *(const float4*)(a_d + cB);
        float psB = hv2.x * sv2.x + hv2.y * sv2.y + hv2.z * sv2.z + hv2.w * sv2.w;
        float pdB = hv2.x * dv2.x + hv2.y * dv2.y + hv2.z * dv2.z + hv2.w * dv2.w;
#pragma unroll
        for (int o = 8; o; o >>= 1) {
            psA += __shfl_xor_sync(0xffffffffu, psA, o);
            pdA += __shfl_xor_sync(0xffffffffu, pdA, o);
            psB += __shfl_xor_sync(0xffffffffu, psB, o);
            pdB += __shfl_xor_sync(0xffffffffu, pdB, o);
        }
        if (lane == 0)  { g_als[wid * 4 + 0] = psA; g_ald[wid * 4 + 0] = pdA;
                          g_als[wid * 4 + 2] = psB; g_ald[wid * 4 + 2] = pdB; }
        if (lane == 16) { g_als[wid * 4 + 1] = psA; g_ald[wid * 4 + 1] = pdA;
                          g_als[wid * 4 + 3] = psB; g_ald[wid * 4 + 3] = pdB; }
    } else {
#pragma unroll
        for (int o = 16; o; o >>= 1) {
            psA += __shfl_xor_sync(0xffffffffu, psA, o);
            pdA += __shfl_xor_sync(0xffffffffu, pdA, o);
        }
        if (lane == 0) { g_als[wid] = psA; g_ald[wid] = pdA; }
    }
}

__device__ __forceinline__ float lrelu(float x) { return x > 0.f ? x : SLOPE * x; }
__device__ __forceinline__ float elu(float x)   { return x > 0.f ? x : expm1f(x); }

// ---------------- warp-per-dst-node softmax + aggregation ----------------
template <int CT, int H, bool DO_ELU, bool EXT_OUT>
__global__ __launch_bounds__(256) void k_agg(const float* __restrict__ bias,
                                             float* __restrict__ extOut) {
    int n = (blockIdx.x * blockDim.x + threadIdx.x) >> 5;
    int lane = threadIdx.x & 31;
    if (n >= NN) return;
    float* __restrict__ out = EXT_OUT ? extOut : (float*)g_agg;
    const int beg = g_off[n], end = g_off[n + 1];
    const float* __restrict__ h = g_h;
    const float* __restrict__ als = g_als;
    const float* __restrict__ ald = g_ald;

    if (H == 4) {
        float4 ad = *(const float4*)(ald + (size_t)n * 4);
        float4 m = make_float4(-INFINITY, -INFINITY, -INFINITY, -INFINITY);
        for (int i = beg + lane; i < end; i += 32) {
            int s = g_csr[i];
            float4 as = *(const float4*)(als + (size_t)s * 4);
            m.x = fmaxf(m.x, lrelu(as.x + ad.x));
            m.y = fmaxf(m.y, lrelu(as.y + ad.y));
            m.z = fmaxf(m.z, lrelu(as.z + ad.z));
            m.w = fmaxf(m.w, lrelu(as.w + ad.w));
        }
#pragma unroll
        for (int o = 16; o; o >>= 1) {
            m.x = fmaxf(m.x, __shfl_xor_sync(0xffffffffu, m.x, o));
            m.y = fmaxf(m.y, __shfl_xor_sync(0xffffffffu, m.y, o));
            m.z = fmaxf(m.z, __shfl_xor_sync(0xffffffffu, m.z, o));
            m.w = fmaxf(m.w, __shfl_xor_sync(0xffffffffu, m.w, o));
        }
        float4 den = make_float4(0.f, 0.f, 0.f, 0.f);
        for (int i = beg + lane; i < end; i += 32) {
            int s = g_csr[i];
            float4 as = *(const float4*)(als + (size_t)s * 4);
            den.x += __expf(lrelu(as.x + ad.x) - m.x);
            den.y += __expf(lrelu(as.y + ad.y) - m.y);
            den.z += __expf(lrelu(as.z + ad.z) - m.z);
            den.w += __expf(lrelu(as.w + ad.w) - m.w);
        }
#pragma unroll
        for (int o = 16; o; o >>= 1) {
            den.x += __shfl_xor_sync(0xffffffffu, den.x, o);
            den.y += __shfl_xor_sync(0xffffffffu, den.y, o);
            den.z += __shfl_xor_sync(0xffffffffu, den.z, o);
            den.w += __shfl_xor_sync(0xffffffffu, den.w, o);
        }
        float4 inv = make_float4(1.f / (den.x + 1e-16f), 1.f / (den.y + 1e-16f),
                                 1.f / (den.z + 1e-16f), 1.f / (den.w + 1e-16f));
        const int hA = lane >> 4;
        const float adA = hA ? ad.y : ad.x;
        const float adB = hA ? ad.w : ad.z;
        const float mA  = hA ? m.y  : m.x;
        const float mB  = hA ? m.w  : m.z;
        const float ivA = hA ? inv.y : inv.x;
        const float ivB = hA ? inv.w : inv.z;
        const int cA = lane * 4;
        const int cB = 128 + lane * 4;
        float acc[8] = {0.f, 0.f, 0.f, 0.f, 0.f, 0.f, 0.f, 0.f};
        for (int i = beg; i < end; i++) {
            int s = g_csr[i];
            float4 as = *(const float4*)(als + (size_t)s * 4);
            float asA = hA ? as.y : as.x;
            float asB = hA ? as.w : as.z;
            float alA = __expf(lrelu(asA + adA) - mA) * ivA;
            float alB = __expf(lrelu(asB + adB) - mB) * ivB;
            const float* hp = h + (size_t)s * 256;
            float4 v0 = *(const float4*)(hp + cA);
            float4 v1 = *(const float4*)(hp + cB);
            acc[0] = fmaf(alA, v0.x, acc[0]); acc[1] = fmaf(alA, v0.y, acc[1]);
            acc[2] = fmaf(alA, v0.z, acc[2]); acc[3] = fmaf(alA, v0.w, acc[3]);
            acc[4] = fmaf(alB, v1.x, acc[4]); acc[5] = fmaf(alB, v1.y, acc[5]);
            acc[6] = fmaf(alB, v1.z, acc[6]); acc[7] = fmaf(alB, v1.w, acc[7]);
        }
        float4 b0 = *(const float4*)(bias + cA);
        float4 b1 = *(const float4*)(bias + cB);
        float4 o0, o1;
        o0.x = acc[0] + b0.x; o0.y = acc[1] + b0.y; o0.z = acc[2] + b0.z; o0.w = acc[3] + b0.w;
        o1.x = acc[4] + b1.x; o1.y = acc[5] + b1.y; o1.z = acc[6] + b1.z; o1.w = acc[7] + b1.w;
        if (DO_ELU) {
            o0.x = elu(o0.x); o0.y = elu(o0.y); o0.z = elu(o0.z); o0.w = elu(o0.w);
            o1.x = elu(o1.x); o1.y = elu(o1.y); o1.z = elu(o1.z); o1.w = elu(o1.w);
        }
        float* op = out + (size_t)n * 256;
        *(float4*)(op + cA) = o0;
        *(float4*)(op + cB) = o1;
    } else {
        float adn = ald[n];
        float m = -INFINITY;
        for (int i = beg + lane; i < end; i += 32) {
            int s = g_csr[i];
            m = fmaxf(m, lrelu(als[s] + adn));
        }
#pragma unroll
        for (int o = 16; o; o >>= 1) m = fmaxf(m, __shfl_xor_sync(0xffffffffu, m, o));
        float den = 0.f;
        for (int i = beg + lane; i < end; i += 32) {
            int s = g_csr[i];
            den += __expf(lrelu(als[s] + adn) - m);
        }
#pragma unroll
        for (int o = 16; o; o >>= 1) den += __shfl_xor_sync(0xffffffffu, den, o);
        float iv = 1.f / (den + 1e-16f);
        const int cA = lane * 4;
        float acc[4] = {0.f, 0.f, 0.f, 0.f};
        for (int i = beg; i < end; i++) {
            int s = g_csr[i];
            float al = __expf(lrelu(als[s] + adn) - m) * iv;
            float4 v = *(const float4*)(h + (size_t)s * 128 + cA);
            acc[0] = fmaf(al, v.x, acc[0]); acc[1] = fmaf(al, v.y, acc[1]);
            acc[2] = fmaf(al, v.z, acc[2]); acc[3] = fmaf(al, v.w, acc[3]);
        }
        float4 bv = *(const float4*)(bias + cA);
        float4 o0;
        o0.x = acc[0] + bv.x; o0.y = acc[1] + bv.y;
        o0.z = acc[2] + bv.z; o0.w = acc[3] + bv.w;
        *(float4*)(out + (size_t)n * 128 + cA) = o0;
    }
}

// ---------------- launch ----------------
extern "C" void kernel_launch(void* const* d_in, const int* in_sizes, int n_in,
                              void* d_out, int out_size) {
    const float* x   = (const float*)d_in[0];
    const void*  ei  = d_in[1];
    const float* W0  = (const float*)d_in[2];
    const float* as0 = (const float*)d_in[3];
    const float* ad0 = (const float*)d_in[4];
    const float* b0  = (const float*)d_in[5];
    const float* W1  = (const float*)d_in[6];
    const float* as1 = (const float*)d_in[7];
    const float* ad1 = (const float*)d_in[8];
    const float* b1  = (const float*)d_in[9];
    const float* W2  = (const float*)d_in[10];
    const float* as2 = (const float*)d_in[11];
    const float* ad2 = (const float*)d_in[12];
    const float* b2  = (const float*)d_in[13];
    float* out = (float*)d_out;

    const int TB = 256;
    const int gN = (NN + TB - 1) / TB;
    const int gE = (EE + TB - 1) / TB;
    const int gW = (NN + 7) / 8;
    const int GEMM_GRID = MPAD / 128;  // 782
    dim3 grid2(GEMM_GRID, 2);
    dim3 grid1(GEMM_GRID, 1);

    // opt-in dynamic smem (idempotent; function attribute, not a stream op)
    cudaFuncSetAttribute(k_mgemm<128, 256>, cudaFuncAttributeMaxDynamicSharedMemorySize, SM_BYTES);
    cudaFuncSetAttribute(k_mgemm<256, 256>, cudaFuncAttributeMaxDynamicSharedMemorySize, SM_BYTES);
    cudaFuncSetAttribute(k_mgemm<256, 128>, cudaFuncAttributeMaxDynamicSharedMemorySize, SM_BYTES);

    // Order keeps mgemm L0 at launch index 3 (ncu's profile slot).
    k_detect<<<1, 32>>>((const int*)ei);                              // 0
    k_convB<<<(F0 * HID + TB - 1) / TB, TB>>>(W0, F0, HID);           // 1
    k_init_deg<<<gN, TB>>>();                                         // 2
    k_mgemm<128, 256><<<grid2, 256, SM_BYTES>>>(x);                   // 3  <- profiled
    k_count_edges<<<gE, TB>>>(ei);                                    // 4
    k_scan_partial<<<NSB, 256>>>();                                   // 5
    k_scan_tops<<<1, 128>>>();                                        // 6
    k_scan_final<<<NSB, SCAN_BLK>>>();                                // 7
    k_scatter_self<<<gN, TB>>>();                                     // 8
    k_scatter_edges<<<gE, TB>>>(ei);                                  // 9
    k_scores<256, 4><<<gW, TB>>>(as0, ad0);                           // 10
    k_agg<256, 4, true, false><<<gW, TB>>>(b0, nullptr);              // 11

    // ---- layer 1: g_agg[N,256] @ W1[256,256] ----
    k_convB<<<(HID * HID + TB - 1) / TB, TB>>>(W1, HID, HID);
    k_mgemm<256, 256><<<grid2, 256, SM_BYTES>>>(nullptr);
    k_scores<256, 4><<<gW, TB>>>(as1, ad1);
    k_agg<256, 4, true, false><<<gW, TB>>>(b1, nullptr);

    // ---- layer 2: g_agg[N,256] @ W2[256,128], 1 head, no ELU ----
    k_convB<<<(HID * OUTC + TB - 1) / TB, TB>>>(W2, HID, OUTC);
    k_mgemm<256, 128><<<grid1, 256, SM_BYTES>>>(nullptr);
    k_scores<128, 1><<<gW, TB>>>(as2, ad2);
    k_agg<128, 1, false, true><<<gW, TB>>>(b2, out);
}

// round 12
// speedup vs baseline: 1.9413x; 1.0129x over previous
#include <cuda_runtime.h>
#include <cuda_bf16.h>
#include <cstdint>
#include <math.h>

// ---------------- problem constants (fixed shapes) ----------------
#define NN 100000      // nodes
#define EE 400000      // edges (without self loops)
#define ET (EE + NN)   // total edges incl self loops
#define F0 128         // input features
#define HID 256        // hidden (4 heads x 64)
#define OUTC 128       // output features
#define SLOPE 0.2f
#define MPAD 100096    // 782 * 128 (row-padded M for the GEMM)

// ---------------- device scratch (no allocations allowed) ----------------
__device__ __align__(16) float g_h[(size_t)NN * HID];
__device__ __align__(16) float g_agg[(size_t)NN * HID];
__device__ __align__(16) float g_als[(size_t)NN * 4];
__device__ __align__(16) float g_ald[(size_t)NN * 4];
__device__ int   g_deg[NN];
__device__ int   g_off[NN + 1];
__device__ int   g_cur[NN];
__device__ int   g_csr[ET];
__device__ int   g_is64;

// bf16 split W^T (small, per layer)
__device__ __align__(16) __nv_bfloat16 g_Bh[256 * 256];   // W^T hi  [N, K]
__device__ __align__(16) __nv_bfloat16 g_Bl[256 * 256];   // W^T lo  [N, K]

// scan temporaries
#define SCAN_BLK 1024
#define NSB ((NN + SCAN_BLK - 1) / SCAN_BLK)   // 98
__device__ int g_bsum[NSB];
__device__ int g_bbase[NSB];

// ---------------- helpers ----------------
__device__ __forceinline__ uint32_t smem_u32(const void* p) {
    uint32_t a;
    asm("{ .reg .u64 t; cvta.to.shared.u64 t, %1; cvt.u32.u64 %0, t; }" : "=r"(a) : "l"(p));
    return a;
}
#define SWZ128(off) ((off) ^ (((off) >> 3) & 0x70))

__device__ __forceinline__ void ldmat_x4(uint32_t& r0, uint32_t& r1, uint32_t& r2,
                                         uint32_t& r3, uint32_t addr) {
    asm volatile("ldmatrix.sync.aligned.m8n8.x4.shared.b16 {%0,%1,%2,%3}, [%4];"
        : "=r"(r0), "=r"(r1), "=r"(r2), "=r"(r3) : "r"(addr));
}
__device__ __forceinline__ void mma_bf16(float* d, const uint32_t* a, const uint32_t* b) {
    asm volatile("mma.sync.aligned.m16n8k16.row.col.f32.bf16.bf16.f32 "
        "{%0,%1,%2,%3}, {%4,%5,%6,%7}, {%8,%9}, {%0,%1,%2,%3};"
        : "+f"(d[0]), "+f"(d[1]), "+f"(d[2]), "+f"(d[3])
        : "r"(a[0]), "r"(a[1]), "r"(a[2]), "r"(a[3]), "r"(b[0]), "r"(b[1]));
}
__device__ __forceinline__ void cp16(uint32_t dst, const void* src, uint32_t src_bytes) {
    asm volatile("cp.async.cg.shared.global [%0], [%1], 16, %2;"
        :: "r"(dst), "l"(src), "r"(src_bytes));
}
#define CP_COMMIT() asm volatile("cp.async.commit_group;" ::: "memory")
#define CP_WAIT0()  asm volatile("cp.async.wait_group 0;" ::: "memory")
#define CP_WAIT1()  asm volatile("cp.async.wait_group 1;" ::: "memory")

// ---------------- edge-index dtype probe ----------------
__global__ void k_detect(const int* __restrict__ ei32) {
    if (threadIdx.x == 0 && blockIdx.x == 0) {
        int odd_nonzero = 0;
        for (int i = 1; i < 256; i += 2) odd_nonzero += (ei32[i] != 0);
        g_is64 = (odd_nonzero == 0) ? 1 : 0;
    }
}
__device__ __forceinline__ int edge_at(const void* __restrict__ ei, size_t idx) {
    if (g_is64) return (int)((const long long*)ei)[idx];
    return ((const int*)ei)[idx];
}

// ---------------- CSR build ----------------
__global__ void k_init_deg() {
    int i = blockIdx.x * blockDim.x + threadIdx.x;
    if (i < NN) g_deg[i] = 1;
}
__global__ void k_count_edges(const void* __restrict__ ei) {
    int i = blockIdx.x * blockDim.x + threadIdx.x;
    if (i < EE) atomicAdd(&g_deg[edge_at(ei, (size_t)EE + i)], 1);
}

__global__ void k_scan_partial() {  // grid NSB, 256 thr
    __shared__ int sh[256];
    int b = blockIdx.x, t = threadIdx.x;
    int base = b * SCAN_BLK;
    int sum = 0;
    for (int i = t; i < SCAN_BLK; i += 256) {
        int g = base + i;
        if (g < NN) sum += g_deg[g];
    }
    sh[t] = sum; __syncthreads();
    for (int o = 128; o; o >>= 1) { if (t < o) sh[t] += sh[t + o]; __syncthreads(); }
    if (t == 0) g_bsum[b] = sh[0];
}
__global__ void k_scan_tops() {  // 1 block, 128 thr
    __shared__ int sh[128];
    int t = threadIdx.x;
    int v = (t < NSB) ? g_bsum[t] : 0;
    sh[t] = v; __syncthreads();
    for (int o = 1; o < 128; o <<= 1) {
        int u = (t >= o) ? sh[t - o] : 0; __syncthreads();
        sh[t] += u; __syncthreads();
    }
    if (t < NSB) g_bbase[t] = sh[t] - v;
    if (t == 127) g_off[NN] = sh[127];
}
__global__ void k_scan_final() {  // grid NSB, 1024 thr
    __shared__ int sh[SCAN_BLK];
    int b = blockIdx.x, t = threadIdx.x;
    int g = b * SCAN_BLK + t;
    int v = (g < NN) ? g_deg[g] : 0;
    sh[t] = v; __syncthreads();
    for (int o = 1; o < SCAN_BLK; o <<= 1) {
        int u = (t >= o) ? sh[t - o] : 0; __syncthreads();
        sh[t] += u; __syncthreads();
    }
    if (g < NN) g_off[g] = g_bbase[b] + sh[t] - v;
}

__global__ void k_scatter_self() {
    int i = blockIdx.x * blockDim.x + threadIdx.x;
    if (i < NN) { int o = g_off[i]; g_csr[o] = i; g_cur[i] = o + 1; }
}
__global__ void k_scatter_edges(const void* __restrict__ ei) {
    int i = blockIdx.x * blockDim.x + threadIdx.x;
    if (i < EE) {
        int d = edge_at(ei, (size_t)EE + i);
        int p = atomicAdd(&g_cur[d], 1);
        g_csr[p] = edge_at(ei, i);
    }
}

// ---------------- W^T hi/lo conversion (tiny, per layer) ----------------
__global__ void k_convB(const float* __restrict__ W, int K, int Ncol) {
    int idx = blockIdx.x * blockDim.x + threadIdx.x;   // n*K + k
    if (idx >= K * Ncol) return;
    int n = idx / K, k = idx % K;
    float w = W[k * Ncol + n];
    __nv_bfloat16 h = __float2bfloat16(w);
    __nv_bfloat16 l = __float2bfloat16(w - __bfloat162float(h));
    g_Bh[idx] = h; g_Bl[idx] = l;
}

// ---------------- cp.async-pipelined bf16 MMA GEMM, 2 CTAs/SM ----------------
// Dynamic smem layout (1024-aligned base), 97 KB total:
//   smF  [0,     32768)  : 128 x 64 fp32 raw A chunk, linear, row stride 256B
//   smAh [32768, 49152)  : 128 x 64 bf16 hi, SW128
//   smAl [49152, 65536)  : 128 x 64 bf16 lo, SW128
//   smB  [65536, 98304)  : Bh 16KB ; Bl 16KB, SW128
// Pipeline groups: [A(c)] drained at loop top; [B(c)] then [A(c+1)] committed,
// wait_group 1 => B(c) ready, A(c+1) still in flight during compute(c).
#define SM_BYTES (98304 + 1024)
template <int K, int NT>
__global__ __launch_bounds__(256, 2) void k_mgemm(const float* __restrict__ Aext) {
    extern __shared__ char dynsm[];
    char* smp = (char*)(((uintptr_t)dynsm + 1023) & ~(uintptr_t)1023);
    const uint32_t sF  = smem_u32(smp);
    const uint32_t sAh = sF + 32768;
    const uint32_t sAl = sF + 49152;
    const uint32_t sB  = sF + 65536;

    const float* __restrict__ A = Aext ? Aext : (const float*)g_agg;
    const int tid = threadIdx.x;
    const int wid = tid >> 5;
    const int lane = tid & 31;
    const int wm = wid >> 2;
    const int wn = wid & 3;
    const size_t rowBase = (size_t)blockIdx.x * 128;
    const int nBase = blockIdx.y * 128;

    float acc[4][4][4];
#pragma unroll
    for (int i = 0; i < 4; i++)
#pragma unroll
        for (int j = 0; j < 4; j++)
#pragma unroll
            for (int f = 0; f < 4; f++) acc[i][j][f] = 0.f;

    const int mat = lane >> 3;
    const int rr = lane & 7;
    constexpr int CH = K / 64;

    auto stageA = [&](int cc) {
        const int off = cc * 64;
#pragma unroll
        for (int u = tid; u < 2048; u += 256) {
            int r = u >> 4, q = u & 15;
            size_t gr = rowBase + r;
            uint32_t ok = (gr < NN) ? 16u : 0u;
            const float* src = A + (gr < NN ? gr : 0) * K + off + q * 4;
            cp16(sF + (uint32_t)(r * 256 + q * 16), src, ok);
        }
    };
    auto stageB = [&](int cc) {
        const int off = cc * 64;
#pragma unroll
        for (int u = tid; u < 1024; u += 256) {
            int r = u >> 3, uu = u & 7;
            uint32_t boff = SWZ128((uint32_t)(r * 128 + uu * 16));
            const size_t gsrc = (size_t)(nBase + r) * K + off + uu * 8;
            cp16(sB + boff,         g_Bh + gsrc, 16u);
            cp16(sB + 16384 + boff, g_Bl + gsrc, 16u);
        }
    };

    stageA(0); CP_COMMIT();

    for (int c = 0; c < CH; c++) {
        CP_WAIT0();            // raw A(c) landed (also orders vs prior compute)
        __syncthreads();

        // ---- convert raw fp32 -> bf16 hi/lo in smem ----
#pragma unroll
        for (int u = tid; u < 2048; u += 256) {
            int r = u >> 4, q = u & 15;
            float4 v = *(const float4*)(smp + r * 256 + q * 16);
            float a0[4] = {v.x, v.y, v.z, v.w};
            __nv_bfloat16 h[4], l[4];
#pragma unroll
            for (int j = 0; j < 4; j++) {
                h[j] = __float2bfloat16(a0[j]);
                l[j] = __float2bfloat16(a0[j] - __bfloat162float(h[j]));
            }
            uint32_t boff = SWZ128((uint32_t)(r * 128 + q * 8));
            *(uint2*)(smp + 32768 + boff) = *(uint2*)h;
            *(uint2*)(smp + 49152 + boff) = *(uint2*)l;
        }
        __syncthreads();       // smF free; conversions visible

        stageB(c); CP_COMMIT();
        if (c + 1 < CH) { stageA(c + 1); CP_COMMIT(); CP_WAIT1(); }  // B(c) done, A(c+1) in flight
        else            { CP_WAIT0(); }
        __syncthreads();

        // ---- compute: hh, hl (Ah frags reused), lh ----
#pragma unroll
        for (int kk = 0; kk < 4; kk++) {
            const int k0 = kk * 16;
            uint32_t bh[4][2], bl[4][2];
#pragma unroll
            for (int nb = 0; nb < 2; nb++) {
                int nrow = wn * 32 + nb * 16 + (mat >> 1) * 8 + rr;
                uint32_t boff = SWZ128((uint32_t)(nrow * 128 + (k0 + (mat & 1) * 8) * 2));
                uint32_t r0, r1, r2, r3;
                ldmat_x4(r0, r1, r2, r3, sB + boff);
                bh[nb * 2][0] = r0;     bh[nb * 2][1] = r1;
                bh[nb * 2 + 1][0] = r2; bh[nb * 2 + 1][1] = r3;
                ldmat_x4(r0, r1, r2, r3, sB + 16384 + boff);
                bl[nb * 2][0] = r0;     bl[nb * 2][1] = r1;
                bl[nb * 2 + 1][0] = r2; bl[nb * 2 + 1][1] = r3;
            }
            uint32_t a[4][4];
#pragma unroll
            for (int ms = 0; ms < 4; ms++) {
                int row = wm * 64 + ms * 16 + (mat & 1) * 8 + rr;
                uint32_t aoff = SWZ128((uint32_t)(row * 128 + (k0 + (mat >> 1) * 8) * 2));
                ldmat_x4(a[ms][0], a[ms][1], a[ms][2], a[ms][3], sAh + aoff);
            }
#pragma unroll
            for (int ms = 0; ms < 4; ms++)
#pragma unroll
                for (int ns = 0; ns < 4; ns++)
                    mma_bf16(acc[ms][ns], a[ms], bh[ns]);
#pragma unroll
            for (int ms = 0; ms < 4; ms++)
#pragma unroll
                for (int ns = 0; ns < 4; ns++)
                    mma_bf16(acc[ms][ns], a[ms], bl[ns]);
#pragma unroll
            for (int ms = 0; ms < 4; ms++) {
                int row = wm * 64 + ms * 16 + (mat & 1) * 8 + rr;
                uint32_t aoff = SWZ128((uint32_t)(row * 128 + (k0 + (mat >> 1) * 8) * 2));
                ldmat_x4(a[ms][0], a[ms][1], a[ms][2], a[ms][3], sAl + aoff);
            }
#pragma unroll
            for (int ms = 0; ms < 4; ms++)
#pragma unroll
                for (int ns = 0; ns < 4; ns++)
                    mma_bf16(acc[ms][ns], a[ms], bh[ns]);
        }
        // no trailing sync: loop-top CP_WAIT0 + __syncthreads protects buffers
    }

    // ---- epilogue (c-frag mapping verified in R8/R10/R11) ----
    const int cr = lane >> 2;
    const int cc2 = (lane & 3) * 2;
#pragma unroll
    for (int ms = 0; ms < 4; ms++) {
#pragma unroll
        for (int ns = 0; ns < 4; ns++) {
            size_t row0 = rowBase + wm * 64 + ms * 16 + cr;
            int col = nBase + wn * 32 + ns * 8 + cc2;
            if (row0 < NN) {
                *(float2*)(g_h + row0 * NT + col) =
                    make_float2(acc[ms][ns][0], acc[ms][ns][1]);
            }
            size_t row1 = row0 + 8;
            if (row1 < NN) {
                *(float2*)(g_h + row1 * NT + col) =
                    make_float2(acc[ms][ns][2], acc[ms][ns][3]);
            }
        }
    }
}

// ---------------- per-node attention scores ----------------
template <int CT, int H>
__global__ __launch_bounds__(256) void k_scores(const float* __restrict__ a_s,
                                                const float* __restrict__ a_d) {
    int wid = (blockIdx.x * blockDim.x + threadIdx.x) >> 5;
    int lane = threadIdx.x & 31;
    if (wid >= NN) return;
    const float* hp = g_h + (size_t)wid * CT;

    int cA = lane * 4;
    float4 hv = *(const float4*)(hp + cA);
    float4 sv = *(const float4*)(a_s + cA);
    float4 dv = *(const float4*)(a_d + cA);
    float psA = hv.x * sv.x + hv.y * sv.y + hv.z * sv.z + hv.w * sv.w;
    float pdA = hv.x * dv.x + hv.y * dv.y + hv.z * dv.z + hv.w * dv.w;

    if (CT == 256) {
        int cB = 128 + lane * 4;
        float4 hv2 = *(const float4*)(hp + cB);
        float4 sv2 = *(const float4*)(a_s + cB);
        float4 dv2 = *(const float4*)(a_d + cB);
        float psB = hv2.x * sv2.x + hv2.y * sv2.y + hv2.z * sv2.z + hv2.w * sv2.w;
        float pdB = hv2.x * dv2.x + hv2.y * dv2.y + hv2.z * dv2.z + hv2.w * dv2.w;
#pragma unroll
        for (int o = 8; o; o >>= 1) {
            psA += __shfl_xor_sync(0xffffffffu, psA, o);
            pdA += __shfl_xor_sync(0xffffffffu, pdA, o);
            psB += __shfl_xor_sync(0xffffffffu, psB, o);
            pdB += __shfl_xor_sync(0xffffffffu, pdB, o);
        }
        if (lane == 0)  { g_als[wid * 4 + 0] = psA; g_ald[wid * 4 + 0] = pdA;
                          g_als[wid * 4 + 2] = psB; g_ald[wid * 4 + 2] = pdB; }
        if (lane == 16) { g_als[wid * 4 + 1] = psA; g_ald[wid * 4 + 1] = pdA;
                          g_als[wid * 4 + 3] = psB; g_ald[wid * 4 + 3] = pdB; }
    } else {
#pragma unroll
        for (int o = 16; o; o >>= 1) {
            psA += __shfl_xor_sync(0xffffffffu, psA, o);
            pdA += __shfl_xor_sync(0xffffffffu, pdA, o);
        }
        if (lane == 0) { g_als[wid] = psA; g_ald[wid] = pdA; }
    }
}

__device__ __forceinline__ float lrelu(float x) { return x > 0.f ? x : SLOPE * x; }
__device__ __forceinline__ float elu(float x)   { return x > 0.f ? x : expm1f(x); }

// ---------------- warp-per-dst-node softmax + aggregation ----------------
template <int CT, int H, bool DO_ELU, bool EXT_OUT>
__global__ __launch_bounds__(256) void k_agg(const float* __restrict__ bias,
                                             float* __restrict__ extOut) {
    int n = (blockIdx.x * blockDim.x + threadIdx.x) >> 5;
    int lane = threadIdx.x & 31;
    if (n >= NN) return;
    float* __restrict__ out = EXT_OUT ? extOut : (float*)g_agg;
    const int beg = g_off[n], end = g_off[n + 1];
    const float* __restrict__ h = g_h;
    const float* __restrict__ als = g_als;
    const float* __restrict__ ald = g_ald;

    if (H == 4) {
        float4 ad = *(const float4*)(ald + (size_t)n * 4);
        float4 m = make_float4(-INFINITY, -INFINITY, -INFINITY, -INFINITY);
        for (int i = beg + lane; i < end; i += 32) {
            int s = g_csr[i];
            float4 as = *(const float4*)(als + (size_t)s * 4);
            m.x = fmaxf(m.x, lrelu(as.x + ad.x));
            m.y = fmaxf(m.y, lrelu(as.y + ad.y));
            m.z = fmaxf(m.z, lrelu(as.z + ad.z));
            m.w = fmaxf(m.w, lrelu(as.w + ad.w));
        }
#pragma unroll
        for (int o = 16; o; o >>= 1) {
            m.x = fmaxf(m.x, __shfl_xor_sync(0xffffffffu, m.x, o));
            m.y = fmaxf(m.y, __shfl_xor_sync(0xffffffffu, m.y, o));
            m.z = fmaxf(m.z, __shfl_xor_sync(0xffffffffu, m.z, o));
            m.w = fmaxf(m.w, __shfl_xor_sync(0xffffffffu, m.w, o));
        }
        float4 den = make_float4(0.f, 0.f, 0.f, 0.f);
        for (int i = beg + lane; i < end; i += 32) {
            int s = g_csr[i];
            float4 as = *(const float4*)(als + (size_t)s * 4);
            den.x += __expf(lrelu(as.x + ad.x) - m.x);
            den.y += __expf(lrelu(as.y + ad.y) - m.y);
            den.z += __expf(lrelu(as.z + ad.z) - m.z);
            den.w += __expf(lrelu(as.w + ad.w) - m.w);
        }
#pragma unroll
        for (int o = 16; o; o >>= 1) {
            den.x += __shfl_xor_sync(0xffffffffu, den.x, o);
            den.y += __shfl_xor_sync(0xffffffffu, den.y, o);
            den.z += __shfl_xor_sync(0xffffffffu, den.z, o);
            den.w += __shfl_xor_sync(0xffffffffu, den.w, o);
        }
        float4 inv = make_float4(1.f / (den.x + 1e-16f), 1.f / (den.y + 1e-16f),
                                 1.f / (den.z + 1e-16f), 1.f / (den.w + 1e-16f));
        const int hA = lane >> 4;
        const float adA = hA ? ad.y : ad.x;
        const float adB = hA ? ad.w : ad.z;
        const float mA  = hA ? m.y  : m.x;
        const float mB  = hA ? m.w  : m.z;
        const float ivA = hA ? inv.y : inv.x;
        const float ivB = hA ? inv.w : inv.z;
        const int cA = lane * 4;
        const int cB = 128 + lane * 4;
        float acc[8] = {0.f, 0.f, 0.f, 0.f, 0.f, 0.f, 0.f, 0.f};
        for (int i = beg; i < end; i++) {
            int s = g_csr[i];
            float4 as = *(const float4*)(als + (size_t)s * 4);
            float asA = hA ? as.y : as.x;
            float asB = hA ? as.w : as.z;
            float alA = __expf(lrelu(asA + adA) - mA) * ivA;
            float alB = __expf(lrelu(asB + adB) - mB) * ivB;
            const float* hp = h + (size_t)s * 256;
            float4 v0 = *(const float4*)(hp + cA);
            float4 v1 = *(const float4*)(hp + cB);
            acc[0] = fmaf(alA, v0.x, acc[0]); acc[1] = fmaf(alA, v0.y, acc[1]);
            acc[2] = fmaf(alA, v0.z, acc[2]); acc[3] = fmaf(alA, v0.w, acc[3]);
            acc[4] = fmaf(alB, v1.x, acc[4]); acc[5] = fmaf(alB, v1.y, acc[5]);
            acc[6] = fmaf(alB, v1.z, acc[6]); acc[7] = fmaf(alB, v1.w, acc[7]);
        }
        float4 b0 = *(const float4*)(bias + cA);
        float4 b1 = *(const float4*)(bias + cB);
        float4 o0, o1;
        o0.x = acc[0] + b0.x; o0.y = acc[1] + b0.y; o0.z = acc[2] + b0.z; o0.w = acc[3] + b0.w;
        o1.x = acc[4] + b1.x; o1.y = acc[5] + b1.y; o1.z = acc[6] + b1.z; o1.w = acc[7] + b1.w;
        if (DO_ELU) {
            o0.x = elu(o0.x); o0.y = elu(o0.y); o0.z = elu(o0.z); o0.w = elu(o0.w);
            o1.x = elu(o1.x); o1.y = elu(o1.y); o1.z = elu(o1.z); o1.w = elu(o1.w);
        }
        float* op = out + (size_t)n * 256;
        *(float4*)(op + cA) = o0;
        *(float4*)(op + cB) = o1;
    } else {
        float adn = ald[n];
        float m = -INFINITY;
        for (int i = beg + lane; i < end; i += 32) {
            int s = g_csr[i];
            m = fmaxf(m, lrelu(als[s] + adn));
        }
#pragma unroll
        for (int o = 16; o; o >>= 1) m = fmaxf(m, __shfl_xor_sync(0xffffffffu, m, o));
        float den = 0.f;
        for (int i = beg + lane; i < end; i += 32) {
            int s = g_csr[i];
            den += __expf(lrelu(als[s] + adn) - m);
        }
#pragma unroll
        for (int o = 16; o; o >>= 1) den += __shfl_xor_sync(0xffffffffu, den, o);
        float iv = 1.f / (den + 1e-16f);
        const int cA = lane * 4;
        float acc[4] = {0.f, 0.f, 0.f, 0.f};
        for (int i = beg; i < end; i++) {
            int s = g_csr[i];
            float al = __expf(lrelu(als[s] + adn) - m) * iv;
            float4 v = *(const float4*)(h + (size_t)s * 128 + cA);
            acc[0] = fmaf(al, v.x, acc[0]); acc[1] = fmaf(al, v.y, acc[1]);
            acc[2] = fmaf(al, v.z, acc[2]); acc[3] = fmaf(al, v.w, acc[3]);
        }
        float4 bv = *(const float4*)(bias + cA);
        float4 o0;
        o0.x = acc[0] + bv.x; o0.y = acc[1] + bv.y;
        o0.z = acc[2] + bv.z; o0.w = acc[3] + bv.w;
        *(float4*)(out + (size_t)n * 128 + cA) = o0;
    }
}

// ---------------- launch ----------------
extern "C" void kernel_launch(void* const* d_in, const int* in_sizes, int n_in,
                              void* d_out, int out_size) {
    const float* x   = (const float*)d_in[0];
    const void*  ei  = d_in[1];
    const float* W0  = (const float*)d_in[2];
    const float* as0 = (const float*)d_in[3];
    const float* ad0 = (const float*)d_in[4];
    const float* b0  = (const float*)d_in[5];
    const float* W1  = (const float*)d_in[6];
    const float* as1 = (const float*)d_in[7];
    const float* ad1 = (const float*)d_in[8];
    const float* b1  = (const float*)d_in[9];
    const float* W2  = (const float*)d_in[10];
    const float* as2 = (const float*)d_in[11];
    const float* ad2 = (const float*)d_in[12];
    const float* b2  = (const float*)d_in[13];
    float* out = (float*)d_out;

    const int TB = 256;
    const int gN = (NN + TB - 1) / TB;
    const int gE = (EE + TB - 1) / TB;
    const int gW = (NN + 7) / 8;
    const int GEMM_GRID = MPAD / 128;  // 782
    dim3 grid2(GEMM_GRID, 2);
    dim3 grid1(GEMM_GRID, 1);

    // opt-in dynamic smem (idempotent; function attribute, not a stream op)
    cudaFuncSetAttribute(k_mgemm<128, 256>, cudaFuncAttributeMaxDynamicSharedMemorySize, SM_BYTES);
    cudaFuncSetAttribute(k_mgemm<256, 256>, cudaFuncAttributeMaxDynamicSharedMemorySize, SM_BYTES);
    cudaFuncSetAttribute(k_mgemm<256, 128>, cudaFuncAttributeMaxDynamicSharedMemorySize, SM_BYTES);

    // Order keeps mgemm L0 at launch index 3 (ncu's profile slot).
    k_detect<<<1, 32>>>((const int*)ei);                              // 0
    k_convB<<<(F0 * HID + TB - 1) / TB, TB>>>(W0, F0, HID);           // 1
    k_init_deg<<<gN, TB>>>();                                         // 2
    k_mgemm<128, 256><<<grid2, 256, SM_BYTES>>>(x);                   // 3  <- profiled
    k_count_edges<<<gE, TB>>>(ei);                                    // 4
    k_scan_partial<<<NSB, 256>>>();                                   // 5
    k_scan_tops<<<1, 128>>>();                                        // 6
    k_scan_final<<<NSB, SCAN_BLK>>>();                                // 7
    k_scatter_self<<<gN, TB>>>();                                     // 8
    k_scatter_edges<<<gE, TB>>>(ei);                                  // 9
    k_scores<256, 4><<<gW, TB>>>(as0, ad0);                           // 10
    k_agg<256, 4, true, false><<<gW, TB>>>(b0, nullptr);              // 11

    // ---- layer 1: g_agg[N,256] @ W1[256,256] ----
    k_convB<<<(HID * HID + TB - 1) / TB, TB>>>(W1, HID, HID);
    k_mgemm<256, 256><<<grid2, 256, SM_BYTES>>>(nullptr);
    k_scores<256, 4><<<gW, TB>>>(as1, ad1);
    k_agg<256, 4, true, false><<<gW, TB>>>(b1, nullptr);

    // ---- layer 2: g_agg[N,256] @ W2[256,128], 1 head, no ELU ----
    k_convB<<<(HID * OUTC + TB - 1) / TB, TB>>>(W2, HID, OUTC);
    k_mgemm<256, 128><<<grid1, 256, SM_BYTES>>>(nullptr);
    k_scores<128, 1><<<gW, TB>>>(as2, ad2);
    k_agg<128, 1, false, true><<<gW, TB>>>(b2, out);
}

// round 13
// speedup vs baseline: 2.4088x; 1.2408x over previous
#include <cuda_runtime.h>
#include <cuda_fp16.h>
#include <cstdint>
#include <math.h>

// ---------------- problem constants (fixed shapes) ----------------
#define NN 100000      // nodes
#define EE 400000      // edges (without self loops)
#define ET (EE + NN)   // total edges incl self loops
#define F0 128         // input features
#define HID 256        // hidden (4 heads x 64)
#define OUTC 128       // output features
#define SLOPE 0.2f
#define MPAD 100096    // 782 * 128 (row-padded M for the GEMM)

// ---------------- device scratch (no allocations allowed) ----------------
__device__ __align__(16) float g_h[(size_t)NN * HID];
__device__ __align__(16) __half g_Af[(size_t)NN * HID];   // fp16 A for layers 1,2
__device__ __align__(16) float g_als[(size_t)NN * 4];
__device__ __align__(16) float g_ald[(size_t)NN * 4];
__device__ int   g_deg[NN];
__device__ int   g_off[NN + 1];
__device__ int   g_cur[NN];
__device__ int   g_csr[ET];
__device__ int   g_is64;

// fp16 split W^T (small, per layer)
__device__ __align__(16) __half g_Bh[256 * 256];   // W^T hi  [N, K]
__device__ __align__(16) __half g_Bl[256 * 256];   // W^T lo  [N, K]

// scan temporaries
#define SCAN_BLK 1024
#define NSB ((NN + SCAN_BLK - 1) / SCAN_BLK)   // 98
__device__ int g_bsum[NSB];
__device__ int g_bbase[NSB];

// ---------------- helpers ----------------
__device__ __forceinline__ uint32_t smem_u32(const void* p) {
    uint32_t a;
    asm("{ .reg .u64 t; cvta.to.shared.u64 t, %1; cvt.u32.u64 %0, t; }" : "=r"(a) : "l"(p));
    return a;
}
#define SWZ128(off) ((off) ^ (((off) >> 3) & 0x70))

__device__ __forceinline__ void ldmat_x4(uint32_t& r0, uint32_t& r1, uint32_t& r2,
                                         uint32_t& r3, uint32_t addr) {
    asm volatile("ldmatrix.sync.aligned.m8n8.x4.shared.b16 {%0,%1,%2,%3}, [%4];"
        : "=r"(r0), "=r"(r1), "=r"(r2), "=r"(r3) : "r"(addr));
}
__device__ __forceinline__ void mma_fp16(float* d, const uint32_t* a, const uint32_t* b) {
    asm volatile("mma.sync.aligned.m16n8k16.row.col.f32.f16.f16.f32 "
        "{%0,%1,%2,%3}, {%4,%5,%6,%7}, {%8,%9}, {%0,%1,%2,%3};"
        : "+f"(d[0]), "+f"(d[1]), "+f"(d[2]), "+f"(d[3])
        : "r"(a[0]), "r"(a[1]), "r"(a[2]), "r"(a[3]), "r"(b[0]), "r"(b[1]));
}
__device__ __forceinline__ void cp16(uint32_t dst, const void* src, uint32_t src_bytes) {
    asm volatile("cp.async.cg.shared.global [%0], [%1], 16, %2;"
        :: "r"(dst), "l"(src), "r"(src_bytes));
}
#define CP_COMMIT() asm volatile("cp.async.commit_group;" ::: "memory")
#define CP_WAIT0()  asm volatile("cp.async.wait_group 0;" ::: "memory")
#define CP_WAIT1()  asm volatile("cp.async.wait_group 1;" ::: "memory")

// ---------------- edge-index dtype probe ----------------
__global__ void k_detect(const int* __restrict__ ei32) {
    if (threadIdx.x == 0 && blockIdx.x == 0) {
        int odd_nonzero = 0;
        for (int i = 1; i < 256; i += 2) odd_nonzero += (ei32[i] != 0);
        g_is64 = (odd_nonzero == 0) ? 1 : 0;
    }
}
__device__ __forceinline__ int edge_at(const void* __restrict__ ei, size_t idx) {
    if (g_is64) return (int)((const long long*)ei)[idx];
    return ((const int*)ei)[idx];
}

// ---------------- CSR build ----------------
__global__ void k_init_deg() {
    int i = blockIdx.x * blockDim.x + threadIdx.x;
    if (i < NN) g_deg[i] = 1;
}
__global__ void k_count_edges(const void* __restrict__ ei) {
    int i = blockIdx.x * blockDim.x + threadIdx.x;
    if (i < EE) atomicAdd(&g_deg[edge_at(ei, (size_t)EE + i)], 1);
}

__global__ void k_scan_partial() {  // grid NSB, 256 thr
    __shared__ int sh[256];
    int b = blockIdx.x, t = threadIdx.x;
    int base = b * SCAN_BLK;
    int sum = 0;
    for (int i = t; i < SCAN_BLK; i += 256) {
        int g = base + i;
        if (g < NN) sum += g_deg[g];
    }
    sh[t] = sum; __syncthreads();
    for (int o = 128; o; o >>= 1) { if (t < o) sh[t] += sh[t + o]; __syncthreads(); }
    if (t == 0) g_bsum[b] = sh[0];
}
__global__ void k_scan_tops() {  // 1 block, 128 thr
    __shared__ int sh[128];
    int t = threadIdx.x;
    int v = (t < NSB) ? g_bsum[t] : 0;
    sh[t] = v; __syncthreads();
    for (int o = 1; o < 128; o <<= 1) {
        int u = (t >= o) ? sh[t - o] : 0; __syncthreads();
        sh[t] += u; __syncthreads();
    }
    if (t < NSB) g_bbase[t] = sh[t] - v;
    if (t == 127) g_off[NN] = sh[127];
}
__global__ void k_scan_final() {  // grid NSB, 1024 thr
    __shared__ int sh[SCAN_BLK];
    int b = blockIdx.x, t = threadIdx.x;
    int g = b * SCAN_BLK + t;
    int v = (g < NN) ? g_deg[g] : 0;
    sh[t] = v; __syncthreads();
    for (int o = 1; o < SCAN_BLK; o <<= 1) {
        int u = (t >= o) ? sh[t - o] : 0; __syncthreads();
        sh[t] += u; __syncthreads();
    }
    if (g < NN) g_off[g] = g_bbase[b] + sh[t] - v;
}

__global__ void k_scatter_self() {
    int i = blockIdx.x * blockDim.x + threadIdx.x;
    if (i < NN) { int o = g_off[i]; g_csr[o] = i; g_cur[i] = o + 1; }
}
__global__ void k_scatter_edges(const void* __restrict__ ei) {
    int i = blockIdx.x * blockDim.x + threadIdx.x;
    if (i < EE) {
        int d = edge_at(ei, (size_t)EE + i);
        int p = atomicAdd(&g_cur[d], 1);
        g_csr[p] = edge_at(ei, i);
    }
}

// ---------------- W^T hi/lo fp16 conversion (tiny, per layer) ----------------
__global__ void k_convB(const float* __restrict__ W, int K, int Ncol) {
    int idx = blockIdx.x * blockDim.x + threadIdx.x;   // n*K + k
    if (idx >= K * Ncol) return;
    int n = idx / K, k = idx % K;
    float w = W[k * Ncol + n];
    __half h = __float2half(w);
    __half l = __float2half(w - __half2float(h));
    g_Bh[idx] = h; g_Bl[idx] = l;
}

// ================= GEMM compute core (fp16, 2-pass B-split) =================
// Per k16: A frags loaded once, used against Bh and Bl.
#define GEMM_COMPUTE(sAbase, sBbase)                                                   \
    _Pragma("unroll")                                                                   \
    for (int kk = 0; kk < 4; kk++) {                                                    \
        const int k0 = kk * 16;                                                         \
        uint32_t bh[4][2], bl[4][2];                                                    \
        _Pragma("unroll")                                                               \
        for (int nb = 0; nb < 2; nb++) {                                                \
            int nrow = wn * 32 + nb * 16 + (mat >> 1) * 8 + rr;                         \
            uint32_t boff = SWZ128((uint32_t)(nrow * 128 + (k0 + (mat & 1) * 8) * 2));  \
            uint32_t r0, r1, r2, r3;                                                    \
            ldmat_x4(r0, r1, r2, r3, (sBbase) + boff);                                  \
            bh[nb * 2][0] = r0;     bh[nb * 2][1] = r1;                                 \
            bh[nb * 2 + 1][0] = r2; bh[nb * 2 + 1][1] = r3;                             \
            ldmat_x4(r0, r1, r2, r3, (sBbase) + 16384 + boff);                          \
            bl[nb * 2][0] = r0;     bl[nb * 2][1] = r1;                                 \
            bl[nb * 2 + 1][0] = r2; bl[nb * 2 + 1][1] = r3;                             \
        }                                                                               \
        uint32_t a[4][4];                                                               \
        _Pragma("unroll")                                                               \
        for (int ms = 0; ms < 4; ms++) {                                                \
            int row = wm * 64 + ms * 16 + (mat & 1) * 8 + rr;                           \
            uint32_t aoff = SWZ128((uint32_t)(row * 128 + (k0 + (mat >> 1) * 8) * 2));  \
            ldmat_x4(a[ms][0], a[ms][1], a[ms][2], a[ms][3], (sAbase) + aoff);          \
        }                                                                               \
        _Pragma("unroll")                                                               \
        for (int ms = 0; ms < 4; ms++)                                                  \
            _Pragma("unroll")                                                           \
            for (int ns = 0; ns < 4; ns++)                                              \
                mma_fp16(acc[ms][ns], a[ms], bh[ns]);                                   \
        _Pragma("unroll")                                                               \
        for (int ms = 0; ms < 4; ms++)                                                  \
            _Pragma("unroll")                                                           \
            for (int ns = 0; ns < 4; ns++)                                              \
                mma_fp16(acc[ms][ns], a[ms], bl[ns]);                                   \
    }

#define GEMM_EPILOGUE(NT)                                                               \
    const int cr = lane >> 2;                                                           \
    const int cc2 = (lane & 3) * 2;                                                     \
    _Pragma("unroll")                                                                   \
    for (int ms = 0; ms < 4; ms++) {                                                    \
        _Pragma("unroll")                                                               \
        for (int ns = 0; ns < 4; ns++) {                                                \
            size_t row0 = rowBase + wm * 64 + ms * 16 + cr;                             \
            int col = nBase + wn * 32 + ns * 8 + cc2;                                   \
            if (row0 < NN)                                                              \
                *(float2*)(g_h + row0 * (NT) + col) =                                   \
                    make_float2(acc[ms][ns][0], acc[ms][ns][1]);                        \
            size_t row1 = row0 + 8;                                                     \
            if (row1 < NN)                                                              \
                *(float2*)(g_h + row1 * (NT) + col) =                                   \
                    make_float2(acc[ms][ns][2], acc[ms][ns][3]);                        \
        }                                                                               \
    }

// ---------------- L0 GEMM: fp32 x -> fused fp16 convert ----------------
// smem: smF raw fp32 32KB @0 ; smA fp16 16KB @32768 ; smB (Bh,Bl) 32KB @49152.
#define SM16_BYTES (81920 + 1024)
template <int K, int NT>
__global__ __launch_bounds__(256, 2) void k_mgemm16(const float* __restrict__ A) {
    extern __shared__ char dynsm[];
    char* smp = (char*)(((uintptr_t)dynsm + 1023) & ~(uintptr_t)1023);
    const uint32_t sF = smem_u32(smp);
    const uint32_t sA = sF + 32768;
    const uint32_t sB = sF + 49152;

    const int tid = threadIdx.x;
    const int wid = tid >> 5;
    const int lane = tid & 31;
    const int wm = wid >> 2;
    const int wn = wid & 3;
    const size_t rowBase = (size_t)blockIdx.x * 128;
    const int nBase = blockIdx.y * 128;

    float acc[4][4][4];
#pragma unroll
    for (int i = 0; i < 4; i++)
#pragma unroll
        for (int j = 0; j < 4; j++)
#pragma unroll
            for (int f = 0; f < 4; f++) acc[i][j][f] = 0.f;

    const int mat = lane >> 3;
    const int rr = lane & 7;
    constexpr int CH = K / 64;

    auto stageA = [&](int cc) {
        const int off = cc * 64;
#pragma unroll
        for (int u = tid; u < 2048; u += 256) {
            int r = u >> 4, q = u & 15;
            size_t gr = rowBase + r;
            uint32_t ok = (gr < NN) ? 16u : 0u;
            const float* src = A + (gr < NN ? gr : 0) * K + off + q * 4;
            cp16(sF + (uint32_t)(r * 256 + q * 16), src, ok);
        }
    };
    auto stageB = [&](int cc) {
        const int off = cc * 64;
#pragma unroll
        for (int u = tid; u < 1024; u += 256) {
            int r = u >> 3, uu = u & 7;
            uint32_t boff = SWZ128((uint32_t)(r * 128 + uu * 16));
            const size_t gsrc = (size_t)(nBase + r) * K + off + uu * 8;
            cp16(sB + boff,         g_Bh + gsrc, 16u);
            cp16(sB + 16384 + boff, g_Bl + gsrc, 16u);
        }
    };

    stageA(0); CP_COMMIT();

    for (int c = 0; c < CH; c++) {
        CP_WAIT0();
        __syncthreads();
        // convert raw fp32 -> fp16 (hi only)
#pragma unroll
        for (int u = tid; u < 2048; u += 256) {
            int r = u >> 4, q = u & 15;
            float4 v = *(const float4*)(smp + r * 256 + q * 16);
            __half h[4];
            h[0] = __float2half(v.x); h[1] = __float2half(v.y);
            h[2] = __float2half(v.z); h[3] = __float2half(v.w);
            uint32_t boff = SWZ128((uint32_t)(r * 128 + q * 8));
            *(uint2*)(smp + 32768 + boff) = *(uint2*)h;
        }
        __syncthreads();
        stageB(c); CP_COMMIT();
        if (c + 1 < CH) { stageA(c + 1); CP_COMMIT(); CP_WAIT1(); }
        else            { CP_WAIT0(); }
        __syncthreads();
        GEMM_COMPUTE(sA, sB)
        // next loop-top wait+sync protects buffers
    }
    GEMM_EPILOGUE(NT)
}

// ---------------- L1/L2 GEMM: fp16 A direct, double-buffered A ----------------
// smem: smA[2] 2x16KB @0 ; smB (Bh,Bl) 32KB @32768. Total 64KB.
#define SMB_BYTES (65536 + 1024)
template <int K, int NT>
__global__ __launch_bounds__(256, 2) void k_bgemm() {
    extern __shared__ char dynsm[];
    char* smp = (char*)(((uintptr_t)dynsm + 1023) & ~(uintptr_t)1023);
    const uint32_t sA0 = smem_u32(smp);
    const uint32_t sB  = sA0 + 32768;

    const int tid = threadIdx.x;
    const int wid = tid >> 5;
    const int lane = tid & 31;
    const int wm = wid >> 2;
    const int wn = wid & 3;
    const size_t rowBase = (size_t)blockIdx.x * 128;
    const int nBase = blockIdx.y * 128;

    float acc[4][4][4];
#pragma unroll
    for (int i = 0; i < 4; i++)
#pragma unroll
        for (int j = 0; j < 4; j++)
#pragma unroll
            for (int f = 0; f < 4; f++) acc[i][j][f] = 0.f;

    const int mat = lane >> 3;
    const int rr = lane & 7;
    constexpr int CH = K / 64;

    auto stageA = [&](int cc) {
        const int buf = cc & 1;
        const int off = cc * 64;
#pragma unroll
        for (int u = tid; u < 1024; u += 256) {
            int r = u >> 3, uu = u & 7;
            size_t gr = rowBase + r;
            uint32_t ok = (gr < NN) ? 16u : 0u;
            const __half* src = g_Af + (gr < NN ? gr : 0) * K + off + uu * 8;
            cp16(sA0 + buf * 16384 + SWZ128((uint32_t)(r * 128 + uu * 16)), src, ok);
        }
    };
    auto stageB = [&](int cc) {
        const int off = cc * 64;
#pragma unroll
        for (int u = tid; u < 1024; u += 256) {
            int r = u >> 3, uu = u & 7;
            uint32_t boff = SWZ128((uint32_t)(r * 128 + uu * 16));
            const size_t gsrc = (size_t)(nBase + r) * K + off + uu * 8;
            cp16(sB + boff,         g_Bh + gsrc, 16u);
            cp16(sB + 16384 + boff, g_Bl + gsrc, 16u);
        }
    };

    stageA(0); CP_COMMIT();

    for (int c = 0; c < CH; c++) {
        stageB(c); CP_COMMIT();
        if (c + 1 < CH) { stageA(c + 1); CP_COMMIT(); CP_WAIT1(); }  // A(c),B(c) done; A(c+1) flying
        else            { CP_WAIT0(); }
        __syncthreads();
        const uint32_t sA = sA0 + (c & 1) * 16384;
        GEMM_COMPUTE(sA, sB)
        __syncthreads();   // protect sB (and alt A buf) before next stage
    }
    GEMM_EPILOGUE(NT)
}

// ---------------- per-node attention scores ----------------
template <int CT, int H>
__global__ __launch_bounds__(256) void k_scores(const float* __restrict__ a_s,
                                                const float* __restrict__ a_d) {
    int wid = (blockIdx.x * blockDim.x + threadIdx.x) >> 5;
    int lane = threadIdx.x & 31;
    if (wid >= NN) return;
    const float* hp = g_h + (size_t)wid * CT;

    int cA = lane * 4;
    float4 hv = *(const float4*)(hp + cA);
    float4 sv = *(const float4*)(a_s + cA);
    float4 dv = *(const float4*)(a_d + cA);
    float psA = hv.x * sv.x + hv.y * sv.y + hv.z * sv.z + hv.w * sv.w;
    float pdA = hv.x * dv.x + hv.y * dv.y + hv.z * dv.z + hv.w * dv.w;

    if (CT == 256) {
        int cB = 128 + lane * 4;
        float4 hv2 = *(const float4*)(hp + cB);
        float4 sv2 = *(const float4*)(a_s + cB);
        float4 dv2 = *(const float4*)(a_d + cB);
        float psB = hv2.x * sv2.x + hv2.y * sv2.y + hv2.z * sv2.z + hv2.w * sv2.w;
        float pdB = hv2.x * dv2.x + hv2.y * dv2.y + hv2.z * dv2.z + hv2.w * dv2.w;
#pragma unroll
        for (int o = 8; o; o >>= 1) {
            psA += __shfl_xor_sync(0xffffffffu, psA, o);
            pdA += __shfl_xor_sync(0xffffffffu, pdA, o);
            psB += __shfl_xor_sync(0xffffffffu, psB, o);
            pdB += __shfl_xor_sync(0xffffffffu, pdB, o);
        }
        if (lane == 0)  { g_als[wid * 4 + 0] = psA; g_ald[wid * 4 + 0] = pdA;
                          g_als[wid * 4 + 2] = psB; g_ald[wid * 4 + 2] = pdB; }
        if (lane == 16) { g_als[wid * 4 + 1] = psA; g_ald[wid * 4 + 1] = pdA;
                          g_als[wid * 4 + 3] = psB; g_ald[wid * 4 + 3] = pdB; }
    } else {
#pragma unroll
        for (int o = 16; o; o >>= 1) {
            psA += __shfl_xor_sync(0xffffffffu, psA, o);
            pdA += __shfl_xor_sync(0xffffffffu, pdA, o);
        }
        if (lane == 0) { g_als[wid] = psA; g_ald[wid] = pdA; }
    }
}

__device__ __forceinline__ float lrelu(float x) { return x > 0.f ? x : SLOPE * x; }
__device__ __forceinline__ float elu(float x)   { return x > 0.f ? x : expm1f(x); }

// ---------------- warp-per-dst-node softmax + aggregation ----------------
// EXT_OUT: write fp32 to extOut (final layer). Else: write fp16 to g_Af.
template <int CT, int H, bool DO_ELU, bool EXT_OUT>
__global__ __launch_bounds__(256) void k_agg(const float* __restrict__ bias,
                                             float* __restrict__ extOut) {
    int n = (blockIdx.x * blockDim.x + threadIdx.x) >> 5;
    int lane = threadIdx.x & 31;
    if (n >= NN) return;
    const int beg = g_off[n], end = g_off[n + 1];
    const float* __restrict__ h = g_h;
    const float* __restrict__ als = g_als;
    const float* __restrict__ ald = g_ald;

    if (H == 4) {
        float4 ad = *(const float4*)(ald + (size_t)n * 4);
        float4 m = make_float4(-INFINITY, -INFINITY, -INFINITY, -INFINITY);
        for (int i = beg + lane; i < end; i += 32) {
            int s = g_csr[i];
            float4 as = *(const float4*)(als + (size_t)s * 4);
            m.x = fmaxf(m.x, lrelu(as.x + ad.x));
            m.y = fmaxf(m.y, lrelu(as.y + ad.y));
            m.z = fmaxf(m.z, lrelu(as.z + ad.z));
            m.w = fmaxf(m.w, lrelu(as.w + ad.w));
        }
#pragma unroll
        for (int o = 16; o; o >>= 1) {
            m.x = fmaxf(m.x, __shfl_xor_sync(0xffffffffu, m.x, o));
            m.y = fmaxf(m.y, __shfl_xor_sync(0xffffffffu, m.y, o));
            m.z = fmaxf(m.z, __shfl_xor_sync(0xffffffffu, m.z, o));
            m.w = fmaxf(m.w, __shfl_xor_sync(0xffffffffu, m.w, o));
        }
        float4 den = make_float4(0.f, 0.f, 0.f, 0.f);
        for (int i = beg + lane; i < end; i += 32) {
            int s = g_csr[i];
            float4 as = *(const float4*)(als + (size_t)s * 4);
            den.x += __expf(lrelu(as.x + ad.x) - m.x);
            den.y += __expf(lrelu(as.y + ad.y) - m.y);
            den.z += __expf(lrelu(as.z + ad.z) - m.z);
            den.w += __expf(lrelu(as.w + ad.w) - m.w);
        }
#pragma unroll
        for (int o = 16; o; o >>= 1) {
            den.x += __shfl_xor_sync(0xffffffffu, den.x, o);
            den.y += __shfl_xor_sync(0xffffffffu, den.y, o);
            den.z += __shfl_xor_sync(0xffffffffu, den.z, o);
            den.w += __shfl_xor_sync(0xffffffffu, den.w, o);
        }
        float4 inv = make_float4(1.f / (den.x + 1e-16f), 1.f / (den.y + 1e-16f),
                                 1.f / (den.z + 1e-16f), 1.f / (den.w + 1e-16f));
        const int hA = lane >> 4;
        const float adA = hA ? ad.y : ad.x;
        const float adB = hA ? ad.w : ad.z;
        const float mA  = hA ? m.y  : m.x;
        const float mB  = hA ? m.w  : m.z;
        const float ivA = hA ? inv.y : inv.x;
        const float ivB = hA ? inv.w : inv.z;
        const int cA = lane * 4;
        const int cB = 128 + lane * 4;
        float acc[8] = {0.f, 0.f, 0.f, 0.f, 0.f, 0.f, 0.f, 0.f};
        for (int i = beg; i < end; i++) {
            int s = g_csr[i];
            float4 as = *(const float4*)(als + (size_t)s * 4);
            float asA = hA ? as.y : as.x;
            float asB = hA ? as.w : as.z;
            float alA = __expf(lrelu(asA + adA) - mA) * ivA;
            float alB = __expf(lrelu(asB + adB) - mB) * ivB;
            const float* hp = h + (size_t)s * 256;
            float4 v0 = *(const float4*)(hp + cA);
            float4 v1 = *(const float4*)(hp + cB);
            acc[0] = fmaf(alA, v0.x, acc[0]); acc[1] = fmaf(alA, v0.y, acc[1]);
            acc[2] = fmaf(alA, v0.z, acc[2]); acc[3] = fmaf(alA, v0.w, acc[3]);
            acc[4] = fmaf(alB, v1.x, acc[4]); acc[5] = fmaf(alB, v1.y, acc[5]);
            acc[6] = fmaf(alB, v1.z, acc[6]); acc[7] = fmaf(alB, v1.w, acc[7]);
        }
        float4 b0 = *(const float4*)(bias + cA);
        float4 b1 = *(const float4*)(bias + cB);
        float v[8];
        v[0] = acc[0] + b0.x; v[1] = acc[1] + b0.y; v[2] = acc[2] + b0.z; v[3] = acc[3] + b0.w;
        v[4] = acc[4] + b1.x; v[5] = acc[5] + b1.y; v[6] = acc[6] + b1.z; v[7] = acc[7] + b1.w;
        if (DO_ELU) {
#pragma unroll
            for (int j = 0; j < 8; j++) v[j] = elu(v[j]);
        }
        if (EXT_OUT) {
            float* op = extOut + (size_t)n * 256;
            *(float4*)(op + cA) = make_float4(v[0], v[1], v[2], v[3]);
            *(float4*)(op + cB) = make_float4(v[4], v[5], v[6], v[7]);
        } else {
            __half hh[8];
#pragma unroll
            for (int j = 0; j < 8; j++) hh[j] = __float2half(v[j]);
            __half* ap = g_Af + (size_t)n * 256;
            *(uint2*)(ap + cA) = *(uint2*)(hh);
            *(uint2*)(ap + cB) = *(uint2*)(hh + 4);
        }
    } else {
        float adn = ald[n];
        float m = -INFINITY;
        for (int i = beg + lane; i < end; i += 32) {
            int s = g_csr[i];
            m = fmaxf(m, lrelu(als[s] + adn));
        }
#pragma unroll
        for (int o = 16; o; o >>= 1) m = fmaxf(m, __shfl_xor_sync(0xffffffffu, m, o));
        float den = 0.f;
        for (int i = beg + lane; i < end; i += 32) {
            int s = g_csr[i];
            den += __expf(lrelu(als[s] + adn) - m);
        }
#pragma unroll
        for (int o = 16; o; o >>= 1) den += __shfl_xor_sync(0xffffffffu, den, o);
        float iv = 1.f / (den + 1e-16f);
        const int cA = lane * 4;
        float acc[4] = {0.f, 0.f, 0.f, 0.f};
        for (int i = beg; i < end; i++) {
            int s = g_csr[i];
            float al = __expf(lrelu(als[s] + adn) - m) * iv;
            float4 v = *(const float4*)(h + (size_t)s * 128 + cA);
            acc[0] = fmaf(al, v.x, acc[0]); acc[1] = fmaf(al, v.y, acc[1]);
            acc[2] = fmaf(al, v.z, acc[2]); acc[3] = fmaf(al, v.w, acc[3]);
        }
        float4 bv = *(const float4*)(bias + cA);
        float4 o0;
        o0.x = acc[0] + bv.x; o0.y = acc[1] + bv.y;
        o0.z = acc[2] + bv.z; o0.w = acc[3] + bv.w;
        *(float4*)(extOut + (size_t)n * 128 + cA) = o0;
    }
}

// ---------------- launch ----------------
extern "C" void kernel_launch(void* const* d_in, const int* in_sizes, int n_in,
                              void* d_out, int out_size) {
    const float* x   = (const float*)d_in[0];
    const void*  ei  = d_in[1];
    const float* W0  = (const float*)d_in[2];
    const float* as0 = (const float*)d_in[3];
    const float* ad0 = (const float*)d_in[4];
    const float* b0  = (const float*)d_in[5];
    const float* W1  = (const float*)d_in[6];
    const float* as1 = (const float*)d_in[7];
    const float* ad1 = (const float*)d_in[8];
    const float* b1  = (const float*)d_in[9];
    const float* W2  = (const float*)d_in[10];
    const float* as2 = (const float*)d_in[11];
    const float* ad2 = (const float*)d_in[12];
    const float* b2  = (const float*)d_in[13];
    float* out = (float*)d_out;

    const int TB = 256;
    const int gN = (NN + TB - 1) / TB;
    const int gE = (EE + TB - 1) / TB;
    const int gW = (NN + 7) / 8;
    const int GEMM_GRID = MPAD / 128;  // 782
    dim3 grid2(GEMM_GRID, 2);
    dim3 grid1(GEMM_GRID, 1);

    cudaFuncSetAttribute(k_mgemm16<128, 256>, cudaFuncAttributeMaxDynamicSharedMemorySize, SM16_BYTES);
    cudaFuncSetAttribute(k_bgemm<256, 256>,  cudaFuncAttributeMaxDynamicSharedMemorySize, SMB_BYTES);
    cudaFuncSetAttribute(k_bgemm<256, 128>,  cudaFuncAttributeMaxDynamicSharedMemorySize, SMB_BYTES);

    // Order keeps GEMM L0 at launch index 3 (ncu's profile slot).
    k_detect<<<1, 32>>>((const int*)ei);                              // 0
    k_convB<<<(F0 * HID + TB - 1) / TB, TB>>>(W0, F0, HID);           // 1
    k_init_deg<<<gN, TB>>>();                                         // 2
    k_mgemm16<128, 256><<<grid2, 256, SM16_BYTES>>>(x);               // 3  <- profiled
    k_count_edges<<<gE, TB>>>(ei);                                    // 4
    k_scan_partial<<<NSB, 256>>>();                                   // 5
    k_scan_tops<<<1, 128>>>();                                        // 6
    k_scan_final<<<NSB, SCAN_BLK>>>();                                // 7
    k_scatter_self<<<gN, TB>>>();                                     // 8
    k_scatter_edges<<<gE, TB>>>(ei);                                  // 9
    k_scores<256, 4><<<gW, TB>>>(as0, ad0);                           // 10
    k_agg<256, 4, true, false><<<gW, TB>>>(b0, nullptr);              // 11 -> g_Af fp16

    // ---- layer 1: g_Af[N,256] @ W1[256,256] ----
    k_convB<<<(HID * HID + TB - 1) / TB, TB>>>(W1, HID, HID);
    k_bgemm<256, 256><<<grid2, 256, SMB_BYTES>>>();
    k_scores<256, 4><<<gW, TB>>>(as1, ad1);
    k_agg<256, 4, true, false><<<gW, TB>>>(b1, nullptr);              // -> g_Af fp16

    // ---- layer 2: g_Af[N,256] @ W2[256,128], 1 head, no ELU ----
    k_convB<<<(HID * OUTC + TB - 1) / TB, TB>>>(W2, HID, OUTC);
    k_bgemm<256, 128><<<grid1, 256, SMB_BYTES>>>();
    k_scores<128, 1><<<gW, TB>>>(as2, ad2);
    k_agg<128, 1, false, true><<<gW, TB>>>(b2, out);
}

// round 14
// speedup vs baseline: 2.7038x; 1.1225x over previous
#include <cuda_runtime.h>
#include <cuda_fp16.h>
#include <cstdint>
#include <math.h>

// ---------------- problem constants (fixed shapes) ----------------
#define NN 100000      // nodes
#define EE 400000      // edges (without self loops)
#define ET (EE + NN)   // total edges incl self loops
#define F0 128         // input features
#define HID 256        // hidden (4 heads x 64)
#define OUTC 128       // output features
#define SLOPE 0.2f
#define MPAD 100096    // 782 * 128 (row-padded M for the GEMM)

// ---------------- device scratch (no allocations allowed) ----------------
__device__ __align__(16) __half g_hf[(size_t)NN * HID];   // fp16 GEMM output (h)
__device__ __align__(16) __half g_Af[(size_t)NN * HID];   // fp16 agg output (next A)
__device__ __align__(16) float g_als[(size_t)NN * 4];
__device__ __align__(16) float g_ald[(size_t)NN * 4];
__device__ int   g_deg[NN];
__device__ int   g_off[NN + 1];
__device__ int   g_cur[NN];
__device__ int   g_csr[ET];
__device__ int   g_is64;

// fp16 split W^T (small, per layer)
__device__ __align__(16) __half g_Bh[256 * 256];   // W^T hi  [N, K]
__device__ __align__(16) __half g_Bl[256 * 256];   // W^T lo  [N, K]

// scan temporaries
#define SCAN_BLK 1024
#define NSB ((NN + SCAN_BLK - 1) / SCAN_BLK)   // 98
__device__ int g_bsum[NSB];
__device__ int g_bbase[NSB];

// ---------------- helpers ----------------
__device__ __forceinline__ uint32_t smem_u32(const void* p) {
    uint32_t a;
    asm("{ .reg .u64 t; cvta.to.shared.u64 t, %1; cvt.u32.u64 %0, t; }" : "=r"(a) : "l"(p));
    return a;
}
#define SWZ128(off) ((off) ^ (((off) >> 3) & 0x70))

__device__ __forceinline__ void ldmat_x4(uint32_t& r0, uint32_t& r1, uint32_t& r2,
                                         uint32_t& r3, uint32_t addr) {
    asm volatile("ldmatrix.sync.aligned.m8n8.x4.shared.b16 {%0,%1,%2,%3}, [%4];"
        : "=r"(r0), "=r"(r1), "=r"(r2), "=r"(r3) : "r"(addr));
}
__device__ __forceinline__ void mma_fp16(float* d, const uint32_t* a, const uint32_t* b) {
    asm volatile("mma.sync.aligned.m16n8k16.row.col.f32.f16.f16.f32 "
        "{%0,%1,%2,%3}, {%4,%5,%6,%7}, {%8,%9}, {%0,%1,%2,%3};"
        : "+f"(d[0]), "+f"(d[1]), "+f"(d[2]), "+f"(d[3])
        : "r"(a[0]), "r"(a[1]), "r"(a[2]), "r"(a[3]), "r"(b[0]), "r"(b[1]));
}
__device__ __forceinline__ void cp16(uint32_t dst, const void* src, uint32_t src_bytes) {
    asm volatile("cp.async.cg.shared.global [%0], [%1], 16, %2;"
        :: "r"(dst), "l"(src), "r"(src_bytes));
}
#define CP_COMMIT() asm volatile("cp.async.commit_group;" ::: "memory")
#define CP_WAIT0()  asm volatile("cp.async.wait_group 0;" ::: "memory")
#define CP_WAIT1()  asm volatile("cp.async.wait_group 1;" ::: "memory")

__device__ __forceinline__ float2 h2f2(uint32_t u) {
    return __half22float2(*(__half2*)&u);
}

// ---------------- edge-index dtype probe ----------------
__global__ void k_detect(const int* __restrict__ ei32) {
    if (threadIdx.x == 0 && blockIdx.x == 0) {
        int odd_nonzero = 0;
        for (int i = 1; i < 256; i += 2) odd_nonzero += (ei32[i] != 0);
        g_is64 = (odd_nonzero == 0) ? 1 : 0;
    }
}
__device__ __forceinline__ int edge_at(const void* __restrict__ ei, size_t idx) {
    if (g_is64) return (int)((const long long*)ei)[idx];
    return ((const int*)ei)[idx];
}

// ---------------- CSR build ----------------
__global__ void k_init_deg() {
    int i = blockIdx.x * blockDim.x + threadIdx.x;
    if (i < NN) g_deg[i] = 1;
}
__global__ void k_count_edges(const void* __restrict__ ei) {
    int i = blockIdx.x * blockDim.x + threadIdx.x;
    if (i < EE) atomicAdd(&g_deg[edge_at(ei, (size_t)EE + i)], 1);
}

__global__ void k_scan_partial() {  // grid NSB, 256 thr
    __shared__ int sh[256];
    int b = blockIdx.x, t = threadIdx.x;
    int base = b * SCAN_BLK;
    int sum = 0;
    for (int i = t; i < SCAN_BLK; i += 256) {
        int g = base + i;
        if (g < NN) sum += g_deg[g];
    }
    sh[t] = sum; __syncthreads();
    for (int o = 128; o; o >>= 1) { if (t < o) sh[t] += sh[t + o]; __syncthreads(); }
    if (t == 0) g_bsum[b] = sh[0];
}
__global__ void k_scan_tops() {  // 1 block, 128 thr
    __shared__ int sh[128];
    int t = threadIdx.x;
    int v = (t < NSB) ? g_bsum[t] : 0;
    sh[t] = v; __syncthreads();
    for (int o = 1; o < 128; o <<= 1) {
        int u = (t >= o) ? sh[t - o] : 0; __syncthreads();
        sh[t] += u; __syncthreads();
    }
    if (t < NSB) g_bbase[t] = sh[t] - v;
    if (t == 127) g_off[NN] = sh[127];
}
__global__ void k_scan_final() {  // grid NSB, 1024 thr
    __shared__ int sh[SCAN_BLK];
    int b = blockIdx.x, t = threadIdx.x;
    int g = b * SCAN_BLK + t;
    int v = (g < NN) ? g_deg[g] : 0;
    sh[t] = v; __syncthreads();
    for (int o = 1; o < SCAN_BLK; o <<= 1) {
        int u = (t >= o) ? sh[t - o] : 0; __syncthreads();
        sh[t] += u; __syncthreads();
    }
    if (g < NN) g_off[g] = g_bbase[b] + sh[t] - v;
}

__global__ void k_scatter_self() {
    int i = blockIdx.x * blockDim.x + threadIdx.x;
    if (i < NN) { int o = g_off[i]; g_csr[o] = i; g_cur[i] = o + 1; }
}
__global__ void k_scatter_edges(const void* __restrict__ ei) {
    int i = blockIdx.x * blockDim.x + threadIdx.x;
    if (i < EE) {
        int d = edge_at(ei, (size_t)EE + i);
        int p = atomicAdd(&g_cur[d], 1);
        g_csr[p] = edge_at(ei, i);
    }
}

// ---------------- W^T hi/lo fp16 conversion (tiny, per layer) ----------------
__global__ void k_convB(const float* __restrict__ W, int K, int Ncol) {
    int idx = blockIdx.x * blockDim.x + threadIdx.x;   // n*K + k
    if (idx >= K * Ncol) return;
    int n = idx / K, k = idx % K;
    float w = W[k * Ncol + n];
    __half h = __float2half(w);
    __half l = __float2half(w - __half2float(h));
    g_Bh[idx] = h; g_Bl[idx] = l;
}

// ================= GEMM compute core (fp16, 2-pass B-split) =================
#define GEMM_COMPUTE(sAbase, sBbase)                                                   \
    _Pragma("unroll")                                                                   \
    for (int kk = 0; kk < 4; kk++) {                                                    \
        const int k0 = kk * 16;                                                         \
        uint32_t bh[4][2], bl[4][2];                                                    \
        _Pragma("unroll")                                                               \
        for (int nb = 0; nb < 2; nb++) {                                                \
            int nrow = wn * 32 + nb * 16 + (mat >> 1) * 8 + rr;                         \
            uint32_t boff = SWZ128((uint32_t)(nrow * 128 + (k0 + (mat & 1) * 8) * 2));  \
            uint32_t r0, r1, r2, r3;                                                    \
            ldmat_x4(r0, r1, r2, r3, (sBbase) + boff);                                  \
            bh[nb * 2][0] = r0;     bh[nb * 2][1] = r1;                                 \
            bh[nb * 2 + 1][0] = r2; bh[nb * 2 + 1][1] = r3;                             \
            ldmat_x4(r0, r1, r2, r3, (sBbase) + 16384 + boff);                          \
            bl[nb * 2][0] = r0;     bl[nb * 2][1] = r1;                                 \
            bl[nb * 2 + 1][0] = r2; bl[nb * 2 + 1][1] = r3;                             \
        }                                                                               \
        uint32_t a[4][4];                                                               \
        _Pragma("unroll")                                                               \
        for (int ms = 0; ms < 4; ms++) {                                                \
            int row = wm * 64 + ms * 16 + (mat & 1) * 8 + rr;                           \
            uint32_t aoff = SWZ128((uint32_t)(row * 128 + (k0 + (mat >> 1) * 8) * 2));  \
            ldmat_x4(a[ms][0], a[ms][1], a[ms][2], a[ms][3], (sAbase) + aoff);          \
        }                                                                               \
        _Pragma("unroll")                                                               \
        for (int ms = 0; ms < 4; ms++)                                                  \
            _Pragma("unroll")                                                           \
            for (int ns = 0; ns < 4; ns++)                                              \
                mma_fp16(acc[ms][ns], a[ms], bh[ns]);                                   \
        _Pragma("unroll")                                                               \
        for (int ms = 0; ms < 4; ms++)                                                  \
            _Pragma("unroll")                                                           \
            for (int ns = 0; ns < 4; ns++)                                              \
                mma_fp16(acc[ms][ns], a[ms], bl[ns]);                                   \
    }

// epilogue: write h as fp16 (half2 stores)
#define GEMM_EPILOGUE(NT)                                                               \
    const int cr = lane >> 2;                                                           \
    const int cc2 = (lane & 3) * 2;                                                     \
    _Pragma("unroll")                                                                   \
    for (int ms = 0; ms < 4; ms++) {                                                    \
        _Pragma("unroll")                                                               \
        for (int ns = 0; ns < 4; ns++) {                                                \
            size_t row0 = rowBase + wm * 64 + ms * 16 + cr;                             \
            int col = nBase + wn * 32 + ns * 8 + cc2;                                   \
            if (row0 < NN)                                                              \
                *(__half2*)(g_hf + row0 * (NT) + col) =                                 \
                    __floats2half2_rn(acc[ms][ns][0], acc[ms][ns][1]);                  \
            size_t row1 = row0 + 8;                                                     \
            if (row1 < NN)                                                              \
                *(__half2*)(g_hf + row1 * (NT) + col) =                                 \
                    __floats2half2_rn(acc[ms][ns][2], acc[ms][ns][3]);                  \
        }                                                                               \
    }

// ---------------- L0 GEMM: fp32 x -> fused fp16 convert ----------------
// smem: smF raw fp32 32KB @0 ; smA fp16 16KB @32768 ; smB (Bh,Bl) 32KB @49152.
#define SM16_BYTES (81920 + 1024)
template <int K, int NT>
__global__ __launch_bounds__(256, 2) void k_mgemm16(const float* __restrict__ A) {
    extern __shared__ char dynsm[];
    char* smp = (char*)(((uintptr_t)dynsm + 1023) & ~(uintptr_t)1023);
    const uint32_t sF = smem_u32(smp);
    const uint32_t sA = sF + 32768;
    const uint32_t sB = sF + 49152;

    const int tid = threadIdx.x;
    const int wid = tid >> 5;
    const int lane = tid & 31;
    const int wm = wid >> 2;
    const int wn = wid & 3;
    const size_t rowBase = (size_t)blockIdx.x * 128;
    const int nBase = blockIdx.y * 128;

    float acc[4][4][4];
#pragma unroll
    for (int i = 0; i < 4; i++)
#pragma unroll
        for (int j = 0; j < 4; j++)
#pragma unroll
            for (int f = 0; f < 4; f++) acc[i][j][f] = 0.f;

    const int mat = lane >> 3;
    const int rr = lane & 7;
    constexpr int CH = K / 64;

    auto stageA = [&](int cc) {
        const int off = cc * 64;
#pragma unroll
        for (int u = tid; u < 2048; u += 256) {
            int r = u >> 4, q = u & 15;
            size_t gr = rowBase + r;
            uint32_t ok = (gr < NN) ? 16u : 0u;
            const float* src = A + (gr < NN ? gr : 0) * K + off + q * 4;
            cp16(sF + (uint32_t)(r * 256 + q * 16), src, ok);
        }
    };
    auto stageB = [&](int cc) {
        const int off = cc * 64;
#pragma unroll
        for (int u = tid; u < 1024; u += 256) {
            int r = u >> 3, uu = u & 7;
            uint32_t boff = SWZ128((uint32_t)(r * 128 + uu * 16));
            const size_t gsrc = (size_t)(nBase + r) * K + off + uu * 8;
            cp16(sB + boff,         g_Bh + gsrc, 16u);
            cp16(sB + 16384 + boff, g_Bl + gsrc, 16u);
        }
    };

    stageA(0); CP_COMMIT();

    for (int c = 0; c < CH; c++) {
        CP_WAIT0();
        __syncthreads();
#pragma unroll
        for (int u = tid; u < 2048; u += 256) {
            int r = u >> 4, q = u & 15;
            float4 v = *(const float4*)(smp + r * 256 + q * 16);
            __half h[4];
            h[0] = __float2half(v.x); h[1] = __float2half(v.y);
            h[2] = __float2half(v.z); h[3] = __float2half(v.w);
            uint32_t boff = SWZ128((uint32_t)(r * 128 + q * 8));
            *(uint2*)(smp + 32768 + boff) = *(uint2*)h;
        }
        __syncthreads();
        stageB(c); CP_COMMIT();
        if (c + 1 < CH) { stageA(c + 1); CP_COMMIT(); CP_WAIT1(); }
        else            { CP_WAIT0(); }
        __syncthreads();
        GEMM_COMPUTE(sA, sB)
    }
    GEMM_EPILOGUE(NT)
}

// ---------------- L1/L2 GEMM: fp16 A direct, double-buffered A ----------------
// smem: smA[2] 2x16KB @0 ; smB (Bh,Bl) 32KB @32768. Total 64KB.
#define SMB_BYTES (65536 + 1024)
template <int K, int NT>
__global__ __launch_bounds__(256, 2) void k_bgemm() {
    extern __shared__ char dynsm[];
    char* smp = (char*)(((uintptr_t)dynsm + 1023) & ~(uintptr_t)1023);
    const uint32_t sA0 = smem_u32(smp);
    const uint32_t sB  = sA0 + 32768;

    const int tid = threadIdx.x;
    const int wid = tid >> 5;
    const int lane = tid & 31;
    const int wm = wid >> 2;
    const int wn = wid & 3;
    const size_t rowBase = (size_t)blockIdx.x * 128;
    const int nBase = blockIdx.y * 128;

    float acc[4][4][4];
#pragma unroll
    for (int i = 0; i < 4; i++)
#pragma unroll
        for (int j = 0; j < 4; j++)
#pragma unroll
            for (int f = 0; f < 4; f++) acc[i][j][f] = 0.f;

    const int mat = lane >> 3;
    const int rr = lane & 7;
    constexpr int CH = K / 64;

    auto stageA = [&](int cc) {
        const int buf = cc & 1;
        const int off = cc * 64;
#pragma unroll
        for (int u = tid; u < 1024; u += 256) {
            int r = u >> 3, uu = u & 7;
            size_t gr = rowBase + r;
            uint32_t ok = (gr < NN) ? 16u : 0u;
            const __half* src = g_Af + (gr < NN ? gr : 0) * K + off + uu * 8;
            cp16(sA0 + buf * 16384 + SWZ128((uint32_t)(r * 128 + uu * 16)), src, ok);
        }
    };
    auto stageB = [&](int cc) {
        const int off = cc * 64;
#pragma unroll
        for (int u = tid; u < 1024; u += 256) {
            int r = u >> 3, uu = u & 7;
            uint32_t boff = SWZ128((uint32_t)(r * 128 + uu * 16));
            const size_t gsrc = (size_t)(nBase + r) * K + off + uu * 8;
            cp16(sB + boff,         g_Bh + gsrc, 16u);
            cp16(sB + 16384 + boff, g_Bl + gsrc, 16u);
        }
    };

    stageA(0); CP_COMMIT();

    for (int c = 0; c < CH; c++) {
        stageB(c); CP_COMMIT();
        if (c + 1 < CH) { stageA(c + 1); CP_COMMIT(); CP_WAIT1(); }
        else            { CP_WAIT0(); }
        __syncthreads();
        const uint32_t sA = sA0 + (c & 1) * 16384;
        GEMM_COMPUTE(sA, sB)
        __syncthreads();
    }
    GEMM_EPILOGUE(NT)
}

// ---------------- per-node attention scores (fp16 h) ----------------
template <int CT, int H>
__global__ __launch_bounds__(256) void k_scores(const float* __restrict__ a_s,
                                                const float* __restrict__ a_d) {
    int wid = (blockIdx.x * blockDim.x + threadIdx.x) >> 5;
    int lane = threadIdx.x & 31;
    if (wid >= NN) return;
    const __half* hp = g_hf + (size_t)wid * CT;

    int cA = lane * 4;
    uint2 hr = *(const uint2*)(hp + cA);
    float2 h01 = h2f2(hr.x), h23 = h2f2(hr.y);
    float4 sv = *(const float4*)(a_s + cA);
    float4 dv = *(const float4*)(a_d + cA);
    float psA = h01.x * sv.x + h01.y * sv.y + h23.x * sv.z + h23.y * sv.w;
    float pdA = h01.x * dv.x + h01.y * dv.y + h23.x * dv.z + h23.y * dv.w;

    if (CT == 256) {
        int cB = 128 + lane * 4;
        uint2 hr2 = *(const uint2*)(hp + cB);
        float2 g01 = h2f2(hr2.x), g23 = h2f2(hr2.y);
        float4 sv2 = *(const float4*)(a_s + cB);
        float4 dv2 = *(const float4*)(a_d + cB);
        float psB = g01.x * sv2.x + g01.y * sv2.y + g23.x * sv2.z + g23.y * sv2.w;
        float pdB = g01.x * dv2.x + g01.y * dv2.y + g23.x * dv2.z + g23.y * dv2.w;
#pragma unroll
        for (int o = 8; o; o >>= 1) {
            psA += __shfl_xor_sync(0xffffffffu, psA, o);
            pdA += __shfl_xor_sync(0xffffffffu, pdA, o);
            psB += __shfl_xor_sync(0xffffffffu, psB, o);
            pdB += __shfl_xor_sync(0xffffffffu, pdB, o);
        }
        if (lane == 0)  { g_als[wid * 4 + 0] = psA; g_ald[wid * 4 + 0] = pdA;
                          g_als[wid * 4 + 2] = psB; g_ald[wid * 4 + 2] = pdB; }
        if (lane == 16) { g_als[wid * 4 + 1] = psA; g_ald[wid * 4 + 1] = pdA;
                          g_als[wid * 4 + 3] = psB; g_ald[wid * 4 + 3] = pdB; }
    } else {
#pragma unroll
        for (int o = 16; o; o >>= 1) {
            psA += __shfl_xor_sync(0xffffffffu, psA, o);
            pdA += __shfl_xor_sync(0xffffffffu, pdA, o);
        }
        if (lane == 0) { g_als[wid] = psA; g_ald[wid] = pdA; }
    }
}

__device__ __forceinline__ float lrelu(float x) { return x > 0.f ? x : SLOPE * x; }
__device__ __forceinline__ float elu(float x)   { return x > 0.f ? x : expm1f(x); }

// ---------------- warp-per-dst-node softmax + aggregation (fp16 gather) ----------------
// EXT_OUT: write fp32 to extOut (final layer). Else: write fp16 to g_Af.
template <int CT, int H, bool DO_ELU, bool EXT_OUT>
__global__ __launch_bounds__(256) void k_agg(const float* __restrict__ bias,
                                             float* __restrict__ extOut) {
    int n = (blockIdx.x * blockDim.x + threadIdx.x) >> 5;
    int lane = threadIdx.x & 31;
    if (n >= NN) return;
    const int beg = g_off[n], end = g_off[n + 1];
    const float* __restrict__ als = g_als;
    const float* __restrict__ ald = g_ald;

    if (H == 4) {
        float4 ad = *(const float4*)(ald + (size_t)n * 4);
        float4 m = make_float4(-INFINITY, -INFINITY, -INFINITY, -INFINITY);
        for (int i = beg + lane; i < end; i += 32) {
            int s = g_csr[i];
            float4 as = *(const float4*)(als + (size_t)s * 4);
            m.x = fmaxf(m.x, lrelu(as.x + ad.x));
            m.y = fmaxf(m.y, lrelu(as.y + ad.y));
            m.z = fmaxf(m.z, lrelu(as.z + ad.z));
            m.w = fmaxf(m.w, lrelu(as.w + ad.w));
        }
#pragma unroll
        for (int o = 16; o; o >>= 1) {
            m.x = fmaxf(m.x, __shfl_xor_sync(0xffffffffu, m.x, o));
            m.y = fmaxf(m.y, __shfl_xor_sync(0xffffffffu, m.y, o));
            m.z = fmaxf(m.z, __shfl_xor_sync(0xffffffffu, m.z, o));
            m.w = fmaxf(m.w, __shfl_xor_sync(0xffffffffu, m.w, o));
        }
        float4 den = make_float4(0.f, 0.f, 0.f, 0.f);
        for (int i = beg + lane; i < end; i += 32) {
            int s = g_csr[i];
            float4 as = *(const float4*)(als + (size_t)s * 4);
            den.x += __expf(lrelu(as.x + ad.x) - m.x);
            den.y += __expf(lrelu(as.y + ad.y) - m.y);
            den.z += __expf(lrelu(as.z + ad.z) - m.z);
            den.w += __expf(lrelu(as.w + ad.w) - m.w);
        }
#pragma unroll
        for (int o = 16; o; o >>= 1) {
            den.x += __shfl_xor_sync(0xffffffffu, den.x, o);
            den.y += __shfl_xor_sync(0xffffffffu, den.y, o);
            den.z += __shfl_xor_sync(0xffffffffu, den.z, o);
            den.w += __shfl_xor_sync(0xffffffffu, den.w, o);
        }
        float4 inv = make_float4(1.f / (den.x + 1e-16f), 1.f / (den.y + 1e-16f),
                                 1.f / (den.z + 1e-16f), 1.f / (den.w + 1e-16f));
        const int hA = lane >> 4;
        const float adA = hA ? ad.y : ad.x;
        const float adB = hA ? ad.w : ad.z;
        const float mA  = hA ? m.y  : m.x;
        const float mB  = hA ? m.w  : m.z;
        const float ivA = hA ? inv.y : inv.x;
        const float ivB = hA ? inv.w : inv.z;
        const int cA = lane * 4;
        const int cB = 128 + lane * 4;
        float acc[8] = {0.f, 0.f, 0.f, 0.f, 0.f, 0.f, 0.f, 0.f};
        for (int i = beg; i < end; i++) {
            int s = g_csr[i];
            float4 as = *(const float4*)(als + (size_t)s * 4);
            float asA = hA ? as.y : as.x;
            float asB = hA ? as.w : as.z;
            float alA = __expf(lrelu(asA + adA) - mA) * ivA;
            float alB = __expf(lrelu(asB + adB) - mB) * ivB;
            const __half* hp = g_hf + (size_t)s * 256;
            uint2 r0 = *(const uint2*)(hp + cA);
            uint2 r1 = *(const uint2*)(hp + cB);
            float2 a01 = h2f2(r0.x), a23 = h2f2(r0.y);
            float2 b01 = h2f2(r1.x), b23 = h2f2(r1.y);
            acc[0] = fmaf(alA, a01.x, acc[0]); acc[1] = fmaf(alA, a01.y, acc[1]);
            acc[2] = fmaf(alA, a23.x, acc[2]); acc[3] = fmaf(alA, a23.y, acc[3]);
            acc[4] = fmaf(alB, b01.x, acc[4]); acc[5] = fmaf(alB, b01.y, acc[5]);
            acc[6] = fmaf(alB, b23.x, acc[6]); acc[7] = fmaf(alB, b23.y, acc[7]);
        }
        float4 b0 = *(const float4*)(bias + cA);
        float4 b1 = *(const float4*)(bias + cB);
        float v[8];
        v[0] = acc[0] + b0.x; v[1] = acc[1] + b0.y; v[2] = acc[2] + b0.z; v[3] = acc[3] + b0.w;
        v[4] = acc[4] + b1.x; v[5] = acc[5] + b1.y; v[6] = acc[6] + b1.z; v[7] = acc[7] + b1.w;
        if (DO_ELU) {
#pragma unroll
            for (int j = 0; j < 8; j++) v[j] = elu(v[j]);
        }
        if (EXT_OUT) {
            float* op = extOut + (size_t)n * 256;
            *(float4*)(op + cA) = make_float4(v[0], v[1], v[2], v[3]);
            *(float4*)(op + cB) = make_float4(v[4], v[5], v[6], v[7]);
        } else {
            __half hh[8];
#pragma unroll
            for (int j = 0; j < 8; j++) hh[j] = __float2half(v[j]);
            __half* ap = g_Af + (size_t)n * 256;
            *(uint2*)(ap + cA) = *(uint2*)(hh);
            *(uint2*)(ap + cB) = *(uint2*)(hh + 4);
        }
    } else {
        float adn = ald[n];
        float m = -INFINITY;
        for (int i = beg + lane; i < end; i += 32) {
            int s = g_csr[i];
            m = fmaxf(m, lrelu(als[s] + adn));
        }
#pragma unroll
        for (int o = 16; o; o >>= 1) m = fmaxf(m, __shfl_xor_sync(0xffffffffu, m, o));
        float den = 0.f;
        for (int i = beg + lane; i < end; i += 32) {
            int s = g_csr[i];
            den += __expf(lrelu(als[s] + adn) - m);
        }
#pragma unroll
        for (int o = 16; o; o >>= 1) den += __shfl_xor_sync(0xffffffffu, den, o);
        float iv = 1.f / (den + 1e-16f);
        const int cA = lane * 4;
        float acc[4] = {0.f, 0.f, 0.f, 0.f};
        for (int i = beg; i < end; i++) {
            int s = g_csr[i];
            float al = __expf(lrelu(als[s] + adn) - m) * iv;
            const __half* hp = g_hf + (size_t)s * 128;
            uint2 r0 = *(const uint2*)(hp + cA);
            float2 a01 = h2f2(r0.x), a23 = h2f2(r0.y);
            acc[0] = fmaf(al, a01.x, acc[0]); acc[1] = fmaf(al, a01.y, acc[1]);
            acc[2] = fmaf(al, a23.x, acc[2]); acc[3] = fmaf(al, a23.y, acc[3]);
        }
        float4 bv = *(const float4*)(bias + cA);
        float4 o0;
        o0.x = acc[0] + bv.x; o0.y = acc[1] + bv.y;
        o0.z = acc[2] + bv.z; o0.w = acc[3] + bv.w;
        *(float4*)(extOut + (size_t)n * 128 + cA) = o0;
    }
}

// ---------------- launch ----------------
extern "C" void kernel_launch(void* const* d_in, const int* in_sizes, int n_in,
                              void* d_out, int out_size) {
    const float* x   = (const float*)d_in[0];
    const void*  ei  = d_in[1];
    const float* W0  = (const float*)d_in[2];
    const float* as0 = (const float*)d_in[3];
    const float* ad0 = (const float*)d_in[4];
    const float* b0  = (const float*)d_in[5];
    const float* W1  = (const float*)d_in[6];
    const float* as1 = (const float*)d_in[7];
    const float* ad1 = (const float*)d_in[8];
    const float* b1  = (const float*)d_in[9];
    const float* W2  = (const float*)d_in[10];
    const float* as2 = (const float*)d_in[11];
    const float* ad2 = (const float*)d_in[12];
    const float* b2  = (const float*)d_in[13];
    float* out = (float*)d_out;

    const int TB = 256;
    const int gN = (NN + TB - 1) / TB;
    const int gE = (EE + TB - 1) / TB;
    const int gW = (NN + 7) / 8;
    const int GEMM_GRID = MPAD / 128;  // 782
    dim3 grid2(GEMM_GRID, 2);
    dim3 grid1(GEMM_GRID, 1);

    cudaFuncSetAttribute(k_mgemm16<128, 256>, cudaFuncAttributeMaxDynamicSharedMemorySize, SM16_BYTES);
    cudaFuncSetAttribute(k_bgemm<256, 256>,  cudaFuncAttributeMaxDynamicSharedMemorySize, SMB_BYTES);
    cudaFuncSetAttribute(k_bgemm<256, 128>,  cudaFuncAttributeMaxDynamicSharedMemorySize, SMB_BYTES);

    // Order keeps GEMM L0 at launch index 3 (ncu's profile slot).
    k_detect<<<1, 32>>>((const int*)ei);                              // 0
    k_convB<<<(F0 * HID + TB - 1) / TB, TB>>>(W0, F0, HID);           // 1
    k_init_deg<<<gN, TB>>>();                                         // 2
    k_mgemm16<128, 256><<<grid2, 256, SM16_BYTES>>>(x);               // 3  <- profiled
    k_count_edges<<<gE, TB>>>(ei);                                    // 4
    k_scan_partial<<<NSB, 256>>>();                                   // 5
    k_scan_tops<<<1, 128>>>();                                        // 6
    k_scan_final<<<NSB, SCAN_BLK>>>();                                // 7
    k_scatter_self<<<gN, TB>>>();                                     // 8
    k_scatter_edges<<<gE, TB>>>(ei);                                  // 9
    k_scores<256, 4><<<gW, TB>>>(as0, ad0);                           // 10
    k_agg<256, 4, true, false><<<gW, TB>>>(b0, nullptr);              // 11 -> g_Af fp16

    // ---- layer 1: g_Af[N,256] @ W1[256,256] ----
    k_convB<<<(HID * HID + TB - 1) / TB, TB>>>(W1, HID, HID);
    k_bgemm<256, 256><<<grid2, 256, SMB_BYTES>>>();
    k_scores<256, 4><<<gW, TB>>>(as1, ad1);
    k_agg<256, 4, true, false><<<gW, TB>>>(b1, nullptr);              // -> g_Af fp16

    // ---- layer 2: g_Af[N,256] @ W2[256,128], 1 head, no ELU ----
    k_convB<<<(HID * OUTC + TB - 1) / TB, TB>>>(W2, HID, OUTC);
    k_bgemm<256, 128><<<grid1, 256, SMB_BYTES>>>();
    k_scores<128, 1><<<gW, TB>>>(as2, ad2);
    k_agg<128, 1, false, true><<<gW, TB>>>(b2, out);
}

// round 15
// speedup vs baseline: 2.7085x; 1.0017x over previous
#include <cuda_runtime.h>
#include <cuda_fp16.h>
#include <cstdint>
#include <math.h>

// ---------------- problem constants (fixed shapes) ----------------
#define NN 100000      // nodes
#define EE 400000      // edges (without self loops)
#define ET (EE + NN)   // total edges incl self loops
#define F0 128         // input features
#define HID 256        // hidden (4 heads x 64)
#define OUTC 128       // output features
#define SLOPE 0.2f
#define MPAD 100096    // 782 * 128 (row-padded M for the GEMM)

// ---------------- device scratch (no allocations allowed) ----------------
__device__ __align__(16) __half g_hf[(size_t)NN * HID];   // fp16 GEMM output (h)
__device__ __align__(16) __half g_Af[(size_t)NN * HID];   // fp16 agg output (next A)
__device__ __align__(16) float g_als[(size_t)NN * 4];
__device__ __align__(16) float g_ald[(size_t)NN * 4];
__device__ int   g_deg[NN];
__device__ int   g_off[NN + 1];
__device__ int   g_cur[NN];
__device__ int   g_csr[ET];
__device__ int   g_is64;

// fp16 split W^T (small, per layer)
__device__ __align__(16) __half g_Bh[256 * 256];   // W^T hi  [N, K]
__device__ __align__(16) __half g_Bl[256 * 256];   // W^T lo  [N, K]

// scan temporaries
#define SCAN_BLK 1024
#define NSB ((NN + SCAN_BLK - 1) / SCAN_BLK)   // 98
__device__ int g_bsum[NSB];
__device__ int g_bbase[NSB];

// ---------------- helpers ----------------
__device__ __forceinline__ uint32_t smem_u32(const void* p) {
    uint32_t a;
    asm("{ .reg .u64 t; cvta.to.shared.u64 t, %1; cvt.u32.u64 %0, t; }" : "=r"(a) : "l"(p));
    return a;
}
#define SWZ128(off) ((off) ^ (((off) >> 3) & 0x70))

__device__ __forceinline__ void ldmat_x4(uint32_t& r0, uint32_t& r1, uint32_t& r2,
                                         uint32_t& r3, uint32_t addr) {
    asm volatile("ldmatrix.sync.aligned.m8n8.x4.shared.b16 {%0,%1,%2,%3}, [%4];"
        : "=r"(r0), "=r"(r1), "=r"(r2), "=r"(r3) : "r"(addr));
}
__device__ __forceinline__ void mma_fp16(float* d, const uint32_t* a, const uint32_t* b) {
    asm volatile("mma.sync.aligned.m16n8k16.row.col.f32.f16.f16.f32 "
        "{%0,%1,%2,%3}, {%4,%5,%6,%7}, {%8,%9}, {%0,%1,%2,%3};"
        : "+f"(d[0]), "+f"(d[1]), "+f"(d[2]), "+f"(d[3])
        : "r"(a[0]), "r"(a[1]), "r"(a[2]), "r"(a[3]), "r"(b[0]), "r"(b[1]));
}
__device__ __forceinline__ void cp16(uint32_t dst, const void* src, uint32_t src_bytes) {
    asm volatile("cp.async.cg.shared.global [%0], [%1], 16, %2;"
        :: "r"(dst), "l"(src), "r"(src_bytes));
}
#define CP_COMMIT() asm volatile("cp.async.commit_group;" ::: "memory")
#define CP_WAIT0()  asm volatile("cp.async.wait_group 0;" ::: "memory")
#define CP_WAIT1()  asm volatile("cp.async.wait_group 1;" ::: "memory")

__device__ __forceinline__ float2 h2f2(uint32_t u) {
    return __half22float2(*(__half2*)&u);
}

// ---------------- edge-index dtype probe + deg init (fused) ----------------
__global__ void k_detect_init(const int* __restrict__ ei32) {
    int i = blockIdx.x * blockDim.x + threadIdx.x;
    if (i < NN) g_deg[i] = 1;   // self loop
    if (i == 0) {
        int odd_nonzero = 0;
        for (int j = 1; j < 256; j += 2) odd_nonzero += (ei32[j] != 0);
        g_is64 = (odd_nonzero == 0) ? 1 : 0;
    }
}
__device__ __forceinline__ int edge_at(const void* __restrict__ ei, size_t idx) {
    if (g_is64) return (int)((const long long*)ei)[idx];
    return ((const int*)ei)[idx];
}

// ---------------- CSR build ----------------
__global__ void k_count_edges(const void* __restrict__ ei) {
    int i = blockIdx.x * blockDim.x + threadIdx.x;
    if (i < EE) atomicAdd(&g_deg[edge_at(ei, (size_t)EE + i)], 1);
}

__global__ void k_scan_partial() {  // grid NSB, 256 thr
    __shared__ int sh[256];
    int b = blockIdx.x, t = threadIdx.x;
    int base = b * SCAN_BLK;
    int sum = 0;
    for (int i = t; i < SCAN_BLK; i += 256) {
        int g = base + i;
        if (g < NN) sum += g_deg[g];
    }
    sh[t] = sum; __syncthreads();
    for (int o = 128; o; o >>= 1) { if (t < o) sh[t] += sh[t + o]; __syncthreads(); }
    if (t == 0) g_bsum[b] = sh[0];
}
__global__ void k_scan_tops() {  // 1 block, 128 thr
    __shared__ int sh[128];
    int t = threadIdx.x;
    int v = (t < NSB) ? g_bsum[t] : 0;
    sh[t] = v; __syncthreads();
    for (int o = 1; o < 128; o <<= 1) {
        int u = (t >= o) ? sh[t - o] : 0; __syncthreads();
        sh[t] += u; __syncthreads();
    }
    if (t < NSB) g_bbase[t] = sh[t] - v;
    if (t == 127) g_off[NN] = sh[127];
}
__global__ void k_scan_final() {  // grid NSB, 1024 thr
    __shared__ int sh[SCAN_BLK];
    int b = blockIdx.x, t = threadIdx.x;
    int g = b * SCAN_BLK + t;
    int v = (g < NN) ? g_deg[g] : 0;
    sh[t] = v; __syncthreads();
    for (int o = 1; o < SCAN_BLK; o <<= 1) {
        int u = (t >= o) ? sh[t - o] : 0; __syncthreads();
        sh[t] += u; __syncthreads();
    }
    if (g < NN) g_off[g] = g_bbase[b] + sh[t] - v;
}

__global__ void k_scatter_self() {
    int i = blockIdx.x * blockDim.x + threadIdx.x;
    if (i < NN) { int o = g_off[i]; g_csr[o] = i; g_cur[i] = o + 1; }
}
__global__ void k_scatter_edges(const void* __restrict__ ei) {
    int i = blockIdx.x * blockDim.x + threadIdx.x;
    if (i < EE) {
        int d = edge_at(ei, (size_t)EE + i);
        int p = atomicAdd(&g_cur[d], 1);
        g_csr[p] = edge_at(ei, i);
    }
}

// ---------------- W^T hi/lo fp16 conversion (tiny, per layer) ----------------
__global__ void k_convB(const float* __restrict__ W, int K, int Ncol) {
    int idx = blockIdx.x * blockDim.x + threadIdx.x;   // n*K + k
    if (idx >= K * Ncol) return;
    int n = idx / K, k = idx % K;
    float w = W[k * Ncol + n];
    __half h = __float2half(w);
    __half l = __float2half(w - __half2float(h));
    g_Bh[idx] = h; g_Bl[idx] = l;
}

// ================= GEMM compute core (fp16, 2-pass B-split) =================
#define GEMM_COMPUTE(sAbase, sBbase)                                                   \
    _Pragma("unroll")                                                                   \
    for (int kk = 0; kk < 4; kk++) {                                                    \
        const int k0 = kk * 16;                                                         \
        uint32_t bh[4][2], bl[4][2];                                                    \
        _Pragma("unroll")                                                               \
        for (int nb = 0; nb < 2; nb++) {                                                \
            int nrow = wn * 32 + nb * 16 + (mat >> 1) * 8 + rr;                         \
            uint32_t boff = SWZ128((uint32_t)(nrow * 128 + (k0 + (mat & 1) * 8) * 2));  \
            uint32_t r0, r1, r2, r3;                                                    \
            ldmat_x4(r0, r1, r2, r3, (sBbase) + boff);                                  \
            bh[nb * 2][0] = r0;     bh[nb * 2][1] = r1;                                 \
            bh[nb * 2 + 1][0] = r2; bh[nb * 2 + 1][1] = r3;                             \
            ldmat_x4(r0, r1, r2, r3, (sBbase) + 16384 + boff);                          \
            bl[nb * 2][0] = r0;     bl[nb * 2][1] = r1;                                 \
            bl[nb * 2 + 1][0] = r2; bl[nb * 2 + 1][1] = r3;                             \
        }                                                                               \
        uint32_t a[4][4];                                                               \
        _Pragma("unroll")                                                               \
        for (int ms = 0; ms < 4; ms++) {                                                \
            int row = wm * 64 + ms * 16 + (mat & 1) * 8 + rr;                           \
            uint32_t aoff = SWZ128((uint32_t)(row * 128 + (k0 + (mat >> 1) * 8) * 2));  \
            ldmat_x4(a[ms][0], a[ms][1], a[ms][2], a[ms][3], (sAbase) + aoff);          \
        }                                                                               \
        _Pragma("unroll")                                                               \
        for (int ms = 0; ms < 4; ms++)                                                  \
            _Pragma("unroll")                                                           \
            for (int ns = 0; ns < 4; ns++)                                              \
                mma_fp16(acc[ms][ns], a[ms], bh[ns]);                                   \
        _Pragma("unroll")                                                               \
        for (int ms = 0; ms < 4; ms++)                                                  \
            _Pragma("unroll")                                                           \
            for (int ns = 0; ns < 4; ns++)                                              \
                mma_fp16(acc[ms][ns], a[ms], bl[ns]);                                   \
    }

// epilogue: write h as fp16 (half2 stores)
#define GEMM_EPILOGUE(NT)                                                               \
    const int cr = lane >> 2;                                                           \
    const int cc2 = (lane & 3) * 2;                                                     \
    _Pragma("unroll")                                                                   \
    for (int ms = 0; ms < 4; ms++) {                                                    \
        _Pragma("unroll")                                                               \
        for (int ns = 0; ns < 4; ns++) {                                                \
            size_t row0 = rowBase + wm * 64 + ms * 16 + cr;                             \
            int col = nBase + wn * 32 + ns * 8 + cc2;                                   \
            if (row0 < NN)                                                              \
                *(__half2*)(g_hf + row0 * (NT) + col) =                                 \
                    __floats2half2_rn(acc[ms][ns][0], acc[ms][ns][1]);                  \
            size_t row1 = row0 + 8;                                                     \
            if (row1 < NN)                                                              \
                *(__half2*)(g_hf + row1 * (NT) + col) =                                 \
                    __floats2half2_rn(acc[ms][ns][2], acc[ms][ns][3]);                  \
        }                                                                               \
    }

// ---------------- L0 GEMM: fp32 x -> fused fp16 convert ----------------
// smem: smF raw fp32 32KB @0 ; smA fp16 16KB @32768 ; smB (Bh,Bl) 32KB @49152.
#define SM16_BYTES (81920 + 1024)
template <int K, int NT>
__global__ __launch_bounds__(256, 2) void k_mgemm16(const float* __restrict__ A) {
    extern __shared__ char dynsm[];
    char* smp = (char*)(((uintptr_t)dynsm + 1023) & ~(uintptr_t)1023);
    const uint32_t sF = smem_u32(smp);
    const uint32_t sA = sF + 32768;
    const uint32_t sB = sF + 49152;

    const int tid = threadIdx.x;
    const int wid = tid >> 5;
    const int lane = tid & 31;
    const int wm = wid >> 2;
    const int wn = wid & 3;
    const size_t rowBase = (size_t)blockIdx.x * 128;
    const int nBase = blockIdx.y * 128;

    float acc[4][4][4];
#pragma unroll
    for (int i = 0; i < 4; i++)
#pragma unroll
        for (int j = 0; j < 4; j++)
#pragma unroll
            for (int f = 0; f < 4; f++) acc[i][j][f] = 0.f;

    const int mat = lane >> 3;
    const int rr = lane & 7;
    constexpr int CH = K / 64;

    auto stageA = [&](int cc) {
        const int off = cc * 64;
#pragma unroll
        for (int u = tid; u < 2048; u += 256) {
            int r = u >> 4, q = u & 15;
            size_t gr = rowBase + r;
            uint32_t ok = (gr < NN) ? 16u : 0u;
            const float* src = A + (gr < NN ? gr : 0) * K + off + q * 4;
            cp16(sF + (uint32_t)(r * 256 + q * 16), src, ok);
        }
    };
    auto stageB = [&](int cc) {
        const int off = cc * 64;
#pragma unroll
        for (int u = tid; u < 1024; u += 256) {
            int r = u >> 3, uu = u & 7;
            uint32_t boff = SWZ128((uint32_t)(r * 128 + uu * 16));
            const size_t gsrc = (size_t)(nBase + r) * K + off + uu * 8;
            cp16(sB + boff,         g_Bh + gsrc, 16u);
            cp16(sB + 16384 + boff, g_Bl + gsrc, 16u);
        }
    };

    stageA(0); CP_COMMIT();

    for (int c = 0; c < CH; c++) {
        CP_WAIT0();
        __syncthreads();
#pragma unroll
        for (int u = tid; u < 2048; u += 256) {
            int r = u >> 4, q = u & 15;
            float4 v = *(const float4*)(smp + r * 256 + q * 16);
            __half h[4];
            h[0] = __float2half(v.x); h[1] = __float2half(v.y);
            h[2] = __float2half(v.z); h[3] = __float2half(v.w);
            uint32_t boff = SWZ128((uint32_t)(r * 128 + q * 8));
            *(uint2*)(smp + 32768 + boff) = *(uint2*)h;
        }
        __syncthreads();
        stageB(c); CP_COMMIT();
        if (c + 1 < CH) { stageA(c + 1); CP_COMMIT(); CP_WAIT1(); }
        else            { CP_WAIT0(); }
        __syncthreads();
        GEMM_COMPUTE(sA, sB)
    }
    GEMM_EPILOGUE(NT)
}

// ---------------- L1/L2 GEMM: fp16 A, fully double-buffered A+B ----------------
// smem: smA[2] 2x16KB @0 ; smB[2] 2x32KB @32768. Total 96KB -> 2 CTAs/SM.
#define SMB_BYTES (98304 + 1024)
template <int K, int NT>
__global__ __launch_bounds__(256, 2) void k_bgemm() {
    extern __shared__ char dynsm[];
    char* smp = (char*)(((uintptr_t)dynsm + 1023) & ~(uintptr_t)1023);
    const uint32_t sA0 = smem_u32(smp);
    const uint32_t sB0 = sA0 + 32768;

    const int tid = threadIdx.x;
    const int wid = tid >> 5;
    const int lane = tid & 31;
    const int wm = wid >> 2;
    const int wn = wid & 3;
    const size_t rowBase = (size_t)blockIdx.x * 128;
    const int nBase = blockIdx.y * 128;

    float acc[4][4][4];
#pragma unroll
    for (int i = 0; i < 4; i++)
#pragma unroll
        for (int j = 0; j < 4; j++)
#pragma unroll
            for (int f = 0; f < 4; f++) acc[i][j][f] = 0.f;

    const int mat = lane >> 3;
    const int rr = lane & 7;
    constexpr int CH = K / 64;

    auto stage = [&](int cc) {
        const int buf = cc & 1;
        const int off = cc * 64;
#pragma unroll
        for (int u = tid; u < 1024; u += 256) {
            int r = u >> 3, uu = u & 7;
            uint32_t boff = SWZ128((uint32_t)(r * 128 + uu * 16));
            size_t gr = rowBase + r;
            uint32_t ok = (gr < NN) ? 16u : 0u;
            const __half* asrc = g_Af + (gr < NN ? gr : 0) * K + off + uu * 8;
            cp16(sA0 + buf * 16384 + boff, asrc, ok);
            const size_t gsrc = (size_t)(nBase + r) * K + off + uu * 8;
            cp16(sB0 + buf * 32768 + boff,         g_Bh + gsrc, 16u);
            cp16(sB0 + buf * 32768 + 16384 + boff, g_Bl + gsrc, 16u);
        }
    };

    stage(0); CP_COMMIT();

    for (int c = 0; c < CH; c++) {
        if (c + 1 < CH) { stage(c + 1); CP_COMMIT(); CP_WAIT1(); }  // chunk c landed
        else            { CP_WAIT0(); }
        __syncthreads();
        const uint32_t sA = sA0 + (c & 1) * 16384;
        const uint32_t sB = sB0 + (c & 1) * 32768;
        GEMM_COMPUTE(sA, sB)
        __syncthreads();   // all warps done reading buf (c&1) before iter c+1 stages it
    }
    GEMM_EPILOGUE(NT)
}

// ---------------- per-node attention scores (fp16 h) ----------------
template <int CT, int H>
__global__ __launch_bounds__(256) void k_scores(const float* __restrict__ a_s,
                                                const float* __restrict__ a_d) {
    int wid = (blockIdx.x * blockDim.x + threadIdx.x) >> 5;
    int lane = threadIdx.x & 31;
    if (wid >= NN) return;
    const __half* hp = g_hf + (size_t)wid * CT;

    int cA = lane * 4;
    uint2 hr = *(const uint2*)(hp + cA);
    float2 h01 = h2f2(hr.x), h23 = h2f2(hr.y);
    float4 sv = *(const float4*)(a_s + cA);
    float4 dv = *(const float4*)(a_d + cA);
    float psA = h01.x * sv.x + h01.y * sv.y + h23.x * sv.z + h23.y * sv.w;
    float pdA = h01.x * dv.x + h01.y * dv.y + h23.x * dv.z + h23.y * dv.w;

    if (CT == 256) {
        int cB = 128 + lane * 4;
        uint2 hr2 = *(const uint2*)(hp + cB);
        float2 g01 = h2f2(hr2.x), g23 = h2f2(hr2.y);
        float4 sv2 = *(const float4*)(a_s + cB);
        float4 dv2 = *(const float4*)(a_d + cB);
        float psB = g01.x * sv2.x + g01.y * sv2.y + g23.x * sv2.z + g23.y * sv2.w;
        float pdB = g01.x * dv2.x + g01.y * dv2.y + g23.x * dv2.z + g23.y * dv2.w;
#pragma unroll
        for (int o = 8; o; o >>= 1) {
            psA += __shfl_xor_sync(0xffffffffu, psA, o);
            pdA += __shfl_xor_sync(0xffffffffu, pdA, o);
            psB += __shfl_xor_sync(0xffffffffu, psB, o);
            pdB += __shfl_xor_sync(0xffffffffu, pdB, o);
        }
        if (lane == 0)  { g_als[wid * 4 + 0] = psA; g_ald[wid * 4 + 0] = pdA;
                          g_als[wid * 4 + 2] = psB; g_ald[wid * 4 + 2] = pdB; }
        if (lane == 16) { g_als[wid * 4 + 1] = psA; g_ald[wid * 4 + 1] = pdA;
                          g_als[wid * 4 + 3] = psB; g_ald[wid * 4 + 3] = pdB; }
    } else {
#pragma unroll
        for (int o = 16; o; o >>= 1) {
            psA += __shfl_xor_sync(0xffffffffu, psA, o);
            pdA += __shfl_xor_sync(0xffffffffu, pdA, o);
        }
        if (lane == 0) { g_als[wid] = psA; g_ald[wid] = pdA; }
    }
}

__device__ __forceinline__ float lrelu(float x) { return x > 0.f ? x : SLOPE * x; }
__device__ __forceinline__ float elu(float x)   { return x > 0.f ? x : expm1f(x); }

// ---------------- warp-per-dst-node softmax + aggregation (fp16 gather) ----------------
// Pass 3 processes edges pairwise for 2x memory-level parallelism.
template <int CT, int H, bool DO_ELU, bool EXT_OUT>
__global__ __launch_bounds__(256) void k_agg(const float* __restrict__ bias,
                                             float* __restrict__ extOut) {
    int n = (blockIdx.x * blockDim.x + threadIdx.x) >> 5;
    int lane = threadIdx.x & 31;
    if (n >= NN) return;
    const int beg = g_off[n], end = g_off[n + 1];
    const float* __restrict__ als = g_als;
    const float* __restrict__ ald = g_ald;

    if (H == 4) {
        float4 ad = *(const float4*)(ald + (size_t)n * 4);
        float4 m = make_float4(-INFINITY, -INFINITY, -INFINITY, -INFINITY);
        for (int i = beg + lane; i < end; i += 32) {
            int s = g_csr[i];
            float4 as = *(const float4*)(als + (size_t)s * 4);
            m.x = fmaxf(m.x, lrelu(as.x + ad.x));
            m.y = fmaxf(m.y, lrelu(as.y + ad.y));
            m.z = fmaxf(m.z, lrelu(as.z + ad.z));
            m.w = fmaxf(m.w, lrelu(as.w + ad.w));
        }
#pragma unroll
        for (int o = 16; o; o >>= 1) {
            m.x = fmaxf(m.x, __shfl_xor_sync(0xffffffffu, m.x, o));
            m.y = fmaxf(m.y, __shfl_xor_sync(0xffffffffu, m.y, o));
            m.z = fmaxf(m.z, __shfl_xor_sync(0xffffffffu, m.z, o));
            m.w = fmaxf(m.w, __shfl_xor_sync(0xffffffffu, m.w, o));
        }
        float4 den = make_float4(0.f, 0.f, 0.f, 0.f);
        for (int i = beg + lane; i < end; i += 32) {
            int s = g_csr[i];
            float4 as = *(const float4*)(als + (size_t)s * 4);
            den.x += __expf(lrelu(as.x + ad.x) - m.x);
            den.y += __expf(lrelu(as.y + ad.y) - m.y);
            den.z += __expf(lrelu(as.z + ad.z) - m.z);
            den.w += __expf(lrelu(as.w + ad.w) - m.w);
        }
#pragma unroll
        for (int o = 16; o; o >>= 1) {
            den.x += __shfl_xor_sync(0xffffffffu, den.x, o);
            den.y += __shfl_xor_sync(0xffffffffu, den.y, o);
            den.z += __shfl_xor_sync(0xffffffffu, den.z, o);
            den.w += __shfl_xor_sync(0xffffffffu, den.w, o);
        }
        float4 inv = make_float4(1.f / (den.x + 1e-16f), 1.f / (den.y + 1e-16f),
                                 1.f / (den.z + 1e-16f), 1.f / (den.w + 1e-16f));
        const int hA = lane >> 4;
        const float adA = hA ? ad.y : ad.x;
        const float adB = hA ? ad.w : ad.z;
        const float mA  = hA ? m.y  : m.x;
        const float mB  = hA ? m.w  : m.z;
        const float ivA = hA ? inv.y : inv.x;
        const float ivB = hA ? inv.w : inv.z;
        const int cA = lane * 4;
        const int cB = 128 + lane * 4;
        float acc[8] = {0.f, 0.f, 0.f, 0.f, 0.f, 0.f, 0.f, 0.f};
        int i = beg;
        for (; i + 1 < end; i += 2) {
            int s0 = g_csr[i], s1 = g_csr[i + 1];
            float4 as0 = *(const float4*)(als + (size_t)s0 * 4);
            float4 as1 = *(const float4*)(als + (size_t)s1 * 4);
            const __half* hp0 = g_hf + (size_t)s0 * 256;
            const __half* hp1 = g_hf + (size_t)s1 * 256;
            uint2 p0 = *(const uint2*)(hp0 + cA);
            uint2 p1 = *(const uint2*)(hp0 + cB);
            uint2 q0 = *(const uint2*)(hp1 + cA);
            uint2 q1 = *(const uint2*)(hp1 + cB);
            float alA0 = __expf(lrelu((hA ? as0.y : as0.x) + adA) - mA) * ivA;
            float alB0 = __expf(lrelu((hA ? as0.w : as0.z) + adB) - mB) * ivB;
            float alA1 = __expf(lrelu((hA ? as1.y : as1.x) + adA) - mA) * ivA;
            float alB1 = __expf(lrelu((hA ? as1.w : as1.z) + adB) - mB) * ivB;
            float2 a01 = h2f2(p0.x), a23 = h2f2(p0.y);
            float2 b01 = h2f2(p1.x), b23 = h2f2(p1.y);
            acc[0] = fmaf(alA0, a01.x, acc[0]); acc[1] = fmaf(alA0, a01.y, acc[1]);
            acc[2] = fmaf(alA0, a23.x, acc[2]); acc[3] = fmaf(alA0, a23.y, acc[3]);
            acc[4] = fmaf(alB0, b01.x, acc[4]); acc[5] = fmaf(alB0, b01.y, acc[5]);
            acc[6] = fmaf(alB0, b23.x, acc[6]); acc[7] = fmaf(alB0, b23.y, acc[7]);
            float2 c01 = h2f2(q0.x), c23 = h2f2(q0.y);
            float2 d01 = h2f2(q1.x), d23 = h2f2(q1.y);
            acc[0] = fmaf(alA1, c01.x, acc[0]); acc[1] = fmaf(alA1, c01.y, acc[1]);
            acc[2] = fmaf(alA1, c23.x, acc[2]); acc[3] = fmaf(alA1, c23.y, acc[3]);
            acc[4] = fmaf(alB1, d01.x, acc[4]); acc[5] = fmaf(alB1, d01.y, acc[5]);
            acc[6] = fmaf(alB1, d23.x, acc[6]); acc[7] = fmaf(alB1, d23.y, acc[7]);
        }
        if (i < end) {
            int s = g_csr[i];
            float4 as = *(const float4*)(als + (size_t)s * 4);
            float alA = __expf(lrelu((hA ? as.y : as.x) + adA) - mA) * ivA;
            float alB = __expf(lrelu((hA ? as.w : as.z) + adB) - mB) * ivB;
            const __half* hp = g_hf + (size_t)s * 256;
            uint2 r0 = *(const uint2*)(hp + cA);
            uint2 r1 = *(const uint2*)(hp + cB);
            float2 a01 = h2f2(r0.x), a23 = h2f2(r0.y);
            float2 b01 = h2f2(r1.x), b23 = h2f2(r1.y);
            acc[0] = fmaf(alA, a01.x, acc[0]); acc[1] = fmaf(alA, a01.y, acc[1]);
            acc[2] = fmaf(alA, a23.x, acc[2]); acc[3] = fmaf(alA, a23.y, acc[3]);
            acc[4] = fmaf(alB, b01.x, acc[4]); acc[5] = fmaf(alB, b01.y, acc[5]);
            acc[6] = fmaf(alB, b23.x, acc[6]); acc[7] = fmaf(alB, b23.y, acc[7]);
        }
        float4 b0 = *(const float4*)(bias + cA);
        float4 b1 = *(const float4*)(bias + cB);
        float v[8];
        v[0] = acc[0] + b0.x; v[1] = acc[1] + b0.y; v[2] = acc[2] + b0.z; v[3] = acc[3] + b0.w;
        v[4] = acc[4] + b1.x; v[5] = acc[5] + b1.y; v[6] = acc[6] + b1.z; v[7] = acc[7] + b1.w;
        if (DO_ELU) {
#pragma unroll
            for (int j = 0; j < 8; j++) v[j] = elu(v[j]);
        }
        if (EXT_OUT) {
            float* op = extOut + (size_t)n * 256;
            *(float4*)(op + cA) = make_float4(v[0], v[1], v[2], v[3]);
            *(float4*)(op + cB) = make_float4(v[4], v[5], v[6], v[7]);
        } else {
            __half hh[8];
#pragma unroll
            for (int j = 0; j < 8; j++) hh[j] = __float2half(v[j]);
            __half* ap = g_Af + (size_t)n * 256;
            *(uint2*)(ap + cA) = *(uint2*)(hh);
            *(uint2*)(ap + cB) = *(uint2*)(hh + 4);
        }
    } else {
        float adn = ald[n];
        float m = -INFINITY;
        for (int i = beg + lane; i < end; i += 32) {
            int s = g_csr[i];
            m = fmaxf(m, lrelu(als[s] + adn));
        }
#pragma unroll
        for (int o = 16; o; o >>= 1) m = fmaxf(m, __shfl_xor_sync(0xffffffffu, m, o));
        float den = 0.f;
        for (int i = beg + lane; i < end; i += 32) {
            int s = g_csr[i];
            den += __expf(lrelu(als[s] + adn) - m);
        }
#pragma unroll
        for (int o = 16; o; o >>= 1) den += __shfl_xor_sync(0xffffffffu, den, o);
        float iv = 1.f / (den + 1e-16f);
        const int cA = lane * 4;
        float acc[4] = {0.f, 0.f, 0.f, 0.f};
        int i = beg;
        for (; i + 1 < end; i += 2) {
            int s0 = g_csr[i], s1 = g_csr[i + 1];
            float e0 = als[s0], e1 = als[s1];
            const __half* hp0 = g_hf + (size_t)s0 * 128;
            const __half* hp1 = g_hf + (size_t)s1 * 128;
            uint2 r0 = *(const uint2*)(hp0 + cA);
            uint2 r1 = *(const uint2*)(hp1 + cA);
            float al0 = __expf(lrelu(e0 + adn) - m) * iv;
            float al1 = __expf(lrelu(e1 + adn) - m) * iv;
            float2 a01 = h2f2(r0.x), a23 = h2f2(r0.y);
            float2 b01 = h2f2(r1.x), b23 = h2f2(r1.y);
            acc[0] = fmaf(al0, a01.x, acc[0]); acc[1] = fmaf(al0, a01.y, acc[1]);
            acc[2] = fmaf(al0, a23.x, acc[2]); acc[3] = fmaf(al0, a23.y, acc[3]);
            acc[0] = fmaf(al1, b01.x, acc[0]); acc[1] = fmaf(al1, b01.y, acc[1]);
            acc[2] = fmaf(al1, b23.x, acc[2]); acc[3] = fmaf(al1, b23.y, acc[3]);
        }
        if (i < end) {
            int s = g_csr[i];
            float al = __expf(lrelu(als[s] + adn) - m) * iv;
            const __half* hp = g_hf + (size_t)s * 128;
            uint2 r0 = *(const uint2*)(hp + cA);
            float2 a01 = h2f2(r0.x), a23 = h2f2(r0.y);
            acc[0] = fmaf(al, a01.x, acc[0]); acc[1] = fmaf(al, a01.y, acc[1]);
            acc[2] = fmaf(al, a23.x, acc[2]); acc[3] = fmaf(al, a23.y, acc[3]);
        }
        float4 bv = *(const float4*)(bias + cA);
        float4 o0;
        o0.x = acc[0] + bv.x; o0.y = acc[1] + bv.y;
        o0.z = acc[2] + bv.z; o0.w = acc[3] + bv.w;
        *(float4*)(extOut + (size_t)n * 128 + cA) = o0;
    }
}

// ---------------- launch ----------------
extern "C" void kernel_launch(void* const* d_in, const int* in_sizes, int n_in,
                              void* d_out, int out_size) {
    const float* x   = (const float*)d_in[0];
    const void*  ei  = d_in[1];
    const float* W0  = (const float*)d_in[2];
    const float* as0 = (const float*)d_in[3];
    const float* ad0 = (const float*)d_in[4];
    const float* b0  = (const float*)d_in[5];
    const float* W1  = (const float*)d_in[6];
    const float* as1 = (const float*)d_in[7];
    const float* ad1 = (const float*)d_in[8];
    const float* b1  = (const float*)d_in[9];
    const float* W2  = (const float*)d_in[10];
    const float* as2 = (const float*)d_in[11];
    const float* ad2 = (const float*)d_in[12];
    const float* b2  = (const float*)d_in[13];
    float* out = (float*)d_out;

    const int TB = 256;
    const int gN = (NN + TB - 1) / TB;
    const int gE = (EE + TB - 1) / TB;
    const int gW = (NN + 7) / 8;
    const int GEMM_GRID = MPAD / 128;  // 782
    dim3 grid2(GEMM_GRID, 2);
    dim3 grid1(GEMM_GRID, 1);

    cudaFuncSetAttribute(k_mgemm16<128, 256>, cudaFuncAttributeMaxDynamicSharedMemorySize, SM16_BYTES);
    cudaFuncSetAttribute(k_bgemm<256, 256>,  cudaFuncAttributeMaxDynamicSharedMemorySize, SMB_BYTES);
    cudaFuncSetAttribute(k_bgemm<256, 128>,  cudaFuncAttributeMaxDynamicSharedMemorySize, SMB_BYTES);

    // Order keeps GEMM L0 at launch index 3 (ncu's profile slot).
    k_detect_init<<<gN, TB>>>((const int*)ei);                        // 0
    k_convB<<<(F0 * HID + TB - 1) / TB, TB>>>(W0, F0, HID);           // 1
    k_count_edges<<<gE, TB>>>(ei);                                    // 2
    k_mgemm16<128, 256><<<grid2, 256, SM16_BYTES>>>(x);               // 3  <- profiled
    k_scan_partial<<<NSB, 256>>>();                                   // 4
    k_scan_tops<<<1, 128>>>();                                        // 5
    k_scan_final<<<NSB, SCAN_BLK>>>();                                // 6
    k_scatter_self<<<gN, TB>>>();                                     // 7
    k_scatter_edges<<<gE, TB>>>(ei);                                  // 8
    k_scores<256, 4><<<gW, TB>>>(as0, ad0);                           // 9
    k_agg<256, 4, true, false><<<gW, TB>>>(b0, nullptr);              // 10 -> g_Af fp16

    // ---- layer 1: g_Af[N,256] @ W1[256,256] ----
    k_convB<<<(HID * HID + TB - 1) / TB, TB>>>(W1, HID, HID);
    k_bgemm<256, 256><<<grid2, 256, SMB_BYTES>>>();
    k_scores<256, 4><<<gW, TB>>>(as1, ad1);
    k_agg<256, 4, true, false><<<gW, TB>>>(b1, nullptr);              // -> g_Af fp16

    // ---- layer 2: g_Af[N,256] @ W2[256,128], 1 head, no ELU ----
    k_convB<<<(HID * OUTC + TB - 1) / TB, TB>>>(W2, HID, OUTC);
    k_bgemm<256, 128><<<grid1, 256, SMB_BYTES>>>();
    k_scores<128, 1><<<gW, TB>>>(as2, ad2);
    k_agg<128, 1, false, true><<<gW, TB>>>(b2, out);
}

// round 16
// speedup vs baseline: 2.9453x; 1.0874x over previous
#include <cuda_runtime.h>
#include <cuda_fp16.h>
#include <cstdint>
#include <math.h>

// ---------------- problem constants (fixed shapes) ----------------
#define NN 100000      // nodes
#define EE 400000      // edges (without self loops)
#define ET (EE + NN)   // total edges incl self loops
#define F0 128         // input features
#define HID 256        // hidden (4 heads x 64)
#define OUTC 128       // output features
#define SLOPE 0.2f
#define MPAD 100096    // 782 * 128 (row-padded M for the GEMM)

// ---------------- device scratch (no allocations allowed) ----------------
__device__ __align__(16) __half g_hf[(size_t)NN * HID];   // fp16 GEMM output (h)
__device__ __align__(16) __half g_Af[(size_t)NN * HID];   // fp16 agg output (next A)
__device__ __align__(16) float g_als[(size_t)NN * 4];
__device__ __align__(16) float g_ald[(size_t)NN * 4];
__device__ int   g_deg[NN];
__device__ int   g_off[NN + 1];
__device__ int   g_cur[NN];
__device__ int   g_csr[ET];
__device__ int   g_is64;

// fp16 split W^T (small, per layer)
__device__ __align__(16) __half g_Bh[256 * 256];   // W^T hi  [N, K]
__device__ __align__(16) __half g_Bl[256 * 256];   // W^T lo  [N, K]

// scan temporaries
#define SCAN_BLK 1024
#define NSB ((NN + SCAN_BLK - 1) / SCAN_BLK)   // 98
__device__ int g_bsum[NSB];
__device__ int g_bbase[NSB];

// ---------------- helpers ----------------
__device__ __forceinline__ uint32_t smem_u32(const void* p) {
    uint32_t a;
    asm("{ .reg .u64 t; cvta.to.shared.u64 t, %1; cvt.u32.u64 %0, t; }" : "=r"(a) : "l"(p));
    return a;
}
#define SWZ128(off) ((off) ^ (((off) >> 3) & 0x70))

__device__ __forceinline__ void ldmat_x4(uint32_t& r0, uint32_t& r1, uint32_t& r2,
                                         uint32_t& r3, uint32_t addr) {
    asm volatile("ldmatrix.sync.aligned.m8n8.x4.shared.b16 {%0,%1,%2,%3}, [%4];"
        : "=r"(r0), "=r"(r1), "=r"(r2), "=r"(r3) : "r"(addr));
}
__device__ __forceinline__ void mma_fp16(float* d, const uint32_t* a, const uint32_t* b) {
    asm volatile("mma.sync.aligned.m16n8k16.row.col.f32.f16.f16.f32 "
        "{%0,%1,%2,%3}, {%4,%5,%6,%7}, {%8,%9}, {%0,%1,%2,%3};"
        : "+f"(d[0]), "+f"(d[1]), "+f"(d[2]), "+f"(d[3])
        : "r"(a[0]), "r"(a[1]), "r"(a[2]), "r"(a[3]), "r"(b[0]), "r"(b[1]));
}
__device__ __forceinline__ void cp16(uint32_t dst, const void* src, uint32_t src_bytes) {
    asm volatile("cp.async.cg.shared.global [%0], [%1], 16, %2;"
        :: "r"(dst), "l"(src), "r"(src_bytes));
}
#define CP_COMMIT() asm volatile("cp.async.commit_group;" ::: "memory")
#define CP_WAIT0()  asm volatile("cp.async.wait_group 0;" ::: "memory")
#define CP_WAIT1()  asm volatile("cp.async.wait_group 1;" ::: "memory")

__device__ __forceinline__ float2 h2f2(uint32_t u) {
    return __half22float2(*(__half2*)&u);
}

// ---------------- edge-index dtype probe + deg init (fused) ----------------
__global__ void k_detect_init(const int* __restrict__ ei32) {
    int i = blockIdx.x * blockDim.x + threadIdx.x;
    if (i < NN) g_deg[i] = 1;   // self loop
    if (i == 0) {
        int odd_nonzero = 0;
        for (int j = 1; j < 256; j += 2) odd_nonzero += (ei32[j] != 0);
        g_is64 = (odd_nonzero == 0) ? 1 : 0;
    }
}
__device__ __forceinline__ int edge_at(const void* __restrict__ ei, size_t idx) {
    if (g_is64) return (int)((const long long*)ei)[idx];
    return ((const int*)ei)[idx];
}

// ---------------- zero attention-score accumulators ----------------
__global__ void k_zero_scores() {
    int i = blockIdx.x * blockDim.x + threadIdx.x;
    if (i < NN * 4) { g_als[i] = 0.f; g_ald[i] = 0.f; }
}

// ---------------- CSR build ----------------
__global__ void k_count_edges(const void* __restrict__ ei) {
    int i = blockIdx.x * blockDim.x + threadIdx.x;
    if (i < EE) atomicAdd(&g_deg[edge_at(ei, (size_t)EE + i)], 1);
}

__global__ void k_scan_partial() {  // grid NSB, 256 thr
    __shared__ int sh[256];
    int b = blockIdx.x, t = threadIdx.x;
    int base = b * SCAN_BLK;
    int sum = 0;
    for (int i = t; i < SCAN_BLK; i += 256) {
        int g = base + i;
        if (g < NN) sum += g_deg[g];
    }
    sh[t] = sum; __syncthreads();
    for (int o = 128; o; o >>= 1) { if (t < o) sh[t] += sh[t + o]; __syncthreads(); }
    if (t == 0) g_bsum[b] = sh[0];
}
__global__ void k_scan_tops() {  // 1 block, 128 thr
    __shared__ int sh[128];
    int t = threadIdx.x;
    int v = (t < NSB) ? g_bsum[t] : 0;
    sh[t] = v; __syncthreads();
    for (int o = 1; o < 128; o <<= 1) {
        int u = (t >= o) ? sh[t - o] : 0; __syncthreads();
        sh[t] += u; __syncthreads();
    }
    if (t < NSB) g_bbase[t] = sh[t] - v;
    if (t == 127) g_off[NN] = sh[127];
}
__global__ void k_scan_final() {  // grid NSB, 1024 thr
    __shared__ int sh[SCAN_BLK];
    int b = blockIdx.x, t = threadIdx.x;
    int g = b * SCAN_BLK + t;
    int v = (g < NN) ? g_deg[g] : 0;
    sh[t] = v; __syncthreads();
    for (int o = 1; o < SCAN_BLK; o <<= 1) {
        int u = (t >= o) ? sh[t - o] : 0; __syncthreads();
        sh[t] += u; __syncthreads();
    }
    if (g < NN) g_off[g] = g_bbase[b] + sh[t] - v;
}

__global__ void k_scatter_self() {
    int i = blockIdx.x * blockDim.x + threadIdx.x;
    if (i < NN) { int o = g_off[i]; g_csr[o] = i; g_cur[i] = o + 1; }
}
__global__ void k_scatter_edges(const void* __restrict__ ei) {
    int i = blockIdx.x * blockDim.x + threadIdx.x;
    if (i < EE) {
        int d = edge_at(ei, (size_t)EE + i);
        int p = atomicAdd(&g_cur[d], 1);
        g_csr[p] = edge_at(ei, i);
    }
}

// ---------------- W^T hi/lo fp16 conversion (tiny, per layer) ----------------
__global__ void k_convB(const float* __restrict__ W, int K, int Ncol) {
    int idx = blockIdx.x * blockDim.x + threadIdx.x;   // n*K + k
    if (idx >= K * Ncol) return;
    int n = idx / K, k = idx % K;
    float w = W[k * Ncol + n];
    __half h = __float2half(w);
    __half l = __float2half(w - __half2float(h));
    g_Bh[idx] = h; g_Bl[idx] = l;
}

// ================= GEMM compute core (fp16, 2-pass B-split) =================
#define GEMM_COMPUTE(sAbase, sBbase)                                                   \
    _Pragma("unroll")                                                                   \
    for (int kk = 0; kk < 4; kk++) {                                                    \
        const int k0 = kk * 16;                                                         \
        uint32_t bh[4][2], bl[4][2];                                                    \
        _Pragma("unroll")                                                               \
        for (int nb = 0; nb < 2; nb++) {                                                \
            int nrow = wn * 32 + nb * 16 + (mat >> 1) * 8 + rr;                         \
            uint32_t boff = SWZ128((uint32_t)(nrow * 128 + (k0 + (mat & 1) * 8) * 2));  \
            uint32_t r0, r1, r2, r3;                                                    \
            ldmat_x4(r0, r1, r2, r3, (sBbase) + boff);                                  \
            bh[nb * 2][0] = r0;     bh[nb * 2][1] = r1;                                 \
            bh[nb * 2 + 1][0] = r2; bh[nb * 2 + 1][1] = r3;                             \
            ldmat_x4(r0, r1, r2, r3, (sBbase) + 16384 + boff);                          \
            bl[nb * 2][0] = r0;     bl[nb * 2][1] = r1;                                 \
            bl[nb * 2 + 1][0] = r2; bl[nb * 2 + 1][1] = r3;                             \
        }                                                                               \
        uint32_t a[4][4];                                                               \
        _Pragma("unroll")                                                               \
        for (int ms = 0; ms < 4; ms++) {                                                \
            int row = wm * 64 + ms * 16 + (mat & 1) * 8 + rr;                           \
            uint32_t aoff = SWZ128((uint32_t)(row * 128 + (k0 + (mat >> 1) * 8) * 2));  \
            ldmat_x4(a[ms][0], a[ms][1], a[ms][2], a[ms][3], (sAbase) + aoff);          \
        }                                                                               \
        _Pragma("unroll")                                                               \
        for (int ms = 0; ms < 4; ms++)                                                  \
            _Pragma("unroll")                                                           \
            for (int ns = 0; ns < 4; ns++)                                              \
                mma_fp16(acc[ms][ns], a[ms], bh[ns]);                                   \
        _Pragma("unroll")                                                               \
        for (int ms = 0; ms < 4; ms++)                                                  \
            _Pragma("unroll")                                                           \
            for (int ns = 0; ns < 4; ns++)                                              \
                mma_fp16(acc[ms][ns], a[ms], bl[ns]);                                   \
    }

// Epilogue: store h fp16 AND accumulate per-row attention scores (fused k_scores).
// All 4 ns-blocks of a warp lie in one head (32-col span). NT==256: head = colBase/64,
// scores index row*4+head. NT==128 (H=1): index row.
#define GEMM_EPILOGUE(NT)                                                               \
    const int cr = lane >> 2;                                                           \
    const int cc2 = (lane & 3) * 2;                                                     \
    const int colBase = nBase + wn * 32;                                                \
    const int smul = ((NT) == 256) ? 4 : 1;                                             \
    const int hd = ((NT) == 256) ? (colBase >> 6) : 0;                                  \
    _Pragma("unroll")                                                                   \
    for (int ms = 0; ms < 4; ms++) {                                                    \
        float ps0 = 0.f, pd0 = 0.f, ps1 = 0.f, pd1 = 0.f;                               \
        size_t row0 = rowBase + wm * 64 + ms * 16 + cr;                                 \
        size_t row1 = row0 + 8;                                                         \
        _Pragma("unroll")                                                               \
        for (int ns = 0; ns < 4; ns++) {                                                \
            int col = colBase + ns * 8 + cc2;                                           \
            float a0 = a_s[col], a1 = a_s[col + 1];                                     \
            float d0 = a_d[col], d1 = a_d[col + 1];                                     \
            ps0 += acc[ms][ns][0] * a0 + acc[ms][ns][1] * a1;                           \
            pd0 += acc[ms][ns][0] * d0 + acc[ms][ns][1] * d1;                           \
            ps1 += acc[ms][ns][2] * a0 + acc[ms][ns][3] * a1;                           \
            pd1 += acc[ms][ns][2] * d0 + acc[ms][ns][3] * d1;                           \
            if (row0 < NN)                                                              \
                *(__half2*)(g_hf + row0 * (NT) + col) =                                 \
                    __floats2half2_rn(acc[ms][ns][0], acc[ms][ns][1]);                  \
            if (row1 < NN)                                                              \
                *(__half2*)(g_hf + row1 * (NT) + col) =                                 \
                    __floats2half2_rn(acc[ms][ns][2], acc[ms][ns][3]);                  \
        }                                                                               \
        if (row0 < NN) { atomicAdd(&g_als[row0 * smul + hd], ps0);                      \
                         atomicAdd(&g_ald[row0 * smul + hd], pd0); }                    \
        if (row1 < NN) { atomicAdd(&g_als[row1 * smul + hd], ps1);                      \
                         atomicAdd(&g_ald[row1 * smul + hd], pd1); }                    \
    }

// ---------------- L0 GEMM: fp32 x -> fused fp16 convert ----------------
#define SM16_BYTES (81920 + 1024)
template <int K, int NT>
__global__ __launch_bounds__(256, 2) void k_mgemm16(const float* __restrict__ A,
                                                    const float* __restrict__ a_s,
                                                    const float* __restrict__ a_d) {
    extern __shared__ char dynsm[];
    char* smp = (char*)(((uintptr_t)dynsm + 1023) & ~(uintptr_t)1023);
    const uint32_t sF = smem_u32(smp);
    const uint32_t sA = sF + 32768;
    const uint32_t sB = sF + 49152;

    const int tid = threadIdx.x;
    const int wid = tid >> 5;
    const int lane = tid & 31;
    const int wm = wid >> 2;
    const int wn = wid & 3;
    const size_t rowBase = (size_t)blockIdx.x * 128;
    const int nBase = blockIdx.y * 128;

    float acc[4][4][4];
#pragma unroll
    for (int i = 0; i < 4; i++)
#pragma unroll
        for (int j = 0; j < 4; j++)
#pragma unroll
            for (int f = 0; f < 4; f++) acc[i][j][f] = 0.f;

    const int mat = lane >> 3;
    const int rr = lane & 7;
    constexpr int CH = K / 64;

    auto stageA = [&](int cc) {
        const int off = cc * 64;
#pragma unroll
        for (int u = tid; u < 2048; u += 256) {
            int r = u >> 4, q = u & 15;
            size_t gr = rowBase + r;
            uint32_t ok = (gr < NN) ? 16u : 0u;
            const float* src = A + (gr < NN ? gr : 0) * K + off + q * 4;
            cp16(sF + (uint32_t)(r * 256 + q * 16), src, ok);
        }
    };
    auto stageB = [&](int cc) {
        const int off = cc * 64;
#pragma unroll
        for (int u = tid; u < 1024; u += 256) {
            int r = u >> 3, uu = u & 7;
            uint32_t boff = SWZ128((uint32_t)(r * 128 + uu * 16));
            const size_t gsrc = (size_t)(nBase + r) * K + off + uu * 8;
            cp16(sB + boff,         g_Bh + gsrc, 16u);
            cp16(sB + 16384 + boff, g_Bl + gsrc, 16u);
        }
    };

    stageA(0); CP_COMMIT();

    for (int c = 0; c < CH; c++) {
        CP_WAIT0();
        __syncthreads();
#pragma unroll
        for (int u = tid; u < 2048; u += 256) {
            int r = u >> 4, q = u & 15;
            float4 v = *(const float4*)(smp + r * 256 + q * 16);
            __half h[4];
            h[0] = __float2half(v.x); h[1] = __float2half(v.y);
            h[2] = __float2half(v.z); h[3] = __float2half(v.w);
            uint32_t boff = SWZ128((uint32_t)(r * 128 + q * 8));
            *(uint2*)(smp + 32768 + boff) = *(uint2*)h;
        }
        __syncthreads();
        stageB(c); CP_COMMIT();
        if (c + 1 < CH) { stageA(c + 1); CP_COMMIT(); CP_WAIT1(); }
        else            { CP_WAIT0(); }
        __syncthreads();
        GEMM_COMPUTE(sA, sB)
    }
    GEMM_EPILOGUE(NT)
}

// ---------------- L1/L2 GEMM: fp16 A, fully double-buffered A+B ----------------
#define SMB_BYTES (98304 + 1024)
template <int K, int NT>
__global__ __launch_bounds__(256, 2) void k_bgemm(const float* __restrict__ a_s,
                                                  const float* __restrict__ a_d) {
    extern __shared__ char dynsm[];
    char* smp = (char*)(((uintptr_t)dynsm + 1023) & ~(uintptr_t)1023);
    const uint32_t sA0 = smem_u32(smp);
    const uint32_t sB0 = sA0 + 32768;

    const int tid = threadIdx.x;
    const int wid = tid >> 5;
    const int lane = tid & 31;
    const int wm = wid >> 2;
    const int wn = wid & 3;
    const size_t rowBase = (size_t)blockIdx.x * 128;
    const int nBase = blockIdx.y * 128;

    float acc[4][4][4];
#pragma unroll
    for (int i = 0; i < 4; i++)
#pragma unroll
        for (int j = 0; j < 4; j++)
#pragma unroll
            for (int f = 0; f < 4; f++) acc[i][j][f] = 0.f;

    const int mat = lane >> 3;
    const int rr = lane & 7;
    constexpr int CH = K / 64;

    auto stage = [&](int cc) {
        const int buf = cc & 1;
        const int off = cc * 64;
#pragma unroll
        for (int u = tid; u < 1024; u += 256) {
            int r = u >> 3, uu = u & 7;
            uint32_t boff = SWZ128((uint32_t)(r * 128 + uu * 16));
            size_t gr = rowBase + r;
            uint32_t ok = (gr < NN) ? 16u : 0u;
            const __half* asrc = g_Af + (gr < NN ? gr : 0) * K + off + uu * 8;
            cp16(sA0 + buf * 16384 + boff, asrc, ok);
            const size_t gsrc = (size_t)(nBase + r) * K + off + uu * 8;
            cp16(sB0 + buf * 32768 + boff,         g_Bh + gsrc, 16u);
            cp16(sB0 + buf * 32768 + 16384 + boff, g_Bl + gsrc, 16u);
        }
    };

    stage(0); CP_COMMIT();

    for (int c = 0; c < CH; c++) {
        if (c + 1 < CH) { stage(c + 1); CP_COMMIT(); CP_WAIT1(); }
        else            { CP_WAIT0(); }
        __syncthreads();
        const uint32_t sA = sA0 + (c & 1) * 16384;
        const uint32_t sB = sB0 + (c & 1) * 32768;
        GEMM_COMPUTE(sA, sB)
        __syncthreads();
    }
    GEMM_EPILOGUE(NT)
}

__device__ __forceinline__ float lrelu(float x) { return x > 0.f ? x : SLOPE * x; }
__device__ __forceinline__ float elu(float x)   { return x > 0.f ? x : expm1f(x); }
__device__ __forceinline__ float expsc(float x) { return __expf(fminf(x, 80.f)); }

// ---------------- warp-per-dst-node single-pass softmax + aggregation ----------------
// No max-subtraction (scores O(1); exp clamped at 80 as insurance). Every lane walks
// all edges, so per-lane denominators are complete locally — zero shuffles.
template <int CT, int H, bool DO_ELU, bool EXT_OUT>
__global__ __launch_bounds__(256) void k_agg(const float* __restrict__ bias,
                                             float* __restrict__ extOut) {
    int n = (blockIdx.x * blockDim.x + threadIdx.x) >> 5;
    int lane = threadIdx.x & 31;
    if (n >= NN) return;
    const int beg = g_off[n], end = g_off[n + 1];
    const float* __restrict__ als = g_als;
    const float* __restrict__ ald = g_ald;

    if (H == 4) {
        float4 ad = *(const float4*)(ald + (size_t)n * 4);
        const int hA = lane >> 4;
        const float adA = hA ? ad.y : ad.x;
        const float adB = hA ? ad.w : ad.z;
        const int cA = lane * 4;
        const int cB = 128 + lane * 4;
        float acc[8] = {0.f, 0.f, 0.f, 0.f, 0.f, 0.f, 0.f, 0.f};
        float denA = 0.f, denB = 0.f;
        int i = beg;
        for (; i + 1 < end; i += 2) {
            int s0 = g_csr[i], s1 = g_csr[i + 1];
            float4 as0 = *(const float4*)(als + (size_t)s0 * 4);
            float4 as1 = *(const float4*)(als + (size_t)s1 * 4);
            const __half* hp0 = g_hf + (size_t)s0 * 256;
            const __half* hp1 = g_hf + (size_t)s1 * 256;
            uint2 p0 = *(const uint2*)(hp0 + cA);
            uint2 p1 = *(const uint2*)(hp0 + cB);
            uint2 q0 = *(const uint2*)(hp1 + cA);
            uint2 q1 = *(const uint2*)(hp1 + cB);
            float alA0 = expsc(lrelu((hA ? as0.y : as0.x) + adA));
            float alB0 = expsc(lrelu((hA ? as0.w : as0.z) + adB));
            float alA1 = expsc(lrelu((hA ? as1.y : as1.x) + adA));
            float alB1 = expsc(lrelu((hA ? as1.w : as1.z) + adB));
            denA += alA0 + alA1; denB += alB0 + alB1;
            float2 a01 = h2f2(p0.x), a23 = h2f2(p0.y);
            float2 b01 = h2f2(p1.x), b23 = h2f2(p1.y);
            acc[0] = fmaf(alA0, a01.x, acc[0]); acc[1] = fmaf(alA0, a01.y, acc[1]);
            acc[2] = fmaf(alA0, a23.x, acc[2]); acc[3] = fmaf(alA0, a23.y, acc[3]);
            acc[4] = fmaf(alB0, b01.x, acc[4]); acc[5] = fmaf(alB0, b01.y, acc[5]);
            acc[6] = fmaf(alB0, b23.x, acc[6]); acc[7] = fmaf(alB0, b23.y, acc[7]);
            float2 c01 = h2f2(q0.x), c23 = h2f2(q0.y);
            float2 d01 = h2f2(q1.x), d23 = h2f2(q1.y);
            acc[0] = fmaf(alA1, c01.x, acc[0]); acc[1] = fmaf(alA1, c01.y, acc[1]);
            acc[2] = fmaf(alA1, c23.x, acc[2]); acc[3] = fmaf(alA1, c23.y, acc[3]);
            acc[4] = fmaf(alB1, d01.x, acc[4]); acc[5] = fmaf(alB1, d01.y, acc[5]);
            acc[6] = fmaf(alB1, d23.x, acc[6]); acc[7] = fmaf(alB1, d23.y, acc[7]);
        }
        if (i < end) {
            int s = g_csr[i];
            float4 as = *(const float4*)(als + (size_t)s * 4);
            float alA = expsc(lrelu((hA ? as.y : as.x) + adA));
            float alB = expsc(lrelu((hA ? as.w : as.z) + adB));
            denA += alA; denB += alB;
            const __half* hp = g_hf + (size_t)s * 256;
            uint2 r0 = *(const uint2*)(hp + cA);
            uint2 r1 = *(const uint2*)(hp + cB);
            float2 a01 = h2f2(r0.x), a23 = h2f2(r0.y);
            float2 b01 = h2f2(r1.x), b23 = h2f2(r1.y);
            acc[0] = fmaf(alA, a01.x, acc[0]); acc[1] = fmaf(alA, a01.y, acc[1]);
            acc[2] = fmaf(alA, a23.x, acc[2]); acc[3] = fmaf(alA, a23.y, acc[3]);
            acc[4] = fmaf(alB, b01.x, acc[4]); acc[5] = fmaf(alB, b01.y, acc[5]);
            acc[6] = fmaf(alB, b23.x, acc[6]); acc[7] = fmaf(alB, b23.y, acc[7]);
        }
        float ivA = 1.f / (denA + 1e-16f);
        float ivB = 1.f / (denB + 1e-16f);
        float4 b0 = *(const float4*)(bias + cA);
        float4 b1 = *(const float4*)(bias + cB);
        float v[8];
        v[0] = acc[0] * ivA + b0.x; v[1] = acc[1] * ivA + b0.y;
        v[2] = acc[2] * ivA + b0.z; v[3] = acc[3] * ivA + b0.w;
        v[4] = acc[4] * ivB + b1.x; v[5] = acc[5] * ivB + b1.y;
        v[6] = acc[6] * ivB + b1.z; v[7] = acc[7] * ivB + b1.w;
        if (DO_ELU) {
#pragma unroll
            for (int j = 0; j < 8; j++) v[j] = elu(v[j]);
        }
        if (EXT_OUT) {
            float* op = extOut + (size_t)n * 256;
            *(float4*)(op + cA) = make_float4(v[0], v[1], v[2], v[3]);
            *(float4*)(op + cB) = make_float4(v[4], v[5], v[6], v[7]);
        } else {
            __half hh[8];
#pragma unroll
            for (int j = 0; j < 8; j++) hh[j] = __float2half(v[j]);
            __half* ap = g_Af + (size_t)n * 256;
            *(uint2*)(ap + cA) = *(uint2*)(hh);
            *(uint2*)(ap + cB) = *(uint2*)(hh + 4);
        }
    } else {
        float adn = ald[n];
        const int cA = lane * 4;
        float acc[4] = {0.f, 0.f, 0.f, 0.f};
        float den = 0.f;
        int i = beg;
        for (; i + 1 < end; i += 2) {
            int s0 = g_csr[i], s1 = g_csr[i + 1];
            float e0 = als[s0], e1 = als[s1];
            const __half* hp0 = g_hf + (size_t)s0 * 128;
            const __half* hp1 = g_hf + (size_t)s1 * 128;
            uint2 r0 = *(const uint2*)(hp0 + cA);
            uint2 r1 = *(const uint2*)(hp1 + cA);
            float al0 = expsc(lrelu(e0 + adn));
            float al1 = expsc(lrelu(e1 + adn));
            den += al0 + al1;
            float2 a01 = h2f2(r0.x), a23 = h2f2(r0.y);
            float2 b01 = h2f2(r1.x), b23 = h2f2(r1.y);
            acc[0] = fmaf(al0, a01.x, acc[0]); acc[1] = fmaf(al0, a01.y, acc[1]);
            acc[2] = fmaf(al0, a23.x, acc[2]); acc[3] = fmaf(al0, a23.y, acc[3]);
            acc[0] = fmaf(al1, b01.x, acc[0]); acc[1] = fmaf(al1, b01.y, acc[1]);
            acc[2] = fmaf(al1, b23.x, acc[2]); acc[3] = fmaf(al1, b23.y, acc[3]);
        }
        if (i < end) {
            int s = g_csr[i];
            float al = expsc(lrelu(als[s] + adn));
            den += al;
            const __half* hp = g_hf + (size_t)s * 128;
            uint2 r0 = *(const uint2*)(hp + cA);
            float2 a01 = h2f2(r0.x), a23 = h2f2(r0.y);
            acc[0] = fmaf(al, a01.x, acc[0]); acc[1] = fmaf(al, a01.y, acc[1]);
            acc[2] = fmaf(al, a23.x, acc[2]); acc[3] = fmaf(al, a23.y, acc[3]);
        }
        float iv = 1.f / (den + 1e-16f);
        float4 bv = *(const float4*)(bias + cA);
        float4 o0;
        o0.x = acc[0] * iv + bv.x; o0.y = acc[1] * iv + bv.y;
        o0.z = acc[2] * iv + bv.z; o0.w = acc[3] * iv + bv.w;
        *(float4*)(extOut + (size_t)n * 128 + cA) = o0;
    }
}

// ---------------- launch ----------------
extern "C" void kernel_launch(void* const* d_in, const int* in_sizes, int n_in,
                              void* d_out, int out_size) {
    const float* x   = (const float*)d_in[0];
    const void*  ei  = d_in[1];
    const float* W0  = (const float*)d_in[2];
    const float* as0 = (const float*)d_in[3];
    const float* ad0 = (const float*)d_in[4];
    const float* b0  = (const float*)d_in[5];
    const float* W1  = (const float*)d_in[6];
    const float* as1 = (const float*)d_in[7];
    const float* ad1 = (const float*)d_in[8];
    const float* b1  = (const float*)d_in[9];
    const float* W2  = (const float*)d_in[10];
    const float* as2 = (const float*)d_in[11];
    const float* ad2 = (const float*)d_in[12];
    const float* b2  = (const float*)d_in[13];
    float* out = (float*)d_out;

    const int TB = 256;
    const int gN = (NN + TB - 1) / TB;
    const int gE = (EE + TB - 1) / TB;
    const int gZ = (NN * 4 + TB - 1) / TB;
    const int gW = (NN + 7) / 8;
    const int GEMM_GRID = MPAD / 128;  // 782
    dim3 grid2(GEMM_GRID, 2);
    dim3 grid1(GEMM_GRID, 1);

    cudaFuncSetAttribute(k_mgemm16<128, 256>, cudaFuncAttributeMaxDynamicSharedMemorySize, SM16_BYTES);
    cudaFuncSetAttribute(k_bgemm<256, 256>,  cudaFuncAttributeMaxDynamicSharedMemorySize, SMB_BYTES);
    cudaFuncSetAttribute(k_bgemm<256, 128>,  cudaFuncAttributeMaxDynamicSharedMemorySize, SMB_BYTES);

    // Order keeps GEMM L0 at launch index 3 (ncu's profile slot).
    k_detect_init<<<gN, TB>>>((const int*)ei);                        // 0
    k_convB<<<(F0 * HID + TB - 1) / TB, TB>>>(W0, F0, HID);           // 1
    k_zero_scores<<<gZ, TB>>>();                                      // 2
    k_mgemm16<128, 256><<<grid2, 256, SM16_BYTES>>>(x, as0, ad0);     // 3  <- profiled
    k_count_edges<<<gE, TB>>>(ei);                                    // 4
    k_scan_partial<<<NSB, 256>>>();                                   // 5
    k_scan_tops<<<1, 128>>>();                                        // 6
    k_scan_final<<<NSB, SCAN_BLK>>>();                                // 7
    k_scatter_self<<<gN, TB>>>();                                     // 8
    k_scatter_edges<<<gE, TB>>>(ei);                                  // 9
    k_agg<256, 4, true, false><<<gW, TB>>>(b0, nullptr);              // 10 -> g_Af fp16

    // ---- layer 1: g_Af[N,256] @ W1[256,256] ----
    k_convB<<<(HID * HID + TB - 1) / TB, TB>>>(W1, HID, HID);
    k_zero_scores<<<gZ, TB>>>();
    k_bgemm<256, 256><<<grid2, 256, SMB_BYTES>>>(as1, ad1);
    k_agg<256, 4, true, false><<<gW, TB>>>(b1, nullptr);              // -> g_Af fp16

    // ---- layer 2: g_Af[N,256] @ W2[256,128], 1 head, no ELU ----
    k_convB<<<(HID * OUTC + TB - 1) / TB, TB>>>(W2, HID, OUTC);
    k_zero_scores<<<gZ, TB>>>();
    k_bgemm<256, 128><<<grid1, 256, SMB_BYTES>>>(as2, ad2);
    k_agg<128, 1, false, true><<<gW, TB>>>(b2, out);
}